// round 12
// baseline (speedup 1.0000x reference)
#include <cuda_runtime.h>
#include <cuda_bf16.h>
#include <cstdint>

// ---------------------------------------------------------------------------
// Static scratch (no allocation allowed)
// ---------------------------------------------------------------------------
__device__ float g_bufA[16777216];
__device__ float g_bufB[4194304];
__device__ float g_Wp[279936];      // [k1lin 27][k2lin 27][ci 128][co 3]
__device__ float g_WpT[279936];     // [k1lin 27][k2lin 27][co 3][ci 128]
__device__ float g_Weff[110592];    // [pz 8][dxlin 27][co 3][ci 128]
__device__ float g_bconv[81];       // [k2lin 27][co 3]
__device__ float g_btot[3];
__device__ __nv_bfloat16 g_xhi[4194304];
__device__ __nv_bfloat16 g_xlo[4194304];
__device__ __nv_bfloat16 g_whi[442368];    // L4 weights (w10)
__device__ __nv_bfloat16 g_wlo[442368];
__device__ __nv_bfloat16 g_whiB[442368];   // L3 weights (w1)
__device__ __nv_bfloat16 g_wloB[442368];

typedef unsigned long long ull;

// ---------------------------------------------------------------------------
// f32x2 packed helpers
// ---------------------------------------------------------------------------
__device__ __forceinline__ ull pack2(float x, float y){
  ull r; asm("mov.b64 %0, {%1, %2};" : "=l"(r) : "f"(x), "f"(y)); return r;
}
__device__ __forceinline__ void unpack2(ull v, float& x, float& y){
  asm("mov.b64 {%0, %1}, %2;" : "=f"(x), "=f"(y) : "l"(v));
}
__device__ __forceinline__ void ffma2(ull& acc, ull a, ull b){
  asm("fma.rn.f32x2 %0, %1, %2, %0;" : "+l"(acc) : "l"(a), "l"(b));
}

// ---------------------------------------------------------------------------
// mma.sync / ldmatrix / cp.async helpers (baseline PTX, legal on sm_103)
// ---------------------------------------------------------------------------
__device__ __forceinline__ void ldsm4(uint32_t* r, const void* p){
  uint32_t a = (uint32_t)__cvta_generic_to_shared(p);
  asm volatile("ldmatrix.sync.aligned.m8n8.x4.shared.b16 {%0,%1,%2,%3}, [%4];"
    : "=r"(r[0]), "=r"(r[1]), "=r"(r[2]), "=r"(r[3]) : "r"(a));
}
__device__ __forceinline__ void ldsm4t(uint32_t* r, const void* p){
  uint32_t a = (uint32_t)__cvta_generic_to_shared(p);
  asm volatile("ldmatrix.sync.aligned.m8n8.x4.trans.shared.b16 {%0,%1,%2,%3}, [%4];"
    : "=r"(r[0]), "=r"(r[1]), "=r"(r[2]), "=r"(r[3]) : "r"(a));
}
__device__ __forceinline__ void mma_bf16(float* c, const uint32_t* a,
                                         uint32_t b0, uint32_t b1){
  asm volatile("mma.sync.aligned.m16n8k16.row.col.f32.bf16.bf16.f32 "
    "{%0,%1,%2,%3}, {%4,%5,%6,%7}, {%8,%9}, {%0,%1,%2,%3};"
    : "+f"(c[0]), "+f"(c[1]), "+f"(c[2]), "+f"(c[3])
    : "r"(a[0]), "r"(a[1]), "r"(a[2]), "r"(a[3]), "r"(b0), "r"(b1));
}
__device__ __forceinline__ void cpasync16(void* dst, const void* src, bool pred){
  uint32_t d = (uint32_t)__cvta_generic_to_shared(dst);
  int sz = pred ? 16 : 0;
  asm volatile("cp.async.cg.shared.global [%0], [%1], 16, %2;"
               :: "r"(d), "l"(src), "r"(sz));
}
#define CP_COMMIT() asm volatile("cp.async.commit_group;")
#define CP_WAIT1()  asm volatile("cp.async.wait_group 1;")
#define CP_WAIT0()  asm volatile("cp.async.wait_group 0;")

// ---------------------------------------------------------------------------
// ROUND-1 PROVEN KERNEL (verbatim): generic transposed-conv implicit GEMM.
// ---------------------------------------------------------------------------
template<int BM, int TM>
__global__ __launch_bounds__(256) void deconv_gemm(
    const float* __restrict__ x, const float* __restrict__ w,
    const float* __restrict__ bias, float* __restrict__ out,
    int inD, int inH, int inW, int Cin,
    int outD, int outH, int outW, int Cout,
    int stride, int relu)
{
  constexpr int BN = 64;
  constexpr int BK = 16;
  constexpr int NP = TM / 2;

  __shared__ float As[BK][BM];
  __shared__ float Bs[BK][BN];
  __shared__ int   offs[BM];

  const int tid = threadIdx.x;
  const int pz = blockIdx.z;
  const int pd = (pz >> 2) & 1, ph = (pz >> 1) & 1, pw = pz & 1;
  const int rH = outH / stride, rW = outW / stride;
  const int nb = blockIdx.y * BN;
  const int vbase = blockIdx.x * BM;

  int md = 0, mh = 0, mw = 0;
  if (tid < BM) {
    int rv = vbase + tid;
    mw = rv % rW; int t = rv / rW; mh = t % rH; md = t / rH;
  }

  int nkd, kdL[3], ddL[3];
  int nkh, khL[3], dhL[3];
  int nkw, kwL[3], dwL[3];
  auto mk = [&](int p, int& n, int* kL, int* dL){
    if (stride == 1){ n = 3; kL[0]=0; kL[1]=1; kL[2]=2; dL[0]=-1; dL[1]=0; dL[2]=1; }
    else if (p == 0){ n = 2; kL[0]=0; kL[1]=2; dL[0]=-1; dL[1]=0; }
    else            { n = 1; kL[0]=1; dL[0]=0; }
  };
  mk(pd, nkd, kdL, ddL);
  mk(ph, nkh, khL, dhL);
  mk(pw, nkw, kwL, dwL);

  const int mg = tid >> 4, ng = tid & 15;
  const int m0 = mg * TM, n0 = ng * 4;

  ull acc[NP][4];
  #pragma unroll
  for (int i = 0; i < NP; i++)
    #pragma unroll
    for (int j = 0; j < 4; j++) acc[i][j] = 0ull;

  for (int ia = 0; ia < nkd; ia++)
  for (int ib = 0; ib < nkh; ib++)
  for (int ic = 0; ic < nkw; ic++){
    const int tap = (kdL[ia]*3 + khL[ib])*3 + kwL[ic];
    const float* wt = w + (size_t)tap * Cin * Cout + nb;

    __syncthreads();
    if (tid < BM){
      int id = md + ddL[ia];
      int ih = mh + dhL[ib];
      int iw = mw + dwL[ic];
      bool v = (unsigned)id < (unsigned)inD &&
               (unsigned)ih < (unsigned)inH &&
               (unsigned)iw < (unsigned)inW;
      offs[tid] = v ? ((id*inH + ih)*inW + iw) * Cin : -1;
    }

    for (int c0 = 0; c0 < Cin; c0 += BK){
      __syncthreads();
      for (int idx = tid; idx < BM*4; idx += 256){
        int v = idx >> 2, c4 = (idx & 3) * 4;
        int o = offs[v];
        float4 val = make_float4(0.f, 0.f, 0.f, 0.f);
        if (o >= 0) val = *(const float4*)(x + o + c0 + c4);
        As[c4+0][v] = val.x; As[c4+1][v] = val.y;
        As[c4+2][v] = val.z; As[c4+3][v] = val.w;
      }
      {
        int r = tid >> 4, col = (tid & 15) * 4;
        float4 bv = *(const float4*)(wt + (size_t)(c0 + r) * Cout + col);
        *(float4*)&Bs[r][col] = bv;
      }
      __syncthreads();
      #pragma unroll
      for (int kk = 0; kk < BK; kk++){
        const ull* a64 = (const ull*)&As[kk][m0];
        float4 bv = *(const float4*)&Bs[kk][n0];
        ull bp0 = pack2(bv.x, bv.x);
        ull bp1 = pack2(bv.y, bv.y);
        ull bp2 = pack2(bv.z, bv.z);
        ull bp3 = pack2(bv.w, bv.w);
        #pragma unroll
        for (int i = 0; i < NP; i++){
          ull av = a64[i];
          ffma2(acc[i][0], av, bp0);
          ffma2(acc[i][1], av, bp1);
          ffma2(acc[i][2], av, bp2);
          ffma2(acc[i][3], av, bp3);
        }
      }
    }
  }

  float4 b4 = *(const float4*)&bias[nb + n0];
  #pragma unroll
  for (int i = 0; i < NP; i++){
    float r0[4], r1[4];
    #pragma unroll
    for (int j = 0; j < 4; j++) unpack2(acc[i][j], r0[j], r1[j]);
    #pragma unroll
    for (int h = 0; h < 2; h++){
      float* rr = h ? r1 : r0;
      int rv = vbase + m0 + 2*i + h;
      int vw = rv % rW; int t = rv / rW; int vh = t % rH; int vd = t / rH;
      int od = vd*stride + pd, oh = vh*stride + ph, ow = vw*stride + pw;
      size_t oo = (size_t)((od*outH + oh)*outW + ow) * Cout + nb + n0;
      float4 res;
      res.x = rr[0] + b4.x; res.y = rr[1] + b4.y;
      res.z = rr[2] + b4.z; res.w = rr[3] + b4.w;
      if (relu){
        res.x = fmaxf(res.x, 0.f); res.y = fmaxf(res.y, 0.f);
        res.z = fmaxf(res.z, 0.f); res.w = fmaxf(res.w, 0.f);
      }
      *(float4*)&out[oo] = res;
    }
  }
}

// ---------------------------------------------------------------------------
// bf16 hi/lo split pre-passes (R9-proven, verbatim)
// ---------------------------------------------------------------------------
__global__ __launch_bounds__(256) void split_x_kernel(
    const float* __restrict__ x, __nv_bfloat16* __restrict__ hi,
    __nv_bfloat16* __restrict__ lo, int n4)
{
  int i = blockIdx.x * 256 + threadIdx.x;
  if (i >= n4) return;
  float4 v = ((const float4*)x)[i];
  __nv_bfloat16 h0 = __float2bfloat16_rn(v.x);
  __nv_bfloat16 h1 = __float2bfloat16_rn(v.y);
  __nv_bfloat16 h2 = __float2bfloat16_rn(v.z);
  __nv_bfloat16 h3 = __float2bfloat16_rn(v.w);
  __nv_bfloat16 l0 = __float2bfloat16_rn(v.x - __bfloat162float(h0));
  __nv_bfloat16 l1 = __float2bfloat16_rn(v.y - __bfloat162float(h1));
  __nv_bfloat16 l2 = __float2bfloat16_rn(v.z - __bfloat162float(h2));
  __nv_bfloat16 l3 = __float2bfloat16_rn(v.w - __bfloat162float(h3));
  ushort4 hv = make_ushort4(*(unsigned short*)&h0, *(unsigned short*)&h1,
                            *(unsigned short*)&h2, *(unsigned short*)&h3);
  ushort4 lv = make_ushort4(*(unsigned short*)&l0, *(unsigned short*)&l1,
                            *(unsigned short*)&l2, *(unsigned short*)&l3);
  ((ushort4*)hi)[i] = hv;
  ((ushort4*)lo)[i] = lv;
}

__global__ __launch_bounds__(256) void split_w_kernel(
    const float* __restrict__ w, __nv_bfloat16* __restrict__ hi,
    __nv_bfloat16* __restrict__ lo)
{
  int i = blockIdx.x * 256 + threadIdx.x;
  if (i >= 27*128*128) return;
  float v = w[i];
  __nv_bfloat16 h = __float2bfloat16_rn(v);
  hi[i] = h;
  lo[i] = __float2bfloat16_rn(v - __bfloat162float(h));
}

// ---------------------------------------------------------------------------
// R11-PROVEN (verbatim): L4 on HMMA with cp.async 2-stage pipeline.
// ---------------------------------------------------------------------------
__global__ __launch_bounds__(256, 2) void mma_s1r_pipe(
    const __nv_bfloat16* __restrict__ xhi, const __nv_bfloat16* __restrict__ xlo,
    const __nv_bfloat16* __restrict__ whi, const __nv_bfloat16* __restrict__ wlo,
    const float* __restrict__ bias, float* __restrict__ out)
{
  constexpr int AP = 40, BP = 136;
  constexpr int ASZ = 128*AP;
  constexpr int BSZ = 32*BP;
  constexpr int STG = 2*ASZ + 2*BSZ;
  constexpr int NIT = 27*4;

  extern __shared__ __align__(16) unsigned short dsm[];
  int* offsAll = (int*)(dsm + 2*STG);

  const int tid  = threadIdx.x;
  const int lane = tid & 31;
  const int wid  = tid >> 5;
  const int warp_m = wid >> 2;
  const int warp_n = wid & 3;
  const int vbase = blockIdx.x * 128;

  for (int s = tid; s < 27*128; s += 256){
    int tap = s >> 7, row = s & 127;
    int kw = tap % 3, kh = (tap/3)%3, kd = tap/9;
    int rv = vbase + row;
    int mw = rv & 31, mh = (rv>>5)&31, md = rv>>10;
    int id = md + kd - 1, ih = mh + kh - 1, iw = mw + kw - 1;
    bool v = (unsigned)id < 32u && (unsigned)ih < 32u && (unsigned)iw < 32u;
    offsAll[s] = v ? ((id*32 + ih)*32 + iw) * 128 : -1;
  }
  __syncthreads();

  const int a_row_in = lane & 15;
  const int a_colb   = (lane >> 4) << 3;
  const int b_krow   = lane & 15;
  const int b_coln   = (lane >> 4) << 3;

  float acc[4][4][4];
  #pragma unroll
  for (int mi = 0; mi < 4; mi++)
    #pragma unroll
    for (int ni = 0; ni < 4; ni++)
      #pragma unroll
      for (int q = 0; q < 4; q++) acc[mi][ni][q] = 0.f;

  auto fill = [&](int st, int it){
    int tap = it >> 2, c0 = (it & 3) * 32;
    unsigned short* Ah = dsm + st*STG;
    unsigned short* Al = Ah + ASZ;
    unsigned short* Bh = Ah + 2*ASZ;
    unsigned short* Bl = Bh + BSZ;
    #pragma unroll
    for (int rep = 0; rep < 2; rep++){
      int idx = rep*256 + tid;
      int row = idx >> 2, cg = idx & 3;
      int o = offsAll[tap*128 + row];
      bool p = o >= 0;
      int ob = (p ? o : 0) + c0 + cg*8;
      cpasync16(&Ah[row*AP + cg*8], xhi + ob, p);
      cpasync16(&Al[row*AP + cg*8], xlo + ob, p);
    }
    #pragma unroll
    for (int rep = 0; rep < 2; rep++){
      int idx = rep*256 + tid;
      int kr = idx >> 4, cg = idx & 15;
      int src = tap*16384 + (c0 + kr)*128 + cg*8;
      cpasync16(&Bh[kr*BP + cg*8], whi + src, true);
      cpasync16(&Bl[kr*BP + cg*8], wlo + src, true);
    }
  };

  fill(0, 0);
  CP_COMMIT();

  for (int it = 0; it < NIT; ++it){
    const int b = it & 1;
    if (it + 1 < NIT){
      fill(b ^ 1, it + 1);
      CP_COMMIT();
      CP_WAIT1();
    } else {
      CP_WAIT0();
    }
    __syncthreads();

    const unsigned short* Ah = dsm + b*STG;
    const unsigned short* Al = Ah + ASZ;
    const unsigned short* Bh = Ah + 2*ASZ;
    const unsigned short* Bl = Bh + BSZ;

    #pragma unroll
    for (int k16 = 0; k16 < 2; k16++){
      uint32_t af[4][4], bh[2][4], bl[2][4];
      #pragma unroll
      for (int mi = 0; mi < 4; mi++){
        int r = warp_m*64 + mi*16 + a_row_in;
        ldsm4(af[mi], &Ah[r*AP + k16*16 + a_colb]);
      }
      #pragma unroll
      for (int nj = 0; nj < 2; nj++){
        int kr = k16*16 + b_krow;
        int nc = warp_n*32 + nj*16 + b_coln;
        ldsm4t(bh[nj], &Bh[kr*BP + nc]);
        ldsm4t(bl[nj], &Bl[kr*BP + nc]);
      }
      #pragma unroll
      for (int mi = 0; mi < 4; mi++)
        #pragma unroll
        for (int ni = 0; ni < 4; ni++){
          const uint32_t* h = &bh[ni>>1][(ni&1)*2];
          const uint32_t* L = &bl[ni>>1][(ni&1)*2];
          mma_bf16(acc[mi][ni], af[mi], h[0], h[1]);
          mma_bf16(acc[mi][ni], af[mi], L[0], L[1]);
        }
      #pragma unroll
      for (int mi = 0; mi < 4; mi++){
        int r = warp_m*64 + mi*16 + a_row_in;
        ldsm4(af[mi], &Al[r*AP + k16*16 + a_colb]);
      }
      #pragma unroll
      for (int mi = 0; mi < 4; mi++)
        #pragma unroll
        for (int ni = 0; ni < 4; ni++){
          const uint32_t* h = &bh[ni>>1][(ni&1)*2];
          mma_bf16(acc[mi][ni], af[mi], h[0], h[1]);
        }
    }
    __syncthreads();
  }

  #pragma unroll
  for (int mi = 0; mi < 4; mi++){
    int v0 = vbase + warp_m*64 + mi*16 + (lane >> 2);
    #pragma unroll
    for (int ni = 0; ni < 4; ni++){
      int col = warp_n*32 + ni*8 + (lane & 3)*2;
      float2 bb = *(const float2*)&bias[col];
      float2 r0, r1;
      r0.x = fmaxf(acc[mi][ni][0] + bb.x, 0.f);
      r0.y = fmaxf(acc[mi][ni][1] + bb.y, 0.f);
      r1.x = fmaxf(acc[mi][ni][2] + bb.x, 0.f);
      r1.y = fmaxf(acc[mi][ni][3] + bb.y, 0.f);
      *(float2*)&out[(size_t)v0*128 + col]     = r0;
      *(float2*)&out[(size_t)(v0+8)*128 + col] = r1;
    }
  }
}

// ---------------------------------------------------------------------------
// R10-PROVEN (verbatim): L3 on HMMA, stride-2 parity decomposition.
// ---------------------------------------------------------------------------
__global__ __launch_bounds__(256, 2) void mma_s2(
    const __nv_bfloat16* __restrict__ xhi, const __nv_bfloat16* __restrict__ xlo,
    const __nv_bfloat16* __restrict__ whi, const __nv_bfloat16* __restrict__ wlo,
    const float* __restrict__ bias, float* __restrict__ out)
{
  constexpr int BM = 128, BK = 32;
  constexpr int AP = 40;
  constexpr int BP = 136;

  __shared__ __align__(16) unsigned short Ahi[BM*AP];
  __shared__ __align__(16) unsigned short Alo[BM*AP];
  __shared__ __align__(16) unsigned short Bhi[BK*BP];
  __shared__ __align__(16) unsigned short Blo[BK*BP];
  __shared__ int offs[BM];

  const int tid  = threadIdx.x;
  const int lane = tid & 31;
  const int wid  = tid >> 5;
  const int warp_m = wid >> 2;
  const int warp_n = wid & 3;
  const int vbase = blockIdx.x * BM;
  const int pz = blockIdx.z;
  const int pd = (pz >> 2) & 1, ph = (pz >> 1) & 1, pw = pz & 1;

  int md, mh, mw;
  { int rv = vbase + (tid & 127);
    mw = rv & 15; int t = rv >> 4; mh = t & 15; md = t >> 4; }

  int nkd, kdL[2], ddL[2];
  int nkh, khL[2], dhL[2];
  int nkw, kwL[2], dwL[2];
  auto mk2 = [&](int p, int& n, int* kL, int* dL){
    if (p == 0){ n = 2; kL[0]=0; kL[1]=2; dL[0]=-1; dL[1]=0; }
    else       { n = 1; kL[0]=1; dL[0]=0; }
  };
  mk2(pd, nkd, kdL, ddL);
  mk2(ph, nkh, khL, dhL);
  mk2(pw, nkw, kwL, dwL);

  const int a_row_in = lane & 15;
  const int a_colb   = (lane >> 4) << 3;
  const int b_krow   = lane & 15;
  const int b_coln   = (lane >> 4) << 3;

  float acc[4][4][4];
  #pragma unroll
  for (int mi = 0; mi < 4; mi++)
    #pragma unroll
    for (int ni = 0; ni < 4; ni++)
      #pragma unroll
      for (int q = 0; q < 4; q++) acc[mi][ni][q] = 0.f;

  for (int ia = 0; ia < nkd; ia++)
  for (int ib = 0; ib < nkh; ib++)
  for (int ic = 0; ic < nkw; ic++){
    const int tap = (kdL[ia]*3 + khL[ib])*3 + kwL[ic];
    __syncthreads();
    if (tid < BM){
      int id = md + ddL[ia], ih = mh + dhL[ib], iw = mw + dwL[ic];
      bool v = (unsigned)id < 16u && (unsigned)ih < 16u && (unsigned)iw < 16u;
      offs[tid] = v ? ((id*16 + ih)*16 + iw) * 128 : -1;
    }

    for (int c0 = 0; c0 < 128; c0 += BK){
      __syncthreads();
      #pragma unroll
      for (int rep = 0; rep < 2; rep++){
        int idx = rep * 256 + tid;
        int row = idx >> 2, cg = idx & 3;
        int o = offs[row];
        uint4 h = make_uint4(0,0,0,0), l = make_uint4(0,0,0,0);
        if (o >= 0){
          h = *(const uint4*)(xhi + o + c0 + cg*8);
          l = *(const uint4*)(xlo + o + c0 + cg*8);
        }
        *(uint4*)&Ahi[row*AP + cg*8] = h;
        *(uint4*)&Alo[row*AP + cg*8] = l;
      }
      #pragma unroll
      for (int rep = 0; rep < 2; rep++){
        int idx = rep * 256 + tid;
        int kr = idx >> 4, cg = idx & 15;
        int src = tap*16384 + (c0 + kr)*128 + cg*8;
        *(uint4*)&Bhi[kr*BP + cg*8] = *(const uint4*)(whi + src);
        *(uint4*)&Blo[kr*BP + cg*8] = *(const uint4*)(wlo + src);
      }
      __syncthreads();

      #pragma unroll
      for (int k16 = 0; k16 < 2; k16++){
        uint32_t af[4][4], bh[2][4], bl[2][4];
        #pragma unroll
        for (int mi = 0; mi < 4; mi++){
          int r = warp_m*64 + mi*16 + a_row_in;
          ldsm4(af[mi], &Ahi[r*AP + k16*16 + a_colb]);
        }
        #pragma unroll
        for (int nj = 0; nj < 2; nj++){
          int kr = k16*16 + b_krow;
          int nc = warp_n*32 + nj*16 + b_coln;
          ldsm4t(bh[nj], &Bhi[kr*BP + nc]);
          ldsm4t(bl[nj], &Blo[kr*BP + nc]);
        }
        #pragma unroll
        for (int mi = 0; mi < 4; mi++)
          #pragma unroll
          for (int ni = 0; ni < 4; ni++){
            const uint32_t* h = &bh[ni>>1][(ni&1)*2];
            const uint32_t* L = &bl[ni>>1][(ni&1)*2];
            mma_bf16(acc[mi][ni], af[mi], h[0], h[1]);
            mma_bf16(acc[mi][ni], af[mi], L[0], L[1]);
          }
        #pragma unroll
        for (int mi = 0; mi < 4; mi++){
          int r = warp_m*64 + mi*16 + a_row_in;
          ldsm4(af[mi], &Alo[r*AP + k16*16 + a_colb]);
        }
        #pragma unroll
        for (int mi = 0; mi < 4; mi++)
          #pragma unroll
          for (int ni = 0; ni < 4; ni++){
            const uint32_t* h = &bh[ni>>1][(ni&1)*2];
            mma_bf16(acc[mi][ni], af[mi], h[0], h[1]);
          }
      }
    }
  }

  #pragma unroll
  for (int mi = 0; mi < 4; mi++){
    int lv0 = warp_m*64 + mi*16 + (lane >> 2);
    #pragma unroll
    for (int ni = 0; ni < 4; ni++){
      int col = warp_n*32 + ni*8 + (lane & 3)*2;
      float2 bb = *(const float2*)&bias[col];
      #pragma unroll
      for (int h = 0; h < 2; h++){
        int rv = vbase + lv0 + h*8;
        int vw = rv & 15; int t = rv >> 4; int vh = t & 15; int vd = t >> 4;
        int od = 2*vd + pd, oh = 2*vh + ph, ow = 2*vw + pw;
        size_t oo = (size_t)((od*32 + oh)*32 + ow) * 128 + col;
        float2 r;
        r.x = acc[mi][ni][2*h+0] + bb.x;
        r.y = acc[mi][ni][2*h+1] + bb.y;
        *(float2*)&out[oo] = r;
      }
    }
  }
}

// ---------------------------------------------------------------------------
// Fused L5+L6 path tables (R6-proven).
// ---------------------------------------------------------------------------
__device__ __constant__ int c_np[2][3]   = {{2,2,0},{1,3,1}};
__device__ __constant__ int c_k1[2][3][3] = {{{1,0,0},{2,1,0},{0,0,0}},
                                             {{0,0,0},{2,1,0},{2,0,0}}};
__device__ __constant__ int c_k2[2][3][3] = {{{0,1,0},{1,2,0},{0,0,0}},
                                             {{0,0,0},{0,1,2},{2,0,0}}};

// P1 (R10-proven, verbatim): Wp + WpT
__global__ __launch_bounds__(256) void p1_wp(
    const float* __restrict__ w2, const float* __restrict__ w20)
{
  int t = blockIdx.x * 256 + threadIdx.x;
  if (t >= 27*27*128) return;
  int ci = t & 127;
  int k2l = (t >> 7) % 27;
  int k1l = t / (27*128);
  const float* a = w2 + ((size_t)k1l*128 + ci) * 64;
  const float* b = w20 + (size_t)k2l * 64 * 3;
  float s0 = 0.f, s1 = 0.f, s2 = 0.f;
  #pragma unroll 4
  for (int cm = 0; cm < 64; cm++){
    float av = a[cm];
    s0 = fmaf(av, b[cm*3+0], s0);
    s1 = fmaf(av, b[cm*3+1], s1);
    s2 = fmaf(av, b[cm*3+2], s2);
  }
  float* o = g_Wp + (size_t)t * 3;
  o[0] = s0; o[1] = s1; o[2] = s2;
  size_t kk = (size_t)k1l*27 + k2l;
  g_WpT[kk*384 + 0*128 + ci] = s0;
  g_WpT[kk*384 + 1*128 + ci] = s1;
  g_WpT[kk*384 + 2*128 + ci] = s2;
}

// P2 (R7-proven, verbatim): Weff[pz][dxl][co][ci]
__global__ __launch_bounds__(256) void p2_weff()
{
  int t = blockIdx.x * 256 + threadIdx.x;
  if (t >= 8*27*128) return;
  int ci = t & 127;
  int dxl = (t >> 7) % 27;
  int pz = t / (27*128);
  int jd = dxl / 9, jh = (dxl / 3) % 3, jw = dxl % 3;
  int pd = (pz >> 2) & 1, ph = (pz >> 1) & 1, pw = pz & 1;
  int nd = c_np[pd][jd], nh = c_np[ph][jh], nw = c_np[pw][jw];
  float s0 = 0.f, s1 = 0.f, s2 = 0.f;
  for (int a = 0; a < nd; a++)
  for (int b = 0; b < nh; b++)
  for (int c = 0; c < nw; c++){
    int k1l = (c_k1[pd][jd][a]*3 + c_k1[ph][jh][b])*3 + c_k1[pw][jw][c];
    int k2l = (c_k2[pd][jd][a]*3 + c_k2[ph][jh][b])*3 + c_k2[pw][jw][c];
    const float* wp = g_Wp + ((size_t)(k1l*27 + k2l)*128 + ci)*3;
    s0 += wp[0]; s1 += wp[1]; s2 += wp[2];
  }
  float* o = g_Weff + (size_t)(pz*27 + dxl) * 3 * 128;
  o[0*128 + ci] = s0;
  o[1*128 + ci] = s1;
  o[2*128 + ci] = s2;
}

// P3 (R6-proven, verbatim)
__global__ void p3_bias(const float* __restrict__ w20,
                        const float* __restrict__ b2,
                        const float* __restrict__ b20)
{
  int tid = threadIdx.x;
  if (tid < 81){
    int k2 = tid / 3, co = tid % 3;
    float s = 0.f;
    for (int cm = 0; cm < 64; cm++)
      s = fmaf(w20[(k2*64+cm)*3+co], b2[cm], s);
    g_bconv[tid] = s;
  }
  __syncthreads();
  if (tid < 3){
    float s = b20[tid];
    for (int k2 = 0; k2 < 27; k2++) s += g_bconv[k2*3+tid];
    g_btot[tid] = s;
  }
}

// ---------------------------------------------------------------------------
// NEW (round 12): fused L5+L6 consumer with ci-quad lanes (LDG.128/LDS.128).
// Same math as R7-proven fused56b; Weff slice staged in SMEM per block
// (one parity, 41.5KB). 4 voxels per warp (acc = 24 ull).
// ---------------------------------------------------------------------------
__global__ __launch_bounds__(256) void fused56c(
    const float* __restrict__ x, float* __restrict__ out)
{
  __shared__ float ws[27*384];   // [dxl][co][ci]

  const int wid  = threadIdx.x >> 5;
  const int lane = threadIdx.x & 31;
  const int pz = blockIdx.z;
  const int pd = (pz >> 2) & 1, ph = (pz >> 1) & 1, pw = pz & 1;
  const int l4 = 4 * lane;

  for (int i = threadIdx.x; i < 27*384; i += 256)
    ws[i] = g_Weff[pz*27*384 + i];
  __syncthreads();

  const int wg  = blockIdx.x * 8 + wid;   // 0..8191 per parity
  const int seg = wg & 7;
  const int row = wg >> 3;                // 0..1023
  const int rd = row >> 5, rh = row & 31;
  const int rw0 = seg * 4;

  ull acc[4][3][2];
  #pragma unroll
  for (int r = 0; r < 4; r++)
    #pragma unroll
    for (int c = 0; c < 3; c++){ acc[r][c][0] = 0ull; acc[r][c][1] = 0ull; }

  for (int jd = 0; jd <= 1 + pd; jd++){
    int id = rd + jd - 1;
    if ((unsigned)id >= 32u) continue;
    for (int jh = 0; jh <= 1 + ph; jh++){
      int ih = rh + jh - 1;
      if ((unsigned)ih >= 32u) continue;
      const float* xrow = x + (size_t)((id*32 + ih)*32) * 128;
      for (int jw = 0; jw <= 1 + pw; jw++){
        const int dxl = jd*9 + jh*3 + jw;
        const float* Wt = ws + dxl*384;
        float4 w0 = *(const float4*)(Wt +   0 + l4);
        float4 w1 = *(const float4*)(Wt + 128 + l4);
        float4 w2 = *(const float4*)(Wt + 256 + l4);
        ull w0a = ((const ull*)&w0)[0], w0b = ((const ull*)&w0)[1];
        ull w1a = ((const ull*)&w1)[0], w1b = ((const ull*)&w1)[1];
        ull w2a = ((const ull*)&w2)[0], w2b = ((const ull*)&w2)[1];
        #pragma unroll
        for (int r = 0; r < 4; r++){
          int iw = rw0 + r + jw - 1;
          if ((unsigned)iw < 32u){
            float4 xv = *(const float4*)(xrow + iw*128 + l4);
            ull xa = ((const ull*)&xv)[0], xb = ((const ull*)&xv)[1];
            ffma2(acc[r][0][0], xa, w0a); ffma2(acc[r][0][1], xb, w0b);
            ffma2(acc[r][1][0], xa, w1a); ffma2(acc[r][1][1], xb, w1b);
            ffma2(acc[r][2][0], xa, w2a); ffma2(acc[r][2][1], xb, w2b);
          }
        }
      }
    }
  }

  const float bt0 = g_btot[0], bt1 = g_btot[1], bt2 = g_btot[2];
  const int od = 2*rd + pd, oh = 2*rh + ph;

  #pragma unroll
  for (int r = 0; r < 4; r++){
    float s0, s1, s2;
    {
      float a, b, c, d;
      unpack2(acc[r][0][0], a, b); unpack2(acc[r][0][1], c, d); s0 = (a+b)+(c+d);
      unpack2(acc[r][1][0], a, b); unpack2(acc[r][1][1], c, d); s1 = (a+b)+(c+d);
      unpack2(acc[r][2][0], a, b); unpack2(acc[r][2][1], c, d); s2 = (a+b)+(c+d);
    }
    #pragma unroll
    for (int sh = 16; sh > 0; sh >>= 1){
      s0 += __shfl_xor_sync(0xffffffffu, s0, sh);
      s1 += __shfl_xor_sync(0xffffffffu, s1, sh);
      s2 += __shfl_xor_sync(0xffffffffu, s2, sh);
    }
    if (lane == 0){
      int ow = 2*(rw0 + r) + pw;
      float* op = out + (size_t)((od*64 + oh)*64 + ow) * 3;
      op[0] = s0 + bt0;
      op[1] = s1 + bt1;
      op[2] = s2 + bt2;
    }
  }
}

// ---------------------------------------------------------------------------
// NEW (round 12): fix56x — R8-proven boundary math with ci-quad lanes:
// per path-block 1 LDG.128 (x) + 3 LDG.128 (WpT) + 6 ffma2.
// ---------------------------------------------------------------------------
__global__ __launch_bounds__(256) void fix56x(
    const float* __restrict__ x, const float* __restrict__ b20,
    float* __restrict__ out)
{
  const int gw = blockIdx.x * 8 + (threadIdx.x >> 5);
  const int lane = threadIdx.x & 31;
  const int l4 = 4 * lane;

  int plane = gw / 4096, r = gw % 4096;
  int a = r / 64, b = r % 64;
  int od, oh, ow;
  if      (plane == 0){ od = 0;  oh = a; ow = b; }
  else if (plane == 1){ od = 63; oh = a; ow = b; }
  else if (plane == 2){ oh = 0;  od = a; ow = b; if (od==0||od==63) return; }
  else if (plane == 3){ oh = 63; od = a; ow = b; if (od==0||od==63) return; }
  else if (plane == 4){ ow = 0;  od = a; oh = b; if (od==0||od==63||oh==0||oh==63) return; }
  else               { ow = 63; od = a; oh = b; if (od==0||od==63||oh==0||oh==63) return; }

  ull a0[2] = {0ull, 0ull}, a1[2] = {0ull, 0ull}, a2[2] = {0ull, 0ull};
  float bias0 = __ldg(&b20[0]), bias1 = __ldg(&b20[1]), bias2 = __ldg(&b20[2]);

  for (int k2d = 0; k2d < 3; k2d++){
    int md = od + k2d - 1; if ((unsigned)md >= 64u) continue;
    int pmd = md & 1, rd = (md - pmd) >> 1;
    int n_d = pmd ? 1 : 2;
    int k1d[2], ixd[2];
    if (pmd){ k1d[0] = 1; ixd[0] = rd; }
    else    { k1d[0] = 0; ixd[0] = rd - 1; k1d[1] = 2; ixd[1] = rd; }
    for (int k2h = 0; k2h < 3; k2h++){
      int mh = oh + k2h - 1; if ((unsigned)mh >= 64u) continue;
      int pmh = mh & 1, rh = (mh - pmh) >> 1;
      int n_h = pmh ? 1 : 2;
      int k1h[2], ixh[2];
      if (pmh){ k1h[0] = 1; ixh[0] = rh; }
      else    { k1h[0] = 0; ixh[0] = rh - 1; k1h[1] = 2; ixh[1] = rh; }
      for (int k2w = 0; k2w < 3; k2w++){
        int mw = ow + k2w - 1; if ((unsigned)mw >= 64u) continue;
        int pmw = mw & 1, rw = (mw - pmw) >> 1;
        int n_w = pmw ? 1 : 2;
        int k1w[2], ixw[2];
        if (pmw){ k1w[0] = 1; ixw[0] = rw; }
        else    { k1w[0] = 0; ixw[0] = rw - 1; k1w[1] = 2; ixw[1] = rw; }

        int k2l = (k2d*3 + k2h)*3 + k2w;
        bias0 += g_bconv[k2l*3+0];
        bias1 += g_bconv[k2l*3+1];
        bias2 += g_bconv[k2l*3+2];

        for (int ia = 0; ia < n_d; ia++){
          if ((unsigned)ixd[ia] >= 32u) continue;
          for (int ib = 0; ib < n_h; ib++){
            if ((unsigned)ixh[ib] >= 32u) continue;
            for (int ic = 0; ic < n_w; ic++){
              if ((unsigned)ixw[ic] >= 32u) continue;
              int k1l = (k1d[ia]*3 + k1h[ib])*3 + k1w[ic];
              const float* wt = g_WpT + (size_t)(k1l*27 + k2l)*384;
              const float* xp = x + (size_t)((ixd[ia]*32 + ixh[ib])*32 + ixw[ic])*128;
              float4 xv = *(const float4*)(xp + l4);
              float4 w0 = *(const float4*)(wt +   0 + l4);
              float4 w1 = *(const float4*)(wt + 128 + l4);
              float4 w2 = *(const float4*)(wt + 256 + l4);
              ull xa = ((const ull*)&xv)[0], xb = ((const ull*)&xv)[1];
              ffma2(a0[0], xa, ((const ull*)&w0)[0]);
              ffma2(a0[1], xb, ((const ull*)&w0)[1]);
              ffma2(a1[0], xa, ((const ull*)&w1)[0]);
              ffma2(a1[1], xb, ((const ull*)&w1)[1]);
              ffma2(a2[0], xa, ((const ull*)&w2)[0]);
              ffma2(a2[1], xb, ((const ull*)&w2)[1]);
            }
          }
        }
      }
    }
  }

  float s0, s1, s2;
  {
    float u, v, w, z;
    unpack2(a0[0], u, v); unpack2(a0[1], w, z); s0 = (u+v)+(w+z);
    unpack2(a1[0], u, v); unpack2(a1[1], w, z); s1 = (u+v)+(w+z);
    unpack2(a2[0], u, v); unpack2(a2[1], w, z); s2 = (u+v)+(w+z);
  }
  #pragma unroll
  for (int sh = 16; sh > 0; sh >>= 1){
    s0 += __shfl_xor_sync(0xffffffffu, s0, sh);
    s1 += __shfl_xor_sync(0xffffffffu, s1, sh);
    s2 += __shfl_xor_sync(0xffffffffu, s2, sh);
  }
  if (lane == 0){
    float* op = out + (size_t)((od*64 + oh)*64 + ow) * 3;
    op[0] = s0 + bias0;
    op[1] = s1 + bias1;
    op[2] = s2 + bias2;
  }
}

// ---------------------------------------------------------------------------
// kernel_launch
// ---------------------------------------------------------------------------
extern "C" void kernel_launch(void* const* d_in, const int* in_sizes, int n_in,
                              void* d_out, int out_size)
{
  (void)in_sizes; (void)n_in; (void)out_size;
  const float* x   = (const float*)d_in[0];
  const float* w0  = (const float*)d_in[1];
  const float* b0  = (const float*)d_in[2];
  const float* w00 = (const float*)d_in[3];
  const float* b00 = (const float*)d_in[4];
  const float* w1  = (const float*)d_in[5];
  const float* b1  = (const float*)d_in[6];
  const float* w10 = (const float*)d_in[7];
  const float* b10 = (const float*)d_in[8];
  const float* w2  = (const float*)d_in[9];
  const float* b2  = (const float*)d_in[10];
  const float* w20 = (const float*)d_in[11];
  const float* b20 = (const float*)d_in[12];
  float* out = (float*)d_out;

  float *bufA = nullptr, *bufB = nullptr;
  __nv_bfloat16 *xhi, *xlo, *whi, *wlo, *whiB, *wloB;
  cudaGetSymbolAddress((void**)&bufA, g_bufA);
  cudaGetSymbolAddress((void**)&bufB, g_bufB);
  cudaGetSymbolAddress((void**)&xhi, g_xhi);
  cudaGetSymbolAddress((void**)&xlo, g_xlo);
  cudaGetSymbolAddress((void**)&whi, g_whi);
  cudaGetSymbolAddress((void**)&wlo, g_wlo);
  cudaGetSymbolAddress((void**)&whiB, g_whiB);
  cudaGetSymbolAddress((void**)&wloB, g_wloB);

  static bool attr_set = false;
  const int PIPE_SMEM = 2*37888 + 27*128*4;   // 89600 B
  if (!attr_set){
    cudaFuncSetAttribute(mma_s1r_pipe,
                         cudaFuncAttributeMaxDynamicSharedMemorySize, PIPE_SMEM);
    attr_set = true;
  }

  // (1) Wp + WpT precompute (input-only deps)
  p1_wp<<<(27*27*128 + 255)/256, 256>>>(w2, w20);
  // (2) split w1 for L3 HMMA
  split_w_kernel<<<1728, 256>>>(w1, whiB, wloB);
  // (3) L1: deconv0 s2: x(8^3,128) -> bufA(16^3,128)   [R1 proven]
  {
    dim3 g(512/32, 128/64, 8);
    deconv_gemm<32,2><<<g, 256>>>(x,  w0,  b0,  bufA,
                                  8,8,8,128,  16,16,16,128, 2, 0);
  }
  // (4) L2: deconv0_0 s1 + relu: bufA -> bufB(16^3,128)   [R1 proven]
  {
    dim3 g(4096/32, 128/64, 1);
    deconv_gemm<32,2><<<g, 256>>>(bufA, w00, b00, bufB,
                                  16,16,16,128, 16,16,16,128, 1, 1);
  }
  // (5) split L2 output for L3 HMMA
  split_x_kernel<<<512, 256>>>(bufB, xhi, xlo, 524288/4);
  // (6) L3 on HMMA   [R10 proven]
  {
    dim3 g(32, 1, 8);
    mma_s2<<<g, 256>>>(xhi, xlo, whiB, wloB, b1, bufA);
  }
  // (7) split w10 for L4 HMMA
  split_w_kernel<<<1728, 256>>>(w10, whi, wlo);
  // (8) split L3 output for L4 HMMA
  split_x_kernel<<<4096, 256>>>(bufA, xhi, xlo, 4194304/4);
  // (9) L4 on pipelined HMMA   [R11 proven]
  mma_s1r_pipe<<<256, 256, PIPE_SMEM>>>(xhi, xlo, whi, wlo, b10, bufB);
  // (10-11) fused-weight precompute for L5+L6
  p2_weff<<<(8*27*128 + 255)/256, 256>>>();
  p3_bias<<<1, 128>>>(w20, b2, b20);
  // (12) Fused L5+L6 with ci-quad lanes + SMEM weights   [NEW]
  {
    dim3 g(1024, 1, 8);
    fused56c<<<g, 256>>>(bufB, out);
  }
  // (13) Exact boundary fix with ci-quad lanes   [NEW]
  fix56x<<<3072, 256>>>(bufB, b20, out);
}

// round 13
// speedup vs baseline: 1.2505x; 1.2505x over previous
#include <cuda_runtime.h>
#include <cuda_bf16.h>
#include <cstdint>

// ---------------------------------------------------------------------------
// Static scratch (no allocation allowed)
// ---------------------------------------------------------------------------
__device__ float g_bufA[16777216];
__device__ float g_bufB[4194304];
__device__ float g_part[2097152];   // 4 x (4096 voxels x 128 couts) L2 partials
__device__ float g_Wp[279936];
__device__ float g_WpT[279936];
__device__ float g_Weff[110592];
__device__ float g_bconv[81];
__device__ float g_btot[3];
__device__ __nv_bfloat16 g_xhi[4194304];
__device__ __nv_bfloat16 g_xlo[4194304];
__device__ __nv_bfloat16 g_whi[442368];    // L4 weights (w10)
__device__ __nv_bfloat16 g_wlo[442368];
__device__ __nv_bfloat16 g_whiB[442368];   // L3 weights (w1)
__device__ __nv_bfloat16 g_wloB[442368];
__device__ __nv_bfloat16 g_whiC[442368];   // L2 weights (w00)
__device__ __nv_bfloat16 g_wloC[442368];

typedef unsigned long long ull;

// ---------------------------------------------------------------------------
// f32x2 packed helpers
// ---------------------------------------------------------------------------
__device__ __forceinline__ ull pack2(float x, float y){
  ull r; asm("mov.b64 %0, {%1, %2};" : "=l"(r) : "f"(x), "f"(y)); return r;
}
__device__ __forceinline__ void unpack2(ull v, float& x, float& y){
  asm("mov.b64 {%0, %1}, %2;" : "=f"(x), "=f"(y) : "l"(v));
}
__device__ __forceinline__ void ffma2(ull& acc, ull a, ull b){
  asm("fma.rn.f32x2 %0, %1, %2, %0;" : "+l"(acc) : "l"(a), "l"(b));
}

// ---------------------------------------------------------------------------
// mma.sync / ldmatrix / cp.async helpers (baseline PTX, legal on sm_103)
// ---------------------------------------------------------------------------
__device__ __forceinline__ void ldsm4(uint32_t* r, const void* p){
  uint32_t a = (uint32_t)__cvta_generic_to_shared(p);
  asm volatile("ldmatrix.sync.aligned.m8n8.x4.shared.b16 {%0,%1,%2,%3}, [%4];"
    : "=r"(r[0]), "=r"(r[1]), "=r"(r[2]), "=r"(r[3]) : "r"(a));
}
__device__ __forceinline__ void ldsm4t(uint32_t* r, const void* p){
  uint32_t a = (uint32_t)__cvta_generic_to_shared(p);
  asm volatile("ldmatrix.sync.aligned.m8n8.x4.trans.shared.b16 {%0,%1,%2,%3}, [%4];"
    : "=r"(r[0]), "=r"(r[1]), "=r"(r[2]), "=r"(r[3]) : "r"(a));
}
__device__ __forceinline__ void mma_bf16(float* c, const uint32_t* a,
                                         uint32_t b0, uint32_t b1){
  asm volatile("mma.sync.aligned.m16n8k16.row.col.f32.bf16.bf16.f32 "
    "{%0,%1,%2,%3}, {%4,%5,%6,%7}, {%8,%9}, {%0,%1,%2,%3};"
    : "+f"(c[0]), "+f"(c[1]), "+f"(c[2]), "+f"(c[3])
    : "r"(a[0]), "r"(a[1]), "r"(a[2]), "r"(a[3]), "r"(b0), "r"(b1));
}
__device__ __forceinline__ void cpasync16(void* dst, const void* src, bool pred){
  uint32_t d = (uint32_t)__cvta_generic_to_shared(dst);
  int sz = pred ? 16 : 0;
  asm volatile("cp.async.cg.shared.global [%0], [%1], 16, %2;"
               :: "r"(d), "l"(src), "r"(sz));
}
#define CP_COMMIT() asm volatile("cp.async.commit_group;")
#define CP_WAIT1()  asm volatile("cp.async.wait_group 1;")
#define CP_WAIT0()  asm volatile("cp.async.wait_group 0;")

// ---------------------------------------------------------------------------
// ROUND-1 PROVEN KERNEL (verbatim): generic transposed-conv implicit GEMM.
// Used only for L1 now.
// ---------------------------------------------------------------------------
template<int BM, int TM>
__global__ __launch_bounds__(256) void deconv_gemm(
    const float* __restrict__ x, const float* __restrict__ w,
    const float* __restrict__ bias, float* __restrict__ out,
    int inD, int inH, int inW, int Cin,
    int outD, int outH, int outW, int Cout,
    int stride, int relu)
{
  constexpr int BN = 64;
  constexpr int BK = 16;
  constexpr int NP = TM / 2;

  __shared__ float As[BK][BM];
  __shared__ float Bs[BK][BN];
  __shared__ int   offs[BM];

  const int tid = threadIdx.x;
  const int pz = blockIdx.z;
  const int pd = (pz >> 2) & 1, ph = (pz >> 1) & 1, pw = pz & 1;
  const int rH = outH / stride, rW = outW / stride;
  const int nb = blockIdx.y * BN;
  const int vbase = blockIdx.x * BM;

  int md = 0, mh = 0, mw = 0;
  if (tid < BM) {
    int rv = vbase + tid;
    mw = rv % rW; int t = rv / rW; mh = t % rH; md = t / rH;
  }

  int nkd, kdL[3], ddL[3];
  int nkh, khL[3], dhL[3];
  int nkw, kwL[3], dwL[3];
  auto mk = [&](int p, int& n, int* kL, int* dL){
    if (stride == 1){ n = 3; kL[0]=0; kL[1]=1; kL[2]=2; dL[0]=-1; dL[1]=0; dL[2]=1; }
    else if (p == 0){ n = 2; kL[0]=0; kL[1]=2; dL[0]=-1; dL[1]=0; }
    else            { n = 1; kL[0]=1; dL[0]=0; }
  };
  mk(pd, nkd, kdL, ddL);
  mk(ph, nkh, khL, dhL);
  mk(pw, nkw, kwL, dwL);

  const int mg = tid >> 4, ng = tid & 15;
  const int m0 = mg * TM, n0 = ng * 4;

  ull acc[NP][4];
  #pragma unroll
  for (int i = 0; i < NP; i++)
    #pragma unroll
    for (int j = 0; j < 4; j++) acc[i][j] = 0ull;

  for (int ia = 0; ia < nkd; ia++)
  for (int ib = 0; ib < nkh; ib++)
  for (int ic = 0; ic < nkw; ic++){
    const int tap = (kdL[ia]*3 + khL[ib])*3 + kwL[ic];
    const float* wt = w + (size_t)tap * Cin * Cout + nb;

    __syncthreads();
    if (tid < BM){
      int id = md + ddL[ia];
      int ih = mh + dhL[ib];
      int iw = mw + dwL[ic];
      bool v = (unsigned)id < (unsigned)inD &&
               (unsigned)ih < (unsigned)inH &&
               (unsigned)iw < (unsigned)inW;
      offs[tid] = v ? ((id*inH + ih)*inW + iw) * Cin : -1;
    }

    for (int c0 = 0; c0 < Cin; c0 += BK){
      __syncthreads();
      for (int idx = tid; idx < BM*4; idx += 256){
        int v = idx >> 2, c4 = (idx & 3) * 4;
        int o = offs[v];
        float4 val = make_float4(0.f, 0.f, 0.f, 0.f);
        if (o >= 0) val = *(const float4*)(x + o + c0 + c4);
        As[c4+0][v] = val.x; As[c4+1][v] = val.y;
        As[c4+2][v] = val.z; As[c4+3][v] = val.w;
      }
      {
        int r = tid >> 4, col = (tid & 15) * 4;
        float4 bv = *(const float4*)(wt + (size_t)(c0 + r) * Cout + col);
        *(float4*)&Bs[r][col] = bv;
      }
      __syncthreads();
      #pragma unroll
      for (int kk = 0; kk < BK; kk++){
        const ull* a64 = (const ull*)&As[kk][m0];
        float4 bv = *(const float4*)&Bs[kk][n0];
        ull bp0 = pack2(bv.x, bv.x);
        ull bp1 = pack2(bv.y, bv.y);
        ull bp2 = pack2(bv.z, bv.z);
        ull bp3 = pack2(bv.w, bv.w);
        #pragma unroll
        for (int i = 0; i < NP; i++){
          ull av = a64[i];
          ffma2(acc[i][0], av, bp0);
          ffma2(acc[i][1], av, bp1);
          ffma2(acc[i][2], av, bp2);
          ffma2(acc[i][3], av, bp3);
        }
      }
    }
  }

  float4 b4 = *(const float4*)&bias[nb + n0];
  #pragma unroll
  for (int i = 0; i < NP; i++){
    float r0[4], r1[4];
    #pragma unroll
    for (int j = 0; j < 4; j++) unpack2(acc[i][j], r0[j], r1[j]);
    #pragma unroll
    for (int h = 0; h < 2; h++){
      float* rr = h ? r1 : r0;
      int rv = vbase + m0 + 2*i + h;
      int vw = rv % rW; int t = rv / rW; int vh = t % rH; int vd = t / rH;
      int od = vd*stride + pd, oh = vh*stride + ph, ow = vw*stride + pw;
      size_t oo = (size_t)((od*outH + oh)*outW + ow) * Cout + nb + n0;
      float4 res;
      res.x = rr[0] + b4.x; res.y = rr[1] + b4.y;
      res.z = rr[2] + b4.z; res.w = rr[3] + b4.w;
      if (relu){
        res.x = fmaxf(res.x, 0.f); res.y = fmaxf(res.y, 0.f);
        res.z = fmaxf(res.z, 0.f); res.w = fmaxf(res.w, 0.f);
      }
      *(float4*)&out[oo] = res;
    }
  }
}

// ---------------------------------------------------------------------------
// bf16 hi/lo split pre-passes (R9-proven, verbatim)
// ---------------------------------------------------------------------------
__global__ __launch_bounds__(256) void split_x_kernel(
    const float* __restrict__ x, __nv_bfloat16* __restrict__ hi,
    __nv_bfloat16* __restrict__ lo, int n4)
{
  int i = blockIdx.x * 256 + threadIdx.x;
  if (i >= n4) return;
  float4 v = ((const float4*)x)[i];
  __nv_bfloat16 h0 = __float2bfloat16_rn(v.x);
  __nv_bfloat16 h1 = __float2bfloat16_rn(v.y);
  __nv_bfloat16 h2 = __float2bfloat16_rn(v.z);
  __nv_bfloat16 h3 = __float2bfloat16_rn(v.w);
  __nv_bfloat16 l0 = __float2bfloat16_rn(v.x - __bfloat162float(h0));
  __nv_bfloat16 l1 = __float2bfloat16_rn(v.y - __bfloat162float(h1));
  __nv_bfloat16 l2 = __float2bfloat16_rn(v.z - __bfloat162float(h2));
  __nv_bfloat16 l3 = __float2bfloat16_rn(v.w - __bfloat162float(h3));
  ushort4 hv = make_ushort4(*(unsigned short*)&h0, *(unsigned short*)&h1,
                            *(unsigned short*)&h2, *(unsigned short*)&h3);
  ushort4 lv = make_ushort4(*(unsigned short*)&l0, *(unsigned short*)&l1,
                            *(unsigned short*)&l2, *(unsigned short*)&l3);
  ((ushort4*)hi)[i] = hv;
  ((ushort4*)lo)[i] = lv;
}

__global__ __launch_bounds__(256) void split_w_kernel(
    const float* __restrict__ w, __nv_bfloat16* __restrict__ hi,
    __nv_bfloat16* __restrict__ lo)
{
  int i = blockIdx.x * 256 + threadIdx.x;
  if (i >= 27*128*128) return;
  float v = w[i];
  __nv_bfloat16 h = __float2bfloat16_rn(v);
  hi[i] = h;
  lo[i] = __float2bfloat16_rn(v - __bfloat162float(h));
}

// ---------------------------------------------------------------------------
// NEW (round 13): L2 on HMMA with tap-split partials.
// DIM=16, C=128. gridDim.y selects tap group [tap0, tap1); raw f32 partials
// stored to part[y]. Core = R9-proven mma_s1r (ldsm/mma verbatim).
// ---------------------------------------------------------------------------
__global__ __launch_bounds__(256, 2) void mma_s1_part(
    const __nv_bfloat16* __restrict__ xhi, const __nv_bfloat16* __restrict__ xlo,
    const __nv_bfloat16* __restrict__ whi, const __nv_bfloat16* __restrict__ wlo,
    float* __restrict__ part)
{
  constexpr int BM = 128, BK = 32;
  constexpr int AP = 40;
  constexpr int BP = 136;

  __shared__ __align__(16) unsigned short Ahi[BM*AP];
  __shared__ __align__(16) unsigned short Alo[BM*AP];
  __shared__ __align__(16) unsigned short Bhi[BK*BP];
  __shared__ __align__(16) unsigned short Blo[BK*BP];
  __shared__ int offs[BM];

  const int tid  = threadIdx.x;
  const int lane = tid & 31;
  const int wid  = tid >> 5;
  const int warp_m = wid >> 2;
  const int warp_n = wid & 3;
  const int vbase = blockIdx.x * BM;
  const int tap0 = blockIdx.y * 7;
  const int tap1 = min(27, tap0 + 7);
  float* outp = part + (size_t)blockIdx.y * 524288;

  int md, mh, mw;
  { int rv = vbase + (tid & 127);
    mw = rv & 15; int t = rv >> 4; mh = t & 15; md = t >> 4; }

  const int a_row_in = lane & 15;
  const int a_colb   = (lane >> 4) << 3;
  const int b_krow   = lane & 15;
  const int b_coln   = (lane >> 4) << 3;

  float acc[4][4][4];
  #pragma unroll
  for (int mi = 0; mi < 4; mi++)
    #pragma unroll
    for (int ni = 0; ni < 4; ni++)
      #pragma unroll
      for (int q = 0; q < 4; q++) acc[mi][ni][q] = 0.f;

  for (int tap = tap0; tap < tap1; tap++){
    const int kw = tap % 3, kh = (tap / 3) % 3, kd = tap / 9;
    __syncthreads();
    if (tid < BM){
      int id = md + kd - 1, ih = mh + kh - 1, iw = mw + kw - 1;
      bool v = (unsigned)id < 16u && (unsigned)ih < 16u && (unsigned)iw < 16u;
      offs[tid] = v ? ((id*16 + ih)*16 + iw) * 128 : -1;
    }

    for (int c0 = 0; c0 < 128; c0 += BK){
      __syncthreads();
      #pragma unroll
      for (int rep = 0; rep < 2; rep++){
        int idx = rep * 256 + tid;
        int row = idx >> 2, cg = idx & 3;
        int o = offs[row];
        uint4 h = make_uint4(0,0,0,0), l = make_uint4(0,0,0,0);
        if (o >= 0){
          h = *(const uint4*)(xhi + o + c0 + cg*8);
          l = *(const uint4*)(xlo + o + c0 + cg*8);
        }
        *(uint4*)&Ahi[row*AP + cg*8] = h;
        *(uint4*)&Alo[row*AP + cg*8] = l;
      }
      #pragma unroll
      for (int rep = 0; rep < 2; rep++){
        int idx = rep * 256 + tid;
        int kr = idx >> 4, cg = idx & 15;
        int src = tap*16384 + (c0 + kr)*128 + cg*8;
        *(uint4*)&Bhi[kr*BP + cg*8] = *(const uint4*)(whi + src);
        *(uint4*)&Blo[kr*BP + cg*8] = *(const uint4*)(wlo + src);
      }
      __syncthreads();

      #pragma unroll
      for (int k16 = 0; k16 < 2; k16++){
        uint32_t af[4][4], bh[2][4], bl[2][4];
        #pragma unroll
        for (int mi = 0; mi < 4; mi++){
          int r = warp_m*64 + mi*16 + a_row_in;
          ldsm4(af[mi], &Ahi[r*AP + k16*16 + a_colb]);
        }
        #pragma unroll
        for (int nj = 0; nj < 2; nj++){
          int kr = k16*16 + b_krow;
          int nc = warp_n*32 + nj*16 + b_coln;
          ldsm4t(bh[nj], &Bhi[kr*BP + nc]);
          ldsm4t(bl[nj], &Blo[kr*BP + nc]);
        }
        #pragma unroll
        for (int mi = 0; mi < 4; mi++)
          #pragma unroll
          for (int ni = 0; ni < 4; ni++){
            const uint32_t* h = &bh[ni>>1][(ni&1)*2];
            const uint32_t* L = &bl[ni>>1][(ni&1)*2];
            mma_bf16(acc[mi][ni], af[mi], h[0], h[1]);
            mma_bf16(acc[mi][ni], af[mi], L[0], L[1]);
          }
        #pragma unroll
        for (int mi = 0; mi < 4; mi++){
          int r = warp_m*64 + mi*16 + a_row_in;
          ldsm4(af[mi], &Alo[r*AP + k16*16 + a_colb]);
        }
        #pragma unroll
        for (int mi = 0; mi < 4; mi++)
          #pragma unroll
          for (int ni = 0; ni < 4; ni++){
            const uint32_t* h = &bh[ni>>1][(ni&1)*2];
            mma_bf16(acc[mi][ni], af[mi], h[0], h[1]);
          }
      }
    }
  }

  // raw partial store (no bias/relu)
  #pragma unroll
  for (int mi = 0; mi < 4; mi++){
    int v0 = vbase + warp_m*64 + mi*16 + (lane >> 2);
    #pragma unroll
    for (int ni = 0; ni < 4; ni++){
      int col = warp_n*32 + ni*8 + (lane & 3)*2;
      *(float2*)&outp[(size_t)v0*128 + col] =
          make_float2(acc[mi][ni][0], acc[mi][ni][1]);
      *(float2*)&outp[(size_t)(v0+8)*128 + col] =
          make_float2(acc[mi][ni][2], acc[mi][ni][3]);
    }
  }
}

// L2 finish: sum 4 partials + bias + relu -> out (4096 x 128)
__global__ __launch_bounds__(256) void l2_finish(
    const float* __restrict__ part, const float* __restrict__ bias,
    float* __restrict__ out)
{
  int i = blockIdx.x * 256 + threadIdx.x;   // over 131072 float4 groups
  if (i >= 131072) return;
  float4 s = ((const float4*)part)[i];
  float4 p1 = ((const float4*)(part + 524288))[i];
  float4 p2 = ((const float4*)(part + 1048576))[i];
  float4 p3 = ((const float4*)(part + 1572864))[i];
  int col = (i * 4) & 127;
  float4 b = *(const float4*)&bias[col];
  float4 r;
  r.x = fmaxf(s.x + p1.x + p2.x + p3.x + b.x, 0.f);
  r.y = fmaxf(s.y + p1.y + p2.y + p3.y + b.y, 0.f);
  r.z = fmaxf(s.z + p1.z + p2.z + p3.z + b.z, 0.f);
  r.w = fmaxf(s.w + p1.w + p2.w + p3.w + b.w, 0.f);
  ((float4*)out)[i] = r;
}

// ---------------------------------------------------------------------------
// R11-PROVEN (verbatim): L4 on HMMA with cp.async 2-stage pipeline.
// ---------------------------------------------------------------------------
__global__ __launch_bounds__(256, 2) void mma_s1r_pipe(
    const __nv_bfloat16* __restrict__ xhi, const __nv_bfloat16* __restrict__ xlo,
    const __nv_bfloat16* __restrict__ whi, const __nv_bfloat16* __restrict__ wlo,
    const float* __restrict__ bias, float* __restrict__ out)
{
  constexpr int AP = 40, BP = 136;
  constexpr int ASZ = 128*AP;
  constexpr int BSZ = 32*BP;
  constexpr int STG = 2*ASZ + 2*BSZ;
  constexpr int NIT = 27*4;

  extern __shared__ __align__(16) unsigned short dsm[];
  int* offsAll = (int*)(dsm + 2*STG);

  const int tid  = threadIdx.x;
  const int lane = tid & 31;
  const int wid  = tid >> 5;
  const int warp_m = wid >> 2;
  const int warp_n = wid & 3;
  const int vbase = blockIdx.x * 128;

  for (int s = tid; s < 27*128; s += 256){
    int tap = s >> 7, row = s & 127;
    int kw = tap % 3, kh = (tap/3)%3, kd = tap/9;
    int rv = vbase + row;
    int mw = rv & 31, mh = (rv>>5)&31, md = rv>>10;
    int id = md + kd - 1, ih = mh + kh - 1, iw = mw + kw - 1;
    bool v = (unsigned)id < 32u && (unsigned)ih < 32u && (unsigned)iw < 32u;
    offsAll[s] = v ? ((id*32 + ih)*32 + iw) * 128 : -1;
  }
  __syncthreads();

  const int a_row_in = lane & 15;
  const int a_colb   = (lane >> 4) << 3;
  const int b_krow   = lane & 15;
  const int b_coln   = (lane >> 4) << 3;

  float acc[4][4][4];
  #pragma unroll
  for (int mi = 0; mi < 4; mi++)
    #pragma unroll
    for (int ni = 0; ni < 4; ni++)
      #pragma unroll
      for (int q = 0; q < 4; q++) acc[mi][ni][q] = 0.f;

  auto fill = [&](int st, int it){
    int tap = it >> 2, c0 = (it & 3) * 32;
    unsigned short* Ah = dsm + st*STG;
    unsigned short* Al = Ah + ASZ;
    unsigned short* Bh = Ah + 2*ASZ;
    unsigned short* Bl = Bh + BSZ;
    #pragma unroll
    for (int rep = 0; rep < 2; rep++){
      int idx = rep*256 + tid;
      int row = idx >> 2, cg = idx & 3;
      int o = offsAll[tap*128 + row];
      bool p = o >= 0;
      int ob = (p ? o : 0) + c0 + cg*8;
      cpasync16(&Ah[row*AP + cg*8], xhi + ob, p);
      cpasync16(&Al[row*AP + cg*8], xlo + ob, p);
    }
    #pragma unroll
    for (int rep = 0; rep < 2; rep++){
      int idx = rep*256 + tid;
      int kr = idx >> 4, cg = idx & 15;
      int src = tap*16384 + (c0 + kr)*128 + cg*8;
      cpasync16(&Bh[kr*BP + cg*8], whi + src, true);
      cpasync16(&Bl[kr*BP + cg*8], wlo + src, true);
    }
  };

  fill(0, 0);
  CP_COMMIT();

  for (int it = 0; it < NIT; ++it){
    const int b = it & 1;
    if (it + 1 < NIT){
      fill(b ^ 1, it + 1);
      CP_COMMIT();
      CP_WAIT1();
    } else {
      CP_WAIT0();
    }
    __syncthreads();

    const unsigned short* Ah = dsm + b*STG;
    const unsigned short* Al = Ah + ASZ;
    const unsigned short* Bh = Ah + 2*ASZ;
    const unsigned short* Bl = Bh + BSZ;

    #pragma unroll
    for (int k16 = 0; k16 < 2; k16++){
      uint32_t af[4][4], bh[2][4], bl[2][4];
      #pragma unroll
      for (int mi = 0; mi < 4; mi++){
        int r = warp_m*64 + mi*16 + a_row_in;
        ldsm4(af[mi], &Ah[r*AP + k16*16 + a_colb]);
      }
      #pragma unroll
      for (int nj = 0; nj < 2; nj++){
        int kr = k16*16 + b_krow;
        int nc = warp_n*32 + nj*16 + b_coln;
        ldsm4t(bh[nj], &Bh[kr*BP + nc]);
        ldsm4t(bl[nj], &Bl[kr*BP + nc]);
      }
      #pragma unroll
      for (int mi = 0; mi < 4; mi++)
        #pragma unroll
        for (int ni = 0; ni < 4; ni++){
          const uint32_t* h = &bh[ni>>1][(ni&1)*2];
          const uint32_t* L = &bl[ni>>1][(ni&1)*2];
          mma_bf16(acc[mi][ni], af[mi], h[0], h[1]);
          mma_bf16(acc[mi][ni], af[mi], L[0], L[1]);
        }
      #pragma unroll
      for (int mi = 0; mi < 4; mi++){
        int r = warp_m*64 + mi*16 + a_row_in;
        ldsm4(af[mi], &Al[r*AP + k16*16 + a_colb]);
      }
      #pragma unroll
      for (int mi = 0; mi < 4; mi++)
        #pragma unroll
        for (int ni = 0; ni < 4; ni++){
          const uint32_t* h = &bh[ni>>1][(ni&1)*2];
          mma_bf16(acc[mi][ni], af[mi], h[0], h[1]);
        }
    }
    __syncthreads();
  }

  #pragma unroll
  for (int mi = 0; mi < 4; mi++){
    int v0 = vbase + warp_m*64 + mi*16 + (lane >> 2);
    #pragma unroll
    for (int ni = 0; ni < 4; ni++){
      int col = warp_n*32 + ni*8 + (lane & 3)*2;
      float2 bb = *(const float2*)&bias[col];
      float2 r0, r1;
      r0.x = fmaxf(acc[mi][ni][0] + bb.x, 0.f);
      r0.y = fmaxf(acc[mi][ni][1] + bb.y, 0.f);
      r1.x = fmaxf(acc[mi][ni][2] + bb.x, 0.f);
      r1.y = fmaxf(acc[mi][ni][3] + bb.y, 0.f);
      *(float2*)&out[(size_t)v0*128 + col]     = r0;
      *(float2*)&out[(size_t)(v0+8)*128 + col] = r1;
    }
  }
}

// ---------------------------------------------------------------------------
// R10-PROVEN (verbatim): L3 on HMMA, stride-2 parity decomposition.
// ---------------------------------------------------------------------------
__global__ __launch_bounds__(256, 2) void mma_s2(
    const __nv_bfloat16* __restrict__ xhi, const __nv_bfloat16* __restrict__ xlo,
    const __nv_bfloat16* __restrict__ whi, const __nv_bfloat16* __restrict__ wlo,
    const float* __restrict__ bias, float* __restrict__ out)
{
  constexpr int BM = 128, BK = 32;
  constexpr int AP = 40;
  constexpr int BP = 136;

  __shared__ __align__(16) unsigned short Ahi[BM*AP];
  __shared__ __align__(16) unsigned short Alo[BM*AP];
  __shared__ __align__(16) unsigned short Bhi[BK*BP];
  __shared__ __align__(16) unsigned short Blo[BK*BP];
  __shared__ int offs[BM];

  const int tid  = threadIdx.x;
  const int lane = tid & 31;
  const int wid  = tid >> 5;
  const int warp_m = wid >> 2;
  const int warp_n = wid & 3;
  const int vbase = blockIdx.x * BM;
  const int pz = blockIdx.z;
  const int pd = (pz >> 2) & 1, ph = (pz >> 1) & 1, pw = pz & 1;

  int md, mh, mw;
  { int rv = vbase + (tid & 127);
    mw = rv & 15; int t = rv >> 4; mh = t & 15; md = t >> 4; }

  int nkd, kdL[2], ddL[2];
  int nkh, khL[2], dhL[2];
  int nkw, kwL[2], dwL[2];
  auto mk2 = [&](int p, int& n, int* kL, int* dL){
    if (p == 0){ n = 2; kL[0]=0; kL[1]=2; dL[0]=-1; dL[1]=0; }
    else       { n = 1; kL[0]=1; dL[0]=0; }
  };
  mk2(pd, nkd, kdL, ddL);
  mk2(ph, nkh, khL, dhL);
  mk2(pw, nkw, kwL, dwL);

  const int a_row_in = lane & 15;
  const int a_colb   = (lane >> 4) << 3;
  const int b_krow   = lane & 15;
  const int b_coln   = (lane >> 4) << 3;

  float acc[4][4][4];
  #pragma unroll
  for (int mi = 0; mi < 4; mi++)
    #pragma unroll
    for (int ni = 0; ni < 4; ni++)
      #pragma unroll
      for (int q = 0; q < 4; q++) acc[mi][ni][q] = 0.f;

  for (int ia = 0; ia < nkd; ia++)
  for (int ib = 0; ib < nkh; ib++)
  for (int ic = 0; ic < nkw; ic++){
    const int tap = (kdL[ia]*3 + khL[ib])*3 + kwL[ic];
    __syncthreads();
    if (tid < BM){
      int id = md + ddL[ia], ih = mh + dhL[ib], iw = mw + dwL[ic];
      bool v = (unsigned)id < 16u && (unsigned)ih < 16u && (unsigned)iw < 16u;
      offs[tid] = v ? ((id*16 + ih)*16 + iw) * 128 : -1;
    }

    for (int c0 = 0; c0 < 128; c0 += BK){
      __syncthreads();
      #pragma unroll
      for (int rep = 0; rep < 2; rep++){
        int idx = rep * 256 + tid;
        int row = idx >> 2, cg = idx & 3;
        int o = offs[row];
        uint4 h = make_uint4(0,0,0,0), l = make_uint4(0,0,0,0);
        if (o >= 0){
          h = *(const uint4*)(xhi + o + c0 + cg*8);
          l = *(const uint4*)(xlo + o + c0 + cg*8);
        }
        *(uint4*)&Ahi[row*AP + cg*8] = h;
        *(uint4*)&Alo[row*AP + cg*8] = l;
      }
      #pragma unroll
      for (int rep = 0; rep < 2; rep++){
        int idx = rep * 256 + tid;
        int kr = idx >> 4, cg = idx & 15;
        int src = tap*16384 + (c0 + kr)*128 + cg*8;
        *(uint4*)&Bhi[kr*BP + cg*8] = *(const uint4*)(whi + src);
        *(uint4*)&Blo[kr*BP + cg*8] = *(const uint4*)(wlo + src);
      }
      __syncthreads();

      #pragma unroll
      for (int k16 = 0; k16 < 2; k16++){
        uint32_t af[4][4], bh[2][4], bl[2][4];
        #pragma unroll
        for (int mi = 0; mi < 4; mi++){
          int r = warp_m*64 + mi*16 + a_row_in;
          ldsm4(af[mi], &Ahi[r*AP + k16*16 + a_colb]);
        }
        #pragma unroll
        for (int nj = 0; nj < 2; nj++){
          int kr = k16*16 + b_krow;
          int nc = warp_n*32 + nj*16 + b_coln;
          ldsm4t(bh[nj], &Bhi[kr*BP + nc]);
          ldsm4t(bl[nj], &Blo[kr*BP + nc]);
        }
        #pragma unroll
        for (int mi = 0; mi < 4; mi++)
          #pragma unroll
          for (int ni = 0; ni < 4; ni++){
            const uint32_t* h = &bh[ni>>1][(ni&1)*2];
            const uint32_t* L = &bl[ni>>1][(ni&1)*2];
            mma_bf16(acc[mi][ni], af[mi], h[0], h[1]);
            mma_bf16(acc[mi][ni], af[mi], L[0], L[1]);
          }
        #pragma unroll
        for (int mi = 0; mi < 4; mi++){
          int r = warp_m*64 + mi*16 + a_row_in;
          ldsm4(af[mi], &Alo[r*AP + k16*16 + a_colb]);
        }
        #pragma unroll
        for (int mi = 0; mi < 4; mi++)
          #pragma unroll
          for (int ni = 0; ni < 4; ni++){
            const uint32_t* h = &bh[ni>>1][(ni&1)*2];
            mma_bf16(acc[mi][ni], af[mi], h[0], h[1]);
          }
      }
    }
  }

  #pragma unroll
  for (int mi = 0; mi < 4; mi++){
    int lv0 = warp_m*64 + mi*16 + (lane >> 2);
    #pragma unroll
    for (int ni = 0; ni < 4; ni++){
      int col = warp_n*32 + ni*8 + (lane & 3)*2;
      float2 bb = *(const float2*)&bias[col];
      #pragma unroll
      for (int h = 0; h < 2; h++){
        int rv = vbase + lv0 + h*8;
        int vw = rv & 15; int t = rv >> 4; int vh = t & 15; int vd = t >> 4;
        int od = 2*vd + pd, oh = 2*vh + ph, ow = 2*vw + pw;
        size_t oo = (size_t)((od*32 + oh)*32 + ow) * 128 + col;
        float2 r;
        r.x = acc[mi][ni][2*h+0] + bb.x;
        r.y = acc[mi][ni][2*h+1] + bb.y;
        *(float2*)&out[oo] = r;
      }
    }
  }
}

// ---------------------------------------------------------------------------
// Fused L5+L6 path tables (R6-proven).
// ---------------------------------------------------------------------------
__device__ __constant__ int c_np[2][3]   = {{2,2,0},{1,3,1}};
__device__ __constant__ int c_k1[2][3][3] = {{{1,0,0},{2,1,0},{0,0,0}},
                                             {{0,0,0},{2,1,0},{2,0,0}}};
__device__ __constant__ int c_k2[2][3][3] = {{{0,1,0},{1,2,0},{0,0,0}},
                                             {{0,0,0},{0,1,2},{2,0,0}}};

// P1 (R10-proven, verbatim): Wp + WpT
__global__ __launch_bounds__(256) void p1_wp(
    const float* __restrict__ w2, const float* __restrict__ w20)
{
  int t = blockIdx.x * 256 + threadIdx.x;
  if (t >= 27*27*128) return;
  int ci = t & 127;
  int k2l = (t >> 7) % 27;
  int k1l = t / (27*128);
  const float* a = w2 + ((size_t)k1l*128 + ci) * 64;
  const float* b = w20 + (size_t)k2l * 64 * 3;
  float s0 = 0.f, s1 = 0.f, s2 = 0.f;
  #pragma unroll 4
  for (int cm = 0; cm < 64; cm++){
    float av = a[cm];
    s0 = fmaf(av, b[cm*3+0], s0);
    s1 = fmaf(av, b[cm*3+1], s1);
    s2 = fmaf(av, b[cm*3+2], s2);
  }
  float* o = g_Wp + (size_t)t * 3;
  o[0] = s0; o[1] = s1; o[2] = s2;
  size_t kk = (size_t)k1l*27 + k2l;
  g_WpT[kk*384 + 0*128 + ci] = s0;
  g_WpT[kk*384 + 1*128 + ci] = s1;
  g_WpT[kk*384 + 2*128 + ci] = s2;
}

// P2 (R7-proven, verbatim): Weff[pz][dxl][co][ci]
__global__ __launch_bounds__(256) void p2_weff()
{
  int t = blockIdx.x * 256 + threadIdx.x;
  if (t >= 8*27*128) return;
  int ci = t & 127;
  int dxl = (t >> 7) % 27;
  int pz = t / (27*128);
  int jd = dxl / 9, jh = (dxl / 3) % 3, jw = dxl % 3;
  int pd = (pz >> 2) & 1, ph = (pz >> 1) & 1, pw = pz & 1;
  int nd = c_np[pd][jd], nh = c_np[ph][jh], nw = c_np[pw][jw];
  float s0 = 0.f, s1 = 0.f, s2 = 0.f;
  for (int a = 0; a < nd; a++)
  for (int b = 0; b < nh; b++)
  for (int c = 0; c < nw; c++){
    int k1l = (c_k1[pd][jd][a]*3 + c_k1[ph][jh][b])*3 + c_k1[pw][jw][c];
    int k2l = (c_k2[pd][jd][a]*3 + c_k2[ph][jh][b])*3 + c_k2[pw][jw][c];
    const float* wp = g_Wp + ((size_t)(k1l*27 + k2l)*128 + ci)*3;
    s0 += wp[0]; s1 += wp[1]; s2 += wp[2];
  }
  float* o = g_Weff + (size_t)(pz*27 + dxl) * 3 * 128;
  o[0*128 + ci] = s0;
  o[1*128 + ci] = s1;
  o[2*128 + ci] = s2;
}

// P3 (R6-proven, verbatim)
__global__ void p3_bias(const float* __restrict__ w20,
                        const float* __restrict__ b2,
                        const float* __restrict__ b20)
{
  int tid = threadIdx.x;
  if (tid < 81){
    int k2 = tid / 3, co = tid % 3;
    float s = 0.f;
    for (int cm = 0; cm < 64; cm++)
      s = fmaf(w20[(k2*64+cm)*3+co], b2[cm], s);
    g_bconv[tid] = s;
  }
  __syncthreads();
  if (tid < 3){
    float s = b20[tid];
    for (int k2 = 0; k2 < 27; k2++) s += g_bconv[k2*3+tid];
    g_btot[tid] = s;
  }
}

// ---------------------------------------------------------------------------
// Fused L5+L6 consumer (R7-proven, verbatim).
// ---------------------------------------------------------------------------
__global__ __launch_bounds__(256) void fused56b(
    const float* __restrict__ x, float* __restrict__ out)
{
  const int wid  = threadIdx.x >> 5;
  const int lane = threadIdx.x & 31;
  const int pz = blockIdx.z;
  const int pd = (pz >> 2) & 1, ph = (pz >> 1) & 1, pw = pz & 1;
  const int wg  = blockIdx.x * 8 + wid;
  const int seg = wg & 3;
  const int row = wg >> 2;
  const int rd = row >> 5, rh = row & 31;
  const int rw0 = seg * 8;
  const int l2 = 2 * lane;

  ull acc[8][3];
  #pragma unroll
  for (int r = 0; r < 8; r++)
    #pragma unroll
    for (int c = 0; c < 3; c++) acc[r][c] = 0ull;

  for (int jd = 0; jd <= 1 + pd; jd++){
    int id = rd + jd - 1;
    if ((unsigned)id >= 32u) continue;
    for (int jh = 0; jh <= 1 + ph; jh++){
      int ih = rh + jh - 1;
      if ((unsigned)ih >= 32u) continue;
      const float* xrow = x + (size_t)((id*32 + ih)*32) * 128;
      for (int jw = 0; jw <= 1 + pw; jw++){
        const int dxl = jd*9 + jh*3 + jw;
        const float* Wt = g_Weff + (size_t)(pz*27 + dxl) * 3 * 128;
        ull w00 = *(const ull*)(Wt +   0 + l2);
        ull w01 = *(const ull*)(Wt +  64 + l2);
        ull w10 = *(const ull*)(Wt + 128 + l2);
        ull w11 = *(const ull*)(Wt + 192 + l2);
        ull w20 = *(const ull*)(Wt + 256 + l2);
        ull w21 = *(const ull*)(Wt + 320 + l2);
        #pragma unroll
        for (int r = 0; r < 8; r++){
          int iw = rw0 + r + jw - 1;
          if ((unsigned)iw < 32u){
            const float* xp = xrow + iw * 128;
            ull x0 = *(const ull*)(xp + l2);
            ull x1 = *(const ull*)(xp + 64 + l2);
            ffma2(acc[r][0], x0, w00); ffma2(acc[r][0], x1, w01);
            ffma2(acc[r][1], x0, w10); ffma2(acc[r][1], x1, w11);
            ffma2(acc[r][2], x0, w20); ffma2(acc[r][2], x1, w21);
          }
        }
      }
    }
  }

  const float bt0 = g_btot[0], bt1 = g_btot[1], bt2 = g_btot[2];
  const int od = 2*rd + pd, oh = 2*rh + ph;

  #pragma unroll
  for (int r = 0; r < 8; r++){
    float s0, s1, s2;
    {
      float a, b;
      unpack2(acc[r][0], a, b); s0 = a + b;
      unpack2(acc[r][1], a, b); s1 = a + b;
      unpack2(acc[r][2], a, b); s2 = a + b;
    }
    #pragma unroll
    for (int sh = 16; sh > 0; sh >>= 1){
      s0 += __shfl_xor_sync(0xffffffffu, s0, sh);
      s1 += __shfl_xor_sync(0xffffffffu, s1, sh);
      s2 += __shfl_xor_sync(0xffffffffu, s2, sh);
    }
    if (lane == 0){
      int ow = 2*(rw0 + r) + pw;
      float* op = out + (size_t)((od*64 + oh)*64 + ow) * 3;
      op[0] = s0 + bt0;
      op[1] = s1 + bt1;
      op[2] = s2 + bt2;
    }
  }
}

// ---------------------------------------------------------------------------
// fix56w (R8-proven, verbatim): warp-per-voxel exact boundary fix.
// ---------------------------------------------------------------------------
__global__ __launch_bounds__(256) void fix56w(
    const float* __restrict__ x, const float* __restrict__ b20,
    float* __restrict__ out)
{
  const int gw = blockIdx.x * 8 + (threadIdx.x >> 5);
  const int lane = threadIdx.x & 31;
  const int l2 = 2 * lane;

  int plane = gw / 4096, r = gw % 4096;
  int a = r / 64, b = r % 64;
  int od, oh, ow;
  if      (plane == 0){ od = 0;  oh = a; ow = b; }
  else if (plane == 1){ od = 63; oh = a; ow = b; }
  else if (plane == 2){ oh = 0;  od = a; ow = b; if (od==0||od==63) return; }
  else if (plane == 3){ oh = 63; od = a; ow = b; if (od==0||od==63) return; }
  else if (plane == 4){ ow = 0;  od = a; oh = b; if (od==0||od==63||oh==0||oh==63) return; }
  else               { ow = 63; od = a; oh = b; if (od==0||od==63||oh==0||oh==63) return; }

  ull a0 = 0ull, a1 = 0ull, a2 = 0ull;
  float bias0 = __ldg(&b20[0]), bias1 = __ldg(&b20[1]), bias2 = __ldg(&b20[2]);

  for (int k2d = 0; k2d < 3; k2d++){
    int md = od + k2d - 1; if ((unsigned)md >= 64u) continue;
    int pmd = md & 1, rd = (md - pmd) >> 1;
    int n_d = pmd ? 1 : 2;
    int k1d[2], ixd[2];
    if (pmd){ k1d[0] = 1; ixd[0] = rd; }
    else    { k1d[0] = 0; ixd[0] = rd - 1; k1d[1] = 2; ixd[1] = rd; }
    for (int k2h = 0; k2h < 3; k2h++){
      int mh = oh + k2h - 1; if ((unsigned)mh >= 64u) continue;
      int pmh = mh & 1, rh = (mh - pmh) >> 1;
      int n_h = pmh ? 1 : 2;
      int k1h[2], ixh[2];
      if (pmh){ k1h[0] = 1; ixh[0] = rh; }
      else    { k1h[0] = 0; ixh[0] = rh - 1; k1h[1] = 2; ixh[1] = rh; }
      for (int k2w = 0; k2w < 3; k2w++){
        int mw = ow + k2w - 1; if ((unsigned)mw >= 64u) continue;
        int pmw = mw & 1, rw = (mw - pmw) >> 1;
        int n_w = pmw ? 1 : 2;
        int k1w[2], ixw[2];
        if (pmw){ k1w[0] = 1; ixw[0] = rw; }
        else    { k1w[0] = 0; ixw[0] = rw - 1; k1w[1] = 2; ixw[1] = rw; }

        int k2l = (k2d*3 + k2h)*3 + k2w;
        bias0 += g_bconv[k2l*3+0];
        bias1 += g_bconv[k2l*3+1];
        bias2 += g_bconv[k2l*3+2];

        for (int ia = 0; ia < n_d; ia++){
          if ((unsigned)ixd[ia] >= 32u) continue;
          for (int ib = 0; ib < n_h; ib++){
            if ((unsigned)ixh[ib] >= 32u) continue;
            for (int ic = 0; ic < n_w; ic++){
              if ((unsigned)ixw[ic] >= 32u) continue;
              int k1l = (k1d[ia]*3 + k1h[ib])*3 + k1w[ic];
              const float* wt = g_WpT + (size_t)(k1l*27 + k2l)*384;
              const float* xp = x + (size_t)((ixd[ia]*32 + ixh[ib])*32 + ixw[ic])*128;
              ull x0 = *(const ull*)(xp + l2);
              ull x1 = *(const ull*)(xp + 64 + l2);
              ffma2(a0, x0, *(const ull*)(wt +   0 + l2));
              ffma2(a0, x1, *(const ull*)(wt +  64 + l2));
              ffma2(a1, x0, *(const ull*)(wt + 128 + l2));
              ffma2(a1, x1, *(const ull*)(wt + 192 + l2));
              ffma2(a2, x0, *(const ull*)(wt + 256 + l2));
              ffma2(a2, x1, *(const ull*)(wt + 320 + l2));
            }
          }
        }
      }
    }
  }

  float s0, s1, s2;
  {
    float u, v;
    unpack2(a0, u, v); s0 = u + v;
    unpack2(a1, u, v); s1 = u + v;
    unpack2(a2, u, v); s2 = u + v;
  }
  #pragma unroll
  for (int sh = 16; sh > 0; sh >>= 1){
    s0 += __shfl_xor_sync(0xffffffffu, s0, sh);
    s1 += __shfl_xor_sync(0xffffffffu, s1, sh);
    s2 += __shfl_xor_sync(0xffffffffu, s2, sh);
  }
  if (lane == 0){
    float* op = out + (size_t)((od*64 + oh)*64 + ow) * 3;
    op[0] = s0 + bias0;
    op[1] = s1 + bias1;
    op[2] = s2 + bias2;
  }
}

// ---------------------------------------------------------------------------
// kernel_launch
// ---------------------------------------------------------------------------
extern "C" void kernel_launch(void* const* d_in, const int* in_sizes, int n_in,
                              void* d_out, int out_size)
{
  (void)in_sizes; (void)n_in; (void)out_size;
  const float* x   = (const float*)d_in[0];
  const float* w0  = (const float*)d_in[1];
  const float* b0  = (const float*)d_in[2];
  const float* w00 = (const float*)d_in[3];
  const float* b00 = (const float*)d_in[4];
  const float* w1  = (const float*)d_in[5];
  const float* b1  = (const float*)d_in[6];
  const float* w10 = (const float*)d_in[7];
  const float* b10 = (const float*)d_in[8];
  const float* w2  = (const float*)d_in[9];
  const float* b2  = (const float*)d_in[10];
  const float* w20 = (const float*)d_in[11];
  const float* b20 = (const float*)d_in[12];
  float* out = (float*)d_out;

  float *bufA = nullptr, *bufB = nullptr, *part = nullptr;
  __nv_bfloat16 *xhi, *xlo, *whi, *wlo, *whiB, *wloB, *whiC, *wloC;
  cudaGetSymbolAddress((void**)&bufA, g_bufA);
  cudaGetSymbolAddress((void**)&bufB, g_bufB);
  cudaGetSymbolAddress((void**)&part, g_part);
  cudaGetSymbolAddress((void**)&xhi, g_xhi);
  cudaGetSymbolAddress((void**)&xlo, g_xlo);
  cudaGetSymbolAddress((void**)&whi, g_whi);
  cudaGetSymbolAddress((void**)&wlo, g_wlo);
  cudaGetSymbolAddress((void**)&whiB, g_whiB);
  cudaGetSymbolAddress((void**)&wloB, g_wloB);
  cudaGetSymbolAddress((void**)&whiC, g_whiC);
  cudaGetSymbolAddress((void**)&wloC, g_wloC);

  static bool attr_set = false;
  const int PIPE_SMEM = 2*37888 + 27*128*4;   // 89600 B
  if (!attr_set){
    cudaFuncSetAttribute(mma_s1r_pipe,
                         cudaFuncAttributeMaxDynamicSharedMemorySize, PIPE_SMEM);
    attr_set = true;
  }

  // (1) Wp + WpT precompute
  p1_wp<<<(27*27*128 + 255)/256, 256>>>(w2, w20);
  // (2-3) split weights for L2 + L3 HMMA
  split_w_kernel<<<1728, 256>>>(w00, whiC, wloC);
  split_w_kernel<<<1728, 256>>>(w1, whiB, wloB);
  // (4) L1: deconv0 s2: x(8^3,128) -> bufA(16^3,128)   [R1 proven]
  {
    dim3 g(512/32, 128/64, 8);
    deconv_gemm<32,2><<<g, 256>>>(x,  w0,  b0,  bufA,
                                  8,8,8,128,  16,16,16,128, 2, 0);
  }
  // (5) split L1 output for L2 HMMA
  split_x_kernel<<<512, 256>>>(bufA, xhi, xlo, 524288/4);
  // (6) L2 on HMMA with 4-way tap split -> partials   [NEW]
  {
    dim3 g(32, 4, 1);
    mma_s1_part<<<g, 256>>>(xhi, xlo, whiC, wloC, part);
  }
  // (7) L2 finish: sum partials + bias + relu -> bufB
  l2_finish<<<512, 256>>>(part, b00, bufB);
  // (8) split L2 output for L3 HMMA
  split_x_kernel<<<512, 256>>>(bufB, xhi, xlo, 524288/4);
  // (9) L3 on HMMA   [R10 proven]
  {
    dim3 g(32, 1, 8);
    mma_s2<<<g, 256>>>(xhi, xlo, whiB, wloB, b1, bufA);
  }
  // (10) split w10 for L4 HMMA
  split_w_kernel<<<1728, 256>>>(w10, whi, wlo);
  // (11) split L3 output for L4 HMMA
  split_x_kernel<<<4096, 256>>>(bufA, xhi, xlo, 4194304/4);
  // (12) L4 on pipelined HMMA   [R11 proven]
  mma_s1r_pipe<<<256, 256, PIPE_SMEM>>>(xhi, xlo, whi, wlo, b10, bufB);
  // (13-14) fused-weight precompute for L5+L6
  p2_weff<<<(8*27*128 + 255)/256, 256>>>();
  p3_bias<<<1, 128>>>(w20, b2, b20);
  // (15) Fused L5+L6   [R7 proven]
  {
    dim3 g(512, 1, 8);
    fused56b<<<g, 256>>>(bufB, out);
  }
  // (16) Exact boundary fix   [R8 proven]
  fix56w<<<3072, 256>>>(bufB, b20, out);
}

// round 14
// speedup vs baseline: 1.3911x; 1.1125x over previous
#include <cuda_runtime.h>
#include <cuda_bf16.h>
#include <cstdint>

// ---------------------------------------------------------------------------
// Static scratch (no allocation allowed)
// ---------------------------------------------------------------------------
__device__ float g_bufA[16777216];
__device__ float g_bufB[4194304];
__device__ float g_part[2097152];   // 4 x (4096 voxels x 128 couts) L2 partials
__device__ float g_Wp[279936];
__device__ float g_WpT[279936];
__device__ float g_Weff[110592];
__device__ float g_bconv[81];
__device__ float g_btot[3];
__device__ __nv_bfloat16 g_xhi[4194304];
__device__ __nv_bfloat16 g_xlo[4194304];
__device__ __nv_bfloat16 g_whi[442368];    // L4 weights (w10)
__device__ __nv_bfloat16 g_wlo[442368];
__device__ __nv_bfloat16 g_whiB[442368];   // L3 weights (w1)
__device__ __nv_bfloat16 g_wloB[442368];
__device__ __nv_bfloat16 g_whiC[442368];   // L2 weights (w00)
__device__ __nv_bfloat16 g_wloC[442368];
__device__ __nv_bfloat16 g_whiD[442368];   // L1 weights (w0)
__device__ __nv_bfloat16 g_wloD[442368];

typedef unsigned long long ull;

// ---------------------------------------------------------------------------
// f32x2 packed helpers
// ---------------------------------------------------------------------------
__device__ __forceinline__ ull pack2(float x, float y){
  ull r; asm("mov.b64 %0, {%1, %2};" : "=l"(r) : "f"(x), "f"(y)); return r;
}
__device__ __forceinline__ void unpack2(ull v, float& x, float& y){
  asm("mov.b64 {%0, %1}, %2;" : "=f"(x), "=f"(y) : "l"(v));
}
__device__ __forceinline__ void ffma2(ull& acc, ull a, ull b){
  asm("fma.rn.f32x2 %0, %1, %2, %0;" : "+l"(acc) : "l"(a), "l"(b));
}

// ---------------------------------------------------------------------------
// mma.sync / ldmatrix / cp.async helpers (baseline PTX, legal on sm_103)
// ---------------------------------------------------------------------------
__device__ __forceinline__ void ldsm4(uint32_t* r, const void* p){
  uint32_t a = (uint32_t)__cvta_generic_to_shared(p);
  asm volatile("ldmatrix.sync.aligned.m8n8.x4.shared.b16 {%0,%1,%2,%3}, [%4];"
    : "=r"(r[0]), "=r"(r[1]), "=r"(r[2]), "=r"(r[3]) : "r"(a));
}
__device__ __forceinline__ void ldsm4t(uint32_t* r, const void* p){
  uint32_t a = (uint32_t)__cvta_generic_to_shared(p);
  asm volatile("ldmatrix.sync.aligned.m8n8.x4.trans.shared.b16 {%0,%1,%2,%3}, [%4];"
    : "=r"(r[0]), "=r"(r[1]), "=r"(r[2]), "=r"(r[3]) : "r"(a));
}
__device__ __forceinline__ void mma_bf16(float* c, const uint32_t* a,
                                         uint32_t b0, uint32_t b1){
  asm volatile("mma.sync.aligned.m16n8k16.row.col.f32.bf16.bf16.f32 "
    "{%0,%1,%2,%3}, {%4,%5,%6,%7}, {%8,%9}, {%0,%1,%2,%3};"
    : "+f"(c[0]), "+f"(c[1]), "+f"(c[2]), "+f"(c[3])
    : "r"(a[0]), "r"(a[1]), "r"(a[2]), "r"(a[3]), "r"(b0), "r"(b1));
}
__device__ __forceinline__ void cpasync16(void* dst, const void* src, bool pred){
  uint32_t d = (uint32_t)__cvta_generic_to_shared(dst);
  int sz = pred ? 16 : 0;
  asm volatile("cp.async.cg.shared.global [%0], [%1], 16, %2;"
               :: "r"(d), "l"(src), "r"(sz));
}
#define CP_COMMIT() asm volatile("cp.async.commit_group;")
#define CP_WAIT1()  asm volatile("cp.async.wait_group 1;")
#define CP_WAIT0()  asm volatile("cp.async.wait_group 0;")

// ---------------------------------------------------------------------------
// bf16 hi/lo split pre-passes (R9-proven, verbatim)
// ---------------------------------------------------------------------------
__global__ __launch_bounds__(256) void split_x_kernel(
    const float* __restrict__ x, __nv_bfloat16* __restrict__ hi,
    __nv_bfloat16* __restrict__ lo, int n4)
{
  int i = blockIdx.x * 256 + threadIdx.x;
  if (i >= n4) return;
  float4 v = ((const float4*)x)[i];
  __nv_bfloat16 h0 = __float2bfloat16_rn(v.x);
  __nv_bfloat16 h1 = __float2bfloat16_rn(v.y);
  __nv_bfloat16 h2 = __float2bfloat16_rn(v.z);
  __nv_bfloat16 h3 = __float2bfloat16_rn(v.w);
  __nv_bfloat16 l0 = __float2bfloat16_rn(v.x - __bfloat162float(h0));
  __nv_bfloat16 l1 = __float2bfloat16_rn(v.y - __bfloat162float(h1));
  __nv_bfloat16 l2 = __float2bfloat16_rn(v.z - __bfloat162float(h2));
  __nv_bfloat16 l3 = __float2bfloat16_rn(v.w - __bfloat162float(h3));
  ushort4 hv = make_ushort4(*(unsigned short*)&h0, *(unsigned short*)&h1,
                            *(unsigned short*)&h2, *(unsigned short*)&h3);
  ushort4 lv = make_ushort4(*(unsigned short*)&l0, *(unsigned short*)&l1,
                            *(unsigned short*)&l2, *(unsigned short*)&l3);
  ((ushort4*)hi)[i] = hv;
  ((ushort4*)lo)[i] = lv;
}

__global__ __launch_bounds__(256) void split_w_kernel(
    const float* __restrict__ w, __nv_bfloat16* __restrict__ hi,
    __nv_bfloat16* __restrict__ lo)
{
  int i = blockIdx.x * 256 + threadIdx.x;
  if (i >= 27*128*128) return;
  float v = w[i];
  __nv_bfloat16 h = __float2bfloat16_rn(v);
  hi[i] = h;
  lo[i] = __float2bfloat16_rn(v - __bfloat162float(h));
}

// ---------------------------------------------------------------------------
// R13-PROVEN (verbatim): L2 on HMMA with tap-split partials (DIM=16, s1).
// ---------------------------------------------------------------------------
__global__ __launch_bounds__(256, 2) void mma_s1_part(
    const __nv_bfloat16* __restrict__ xhi, const __nv_bfloat16* __restrict__ xlo,
    const __nv_bfloat16* __restrict__ whi, const __nv_bfloat16* __restrict__ wlo,
    float* __restrict__ part)
{
  constexpr int BM = 128, BK = 32;
  constexpr int AP = 40;
  constexpr int BP = 136;

  __shared__ __align__(16) unsigned short Ahi[BM*AP];
  __shared__ __align__(16) unsigned short Alo[BM*AP];
  __shared__ __align__(16) unsigned short Bhi[BK*BP];
  __shared__ __align__(16) unsigned short Blo[BK*BP];
  __shared__ int offs[BM];

  const int tid  = threadIdx.x;
  const int lane = tid & 31;
  const int wid  = tid >> 5;
  const int warp_m = wid >> 2;
  const int warp_n = wid & 3;
  const int vbase = blockIdx.x * BM;
  const int tap0 = blockIdx.y * 7;
  const int tap1 = min(27, tap0 + 7);
  float* outp = part + (size_t)blockIdx.y * 524288;

  int md, mh, mw;
  { int rv = vbase + (tid & 127);
    mw = rv & 15; int t = rv >> 4; mh = t & 15; md = t >> 4; }

  const int a_row_in = lane & 15;
  const int a_colb   = (lane >> 4) << 3;
  const int b_krow   = lane & 15;
  const int b_coln   = (lane >> 4) << 3;

  float acc[4][4][4];
  #pragma unroll
  for (int mi = 0; mi < 4; mi++)
    #pragma unroll
    for (int ni = 0; ni < 4; ni++)
      #pragma unroll
      for (int q = 0; q < 4; q++) acc[mi][ni][q] = 0.f;

  for (int tap = tap0; tap < tap1; tap++){
    const int kw = tap % 3, kh = (tap / 3) % 3, kd = tap / 9;
    __syncthreads();
    if (tid < BM){
      int id = md + kd - 1, ih = mh + kh - 1, iw = mw + kw - 1;
      bool v = (unsigned)id < 16u && (unsigned)ih < 16u && (unsigned)iw < 16u;
      offs[tid] = v ? ((id*16 + ih)*16 + iw) * 128 : -1;
    }

    for (int c0 = 0; c0 < 128; c0 += BK){
      __syncthreads();
      #pragma unroll
      for (int rep = 0; rep < 2; rep++){
        int idx = rep * 256 + tid;
        int row = idx >> 2, cg = idx & 3;
        int o = offs[row];
        uint4 h = make_uint4(0,0,0,0), l = make_uint4(0,0,0,0);
        if (o >= 0){
          h = *(const uint4*)(xhi + o + c0 + cg*8);
          l = *(const uint4*)(xlo + o + c0 + cg*8);
        }
        *(uint4*)&Ahi[row*AP + cg*8] = h;
        *(uint4*)&Alo[row*AP + cg*8] = l;
      }
      #pragma unroll
      for (int rep = 0; rep < 2; rep++){
        int idx = rep * 256 + tid;
        int kr = idx >> 4, cg = idx & 15;
        int src = tap*16384 + (c0 + kr)*128 + cg*8;
        *(uint4*)&Bhi[kr*BP + cg*8] = *(const uint4*)(whi + src);
        *(uint4*)&Blo[kr*BP + cg*8] = *(const uint4*)(wlo + src);
      }
      __syncthreads();

      #pragma unroll
      for (int k16 = 0; k16 < 2; k16++){
        uint32_t af[4][4], bh[2][4], bl[2][4];
        #pragma unroll
        for (int mi = 0; mi < 4; mi++){
          int r = warp_m*64 + mi*16 + a_row_in;
          ldsm4(af[mi], &Ahi[r*AP + k16*16 + a_colb]);
        }
        #pragma unroll
        for (int nj = 0; nj < 2; nj++){
          int kr = k16*16 + b_krow;
          int nc = warp_n*32 + nj*16 + b_coln;
          ldsm4t(bh[nj], &Bhi[kr*BP + nc]);
          ldsm4t(bl[nj], &Blo[kr*BP + nc]);
        }
        #pragma unroll
        for (int mi = 0; mi < 4; mi++)
          #pragma unroll
          for (int ni = 0; ni < 4; ni++){
            const uint32_t* h = &bh[ni>>1][(ni&1)*2];
            const uint32_t* L = &bl[ni>>1][(ni&1)*2];
            mma_bf16(acc[mi][ni], af[mi], h[0], h[1]);
            mma_bf16(acc[mi][ni], af[mi], L[0], L[1]);
          }
        #pragma unroll
        for (int mi = 0; mi < 4; mi++){
          int r = warp_m*64 + mi*16 + a_row_in;
          ldsm4(af[mi], &Alo[r*AP + k16*16 + a_colb]);
        }
        #pragma unroll
        for (int mi = 0; mi < 4; mi++)
          #pragma unroll
          for (int ni = 0; ni < 4; ni++){
            const uint32_t* h = &bh[ni>>1][(ni&1)*2];
            mma_bf16(acc[mi][ni], af[mi], h[0], h[1]);
          }
      }
    }
  }

  #pragma unroll
  for (int mi = 0; mi < 4; mi++){
    int v0 = vbase + warp_m*64 + mi*16 + (lane >> 2);
    #pragma unroll
    for (int ni = 0; ni < 4; ni++){
      int col = warp_n*32 + ni*8 + (lane & 3)*2;
      *(float2*)&outp[(size_t)v0*128 + col] =
          make_float2(acc[mi][ni][0], acc[mi][ni][1]);
      *(float2*)&outp[(size_t)(v0+8)*128 + col] =
          make_float2(acc[mi][ni][2], acc[mi][ni][3]);
    }
  }
}

// L2 finish (R13-proven, verbatim)
__global__ __launch_bounds__(256) void l2_finish(
    const float* __restrict__ part, const float* __restrict__ bias,
    float* __restrict__ out)
{
  int i = blockIdx.x * 256 + threadIdx.x;
  if (i >= 131072) return;
  float4 s = ((const float4*)part)[i];
  float4 p1 = ((const float4*)(part + 524288))[i];
  float4 p2 = ((const float4*)(part + 1048576))[i];
  float4 p3 = ((const float4*)(part + 1572864))[i];
  int col = (i * 4) & 127;
  float4 b = *(const float4*)&bias[col];
  float4 r;
  r.x = fmaxf(s.x + p1.x + p2.x + p3.x + b.x, 0.f);
  r.y = fmaxf(s.y + p1.y + p2.y + p3.y + b.y, 0.f);
  r.z = fmaxf(s.z + p1.z + p2.z + p3.z + b.z, 0.f);
  r.w = fmaxf(s.w + p1.w + p2.w + p3.w + b.w, 0.f);
  ((float4*)out)[i] = r;
}

// ---------------------------------------------------------------------------
// R11-PROVEN (verbatim): L4 on HMMA with cp.async 2-stage pipeline.
// ---------------------------------------------------------------------------
__global__ __launch_bounds__(256, 2) void mma_s1r_pipe(
    const __nv_bfloat16* __restrict__ xhi, const __nv_bfloat16* __restrict__ xlo,
    const __nv_bfloat16* __restrict__ whi, const __nv_bfloat16* __restrict__ wlo,
    const float* __restrict__ bias, float* __restrict__ out)
{
  constexpr int AP = 40, BP = 136;
  constexpr int ASZ = 128*AP;
  constexpr int BSZ = 32*BP;
  constexpr int STG = 2*ASZ + 2*BSZ;
  constexpr int NIT = 27*4;

  extern __shared__ __align__(16) unsigned short dsm[];
  int* offsAll = (int*)(dsm + 2*STG);

  const int tid  = threadIdx.x;
  const int lane = tid & 31;
  const int wid  = tid >> 5;
  const int warp_m = wid >> 2;
  const int warp_n = wid & 3;
  const int vbase = blockIdx.x * 128;

  for (int s = tid; s < 27*128; s += 256){
    int tap = s >> 7, row = s & 127;
    int kw = tap % 3, kh = (tap/3)%3, kd = tap/9;
    int rv = vbase + row;
    int mw = rv & 31, mh = (rv>>5)&31, md = rv>>10;
    int id = md + kd - 1, ih = mh + kh - 1, iw = mw + kw - 1;
    bool v = (unsigned)id < 32u && (unsigned)ih < 32u && (unsigned)iw < 32u;
    offsAll[s] = v ? ((id*32 + ih)*32 + iw) * 128 : -1;
  }
  __syncthreads();

  const int a_row_in = lane & 15;
  const int a_colb   = (lane >> 4) << 3;
  const int b_krow   = lane & 15;
  const int b_coln   = (lane >> 4) << 3;

  float acc[4][4][4];
  #pragma unroll
  for (int mi = 0; mi < 4; mi++)
    #pragma unroll
    for (int ni = 0; ni < 4; ni++)
      #pragma unroll
      for (int q = 0; q < 4; q++) acc[mi][ni][q] = 0.f;

  auto fill = [&](int st, int it){
    int tap = it >> 2, c0 = (it & 3) * 32;
    unsigned short* Ah = dsm + st*STG;
    unsigned short* Al = Ah + ASZ;
    unsigned short* Bh = Ah + 2*ASZ;
    unsigned short* Bl = Bh + BSZ;
    #pragma unroll
    for (int rep = 0; rep < 2; rep++){
      int idx = rep*256 + tid;
      int row = idx >> 2, cg = idx & 3;
      int o = offsAll[tap*128 + row];
      bool p = o >= 0;
      int ob = (p ? o : 0) + c0 + cg*8;
      cpasync16(&Ah[row*AP + cg*8], xhi + ob, p);
      cpasync16(&Al[row*AP + cg*8], xlo + ob, p);
    }
    #pragma unroll
    for (int rep = 0; rep < 2; rep++){
      int idx = rep*256 + tid;
      int kr = idx >> 4, cg = idx & 15;
      int src = tap*16384 + (c0 + kr)*128 + cg*8;
      cpasync16(&Bh[kr*BP + cg*8], whi + src, true);
      cpasync16(&Bl[kr*BP + cg*8], wlo + src, true);
    }
  };

  fill(0, 0);
  CP_COMMIT();

  for (int it = 0; it < NIT; ++it){
    const int b = it & 1;
    if (it + 1 < NIT){
      fill(b ^ 1, it + 1);
      CP_COMMIT();
      CP_WAIT1();
    } else {
      CP_WAIT0();
    }
    __syncthreads();

    const unsigned short* Ah = dsm + b*STG;
    const unsigned short* Al = Ah + ASZ;
    const unsigned short* Bh = Ah + 2*ASZ;
    const unsigned short* Bl = Bh + BSZ;

    #pragma unroll
    for (int k16 = 0; k16 < 2; k16++){
      uint32_t af[4][4], bh[2][4], bl[2][4];
      #pragma unroll
      for (int mi = 0; mi < 4; mi++){
        int r = warp_m*64 + mi*16 + a_row_in;
        ldsm4(af[mi], &Ah[r*AP + k16*16 + a_colb]);
      }
      #pragma unroll
      for (int nj = 0; nj < 2; nj++){
        int kr = k16*16 + b_krow;
        int nc = warp_n*32 + nj*16 + b_coln;
        ldsm4t(bh[nj], &Bh[kr*BP + nc]);
        ldsm4t(bl[nj], &Bl[kr*BP + nc]);
      }
      #pragma unroll
      for (int mi = 0; mi < 4; mi++)
        #pragma unroll
        for (int ni = 0; ni < 4; ni++){
          const uint32_t* h = &bh[ni>>1][(ni&1)*2];
          const uint32_t* L = &bl[ni>>1][(ni&1)*2];
          mma_bf16(acc[mi][ni], af[mi], h[0], h[1]);
          mma_bf16(acc[mi][ni], af[mi], L[0], L[1]);
        }
      #pragma unroll
      for (int mi = 0; mi < 4; mi++){
        int r = warp_m*64 + mi*16 + a_row_in;
        ldsm4(af[mi], &Al[r*AP + k16*16 + a_colb]);
      }
      #pragma unroll
      for (int mi = 0; mi < 4; mi++)
        #pragma unroll
        for (int ni = 0; ni < 4; ni++){
          const uint32_t* h = &bh[ni>>1][(ni&1)*2];
          mma_bf16(acc[mi][ni], af[mi], h[0], h[1]);
        }
    }
    __syncthreads();
  }

  #pragma unroll
  for (int mi = 0; mi < 4; mi++){
    int v0 = vbase + warp_m*64 + mi*16 + (lane >> 2);
    #pragma unroll
    for (int ni = 0; ni < 4; ni++){
      int col = warp_n*32 + ni*8 + (lane & 3)*2;
      float2 bb = *(const float2*)&bias[col];
      float2 r0, r1;
      r0.x = fmaxf(acc[mi][ni][0] + bb.x, 0.f);
      r0.y = fmaxf(acc[mi][ni][1] + bb.y, 0.f);
      r1.x = fmaxf(acc[mi][ni][2] + bb.x, 0.f);
      r1.y = fmaxf(acc[mi][ni][3] + bb.y, 0.f);
      *(float2*)&out[(size_t)v0*128 + col]     = r0;
      *(float2*)&out[(size_t)(v0+8)*128 + col] = r1;
    }
  }
}

// ---------------------------------------------------------------------------
// R10-PROVEN (verbatim): L3 on HMMA, stride-2, DIM=16 -> out 32.
// ---------------------------------------------------------------------------
__global__ __launch_bounds__(256, 2) void mma_s2(
    const __nv_bfloat16* __restrict__ xhi, const __nv_bfloat16* __restrict__ xlo,
    const __nv_bfloat16* __restrict__ whi, const __nv_bfloat16* __restrict__ wlo,
    const float* __restrict__ bias, float* __restrict__ out)
{
  constexpr int BM = 128, BK = 32;
  constexpr int AP = 40;
  constexpr int BP = 136;

  __shared__ __align__(16) unsigned short Ahi[BM*AP];
  __shared__ __align__(16) unsigned short Alo[BM*AP];
  __shared__ __align__(16) unsigned short Bhi[BK*BP];
  __shared__ __align__(16) unsigned short Blo[BK*BP];
  __shared__ int offs[BM];

  const int tid  = threadIdx.x;
  const int lane = tid & 31;
  const int wid  = tid >> 5;
  const int warp_m = wid >> 2;
  const int warp_n = wid & 3;
  const int vbase = blockIdx.x * BM;
  const int pz = blockIdx.z;
  const int pd = (pz >> 2) & 1, ph = (pz >> 1) & 1, pw = pz & 1;

  int md, mh, mw;
  { int rv = vbase + (tid & 127);
    mw = rv & 15; int t = rv >> 4; mh = t & 15; md = t >> 4; }

  int nkd, kdL[2], ddL[2];
  int nkh, khL[2], dhL[2];
  int nkw, kwL[2], dwL[2];
  auto mk2 = [&](int p, int& n, int* kL, int* dL){
    if (p == 0){ n = 2; kL[0]=0; kL[1]=2; dL[0]=-1; dL[1]=0; }
    else       { n = 1; kL[0]=1; dL[0]=0; }
  };
  mk2(pd, nkd, kdL, ddL);
  mk2(ph, nkh, khL, dhL);
  mk2(pw, nkw, kwL, dwL);

  const int a_row_in = lane & 15;
  const int a_colb   = (lane >> 4) << 3;
  const int b_krow   = lane & 15;
  const int b_coln   = (lane >> 4) << 3;

  float acc[4][4][4];
  #pragma unroll
  for (int mi = 0; mi < 4; mi++)
    #pragma unroll
    for (int ni = 0; ni < 4; ni++)
      #pragma unroll
      for (int q = 0; q < 4; q++) acc[mi][ni][q] = 0.f;

  for (int ia = 0; ia < nkd; ia++)
  for (int ib = 0; ib < nkh; ib++)
  for (int ic = 0; ic < nkw; ic++){
    const int tap = (kdL[ia]*3 + khL[ib])*3 + kwL[ic];
    __syncthreads();
    if (tid < BM){
      int id = md + ddL[ia], ih = mh + dhL[ib], iw = mw + dwL[ic];
      bool v = (unsigned)id < 16u && (unsigned)ih < 16u && (unsigned)iw < 16u;
      offs[tid] = v ? ((id*16 + ih)*16 + iw) * 128 : -1;
    }

    for (int c0 = 0; c0 < 128; c0 += BK){
      __syncthreads();
      #pragma unroll
      for (int rep = 0; rep < 2; rep++){
        int idx = rep * 256 + tid;
        int row = idx >> 2, cg = idx & 3;
        int o = offs[row];
        uint4 h = make_uint4(0,0,0,0), l = make_uint4(0,0,0,0);
        if (o >= 0){
          h = *(const uint4*)(xhi + o + c0 + cg*8);
          l = *(const uint4*)(xlo + o + c0 + cg*8);
        }
        *(uint4*)&Ahi[row*AP + cg*8] = h;
        *(uint4*)&Alo[row*AP + cg*8] = l;
      }
      #pragma unroll
      for (int rep = 0; rep < 2; rep++){
        int idx = rep * 256 + tid;
        int kr = idx >> 4, cg = idx & 15;
        int src = tap*16384 + (c0 + kr)*128 + cg*8;
        *(uint4*)&Bhi[kr*BP + cg*8] = *(const uint4*)(whi + src);
        *(uint4*)&Blo[kr*BP + cg*8] = *(const uint4*)(wlo + src);
      }
      __syncthreads();

      #pragma unroll
      for (int k16 = 0; k16 < 2; k16++){
        uint32_t af[4][4], bh[2][4], bl[2][4];
        #pragma unroll
        for (int mi = 0; mi < 4; mi++){
          int r = warp_m*64 + mi*16 + a_row_in;
          ldsm4(af[mi], &Ahi[r*AP + k16*16 + a_colb]);
        }
        #pragma unroll
        for (int nj = 0; nj < 2; nj++){
          int kr = k16*16 + b_krow;
          int nc = warp_n*32 + nj*16 + b_coln;
          ldsm4t(bh[nj], &Bhi[kr*BP + nc]);
          ldsm4t(bl[nj], &Blo[kr*BP + nc]);
        }
        #pragma unroll
        for (int mi = 0; mi < 4; mi++)
          #pragma unroll
          for (int ni = 0; ni < 4; ni++){
            const uint32_t* h = &bh[ni>>1][(ni&1)*2];
            const uint32_t* L = &bl[ni>>1][(ni&1)*2];
            mma_bf16(acc[mi][ni], af[mi], h[0], h[1]);
            mma_bf16(acc[mi][ni], af[mi], L[0], L[1]);
          }
        #pragma unroll
        for (int mi = 0; mi < 4; mi++){
          int r = warp_m*64 + mi*16 + a_row_in;
          ldsm4(af[mi], &Alo[r*AP + k16*16 + a_colb]);
        }
        #pragma unroll
        for (int mi = 0; mi < 4; mi++)
          #pragma unroll
          for (int ni = 0; ni < 4; ni++){
            const uint32_t* h = &bh[ni>>1][(ni&1)*2];
            mma_bf16(acc[mi][ni], af[mi], h[0], h[1]);
          }
      }
    }
  }

  #pragma unroll
  for (int mi = 0; mi < 4; mi++){
    int lv0 = warp_m*64 + mi*16 + (lane >> 2);
    #pragma unroll
    for (int ni = 0; ni < 4; ni++){
      int col = warp_n*32 + ni*8 + (lane & 3)*2;
      float2 bb = *(const float2*)&bias[col];
      #pragma unroll
      for (int h = 0; h < 2; h++){
        int rv = vbase + lv0 + h*8;
        int vw = rv & 15; int t = rv >> 4; int vh = t & 15; int vd = t >> 4;
        int od = 2*vd + pd, oh = 2*vh + ph, ow = 2*vw + pw;
        size_t oo = (size_t)((od*32 + oh)*32 + ow) * 128 + col;
        float2 r;
        r.x = acc[mi][ni][2*h+0] + bb.x;
        r.y = acc[mi][ni][2*h+1] + bb.y;
        *(float2*)&out[oo] = r;
      }
    }
  }
}

// ---------------------------------------------------------------------------
// NEW (round 14): L1 on HMMA = mma_s2 with DIM 16->8 constants (in 8^3,
// out 16^3). Everything else identical to the R10-proven kernel.
// ---------------------------------------------------------------------------
__global__ __launch_bounds__(256, 2) void mma_s2_d8(
    const __nv_bfloat16* __restrict__ xhi, const __nv_bfloat16* __restrict__ xlo,
    const __nv_bfloat16* __restrict__ whi, const __nv_bfloat16* __restrict__ wlo,
    const float* __restrict__ bias, float* __restrict__ out)
{
  constexpr int BM = 128, BK = 32;
  constexpr int AP = 40;
  constexpr int BP = 136;

  __shared__ __align__(16) unsigned short Ahi[BM*AP];
  __shared__ __align__(16) unsigned short Alo[BM*AP];
  __shared__ __align__(16) unsigned short Bhi[BK*BP];
  __shared__ __align__(16) unsigned short Blo[BK*BP];
  __shared__ int offs[BM];

  const int tid  = threadIdx.x;
  const int lane = tid & 31;
  const int wid  = tid >> 5;
  const int warp_m = wid >> 2;
  const int warp_n = wid & 3;
  const int vbase = blockIdx.x * BM;
  const int pz = blockIdx.z;
  const int pd = (pz >> 2) & 1, ph = (pz >> 1) & 1, pw = pz & 1;

  int md, mh, mw;
  { int rv = vbase + (tid & 127);
    mw = rv & 7; int t = rv >> 3; mh = t & 7; md = t >> 3; }

  int nkd, kdL[2], ddL[2];
  int nkh, khL[2], dhL[2];
  int nkw, kwL[2], dwL[2];
  auto mk2 = [&](int p, int& n, int* kL, int* dL){
    if (p == 0){ n = 2; kL[0]=0; kL[1]=2; dL[0]=-1; dL[1]=0; }
    else       { n = 1; kL[0]=1; dL[0]=0; }
  };
  mk2(pd, nkd, kdL, ddL);
  mk2(ph, nkh, khL, dhL);
  mk2(pw, nkw, kwL, dwL);

  const int a_row_in = lane & 15;
  const int a_colb   = (lane >> 4) << 3;
  const int b_krow   = lane & 15;
  const int b_coln   = (lane >> 4) << 3;

  float acc[4][4][4];
  #pragma unroll
  for (int mi = 0; mi < 4; mi++)
    #pragma unroll
    for (int ni = 0; ni < 4; ni++)
      #pragma unroll
      for (int q = 0; q < 4; q++) acc[mi][ni][q] = 0.f;

  for (int ia = 0; ia < nkd; ia++)
  for (int ib = 0; ib < nkh; ib++)
  for (int ic = 0; ic < nkw; ic++){
    const int tap = (kdL[ia]*3 + khL[ib])*3 + kwL[ic];
    __syncthreads();
    if (tid < BM){
      int id = md + ddL[ia], ih = mh + dhL[ib], iw = mw + dwL[ic];
      bool v = (unsigned)id < 8u && (unsigned)ih < 8u && (unsigned)iw < 8u;
      offs[tid] = v ? ((id*8 + ih)*8 + iw) * 128 : -1;
    }

    for (int c0 = 0; c0 < 128; c0 += BK){
      __syncthreads();
      #pragma unroll
      for (int rep = 0; rep < 2; rep++){
        int idx = rep * 256 + tid;
        int row = idx >> 2, cg = idx & 3;
        int o = offs[row];
        uint4 h = make_uint4(0,0,0,0), l = make_uint4(0,0,0,0);
        if (o >= 0){
          h = *(const uint4*)(xhi + o + c0 + cg*8);
          l = *(const uint4*)(xlo + o + c0 + cg*8);
        }
        *(uint4*)&Ahi[row*AP + cg*8] = h;
        *(uint4*)&Alo[row*AP + cg*8] = l;
      }
      #pragma unroll
      for (int rep = 0; rep < 2; rep++){
        int idx = rep * 256 + tid;
        int kr = idx >> 4, cg = idx & 15;
        int src = tap*16384 + (c0 + kr)*128 + cg*8;
        *(uint4*)&Bhi[kr*BP + cg*8] = *(const uint4*)(whi + src);
        *(uint4*)&Blo[kr*BP + cg*8] = *(const uint4*)(wlo + src);
      }
      __syncthreads();

      #pragma unroll
      for (int k16 = 0; k16 < 2; k16++){
        uint32_t af[4][4], bh[2][4], bl[2][4];
        #pragma unroll
        for (int mi = 0; mi < 4; mi++){
          int r = warp_m*64 + mi*16 + a_row_in;
          ldsm4(af[mi], &Ahi[r*AP + k16*16 + a_colb]);
        }
        #pragma unroll
        for (int nj = 0; nj < 2; nj++){
          int kr = k16*16 + b_krow;
          int nc = warp_n*32 + nj*16 + b_coln;
          ldsm4t(bh[nj], &Bhi[kr*BP + nc]);
          ldsm4t(bl[nj], &Blo[kr*BP + nc]);
        }
        #pragma unroll
        for (int mi = 0; mi < 4; mi++)
          #pragma unroll
          for (int ni = 0; ni < 4; ni++){
            const uint32_t* h = &bh[ni>>1][(ni&1)*2];
            const uint32_t* L = &bl[ni>>1][(ni&1)*2];
            mma_bf16(acc[mi][ni], af[mi], h[0], h[1]);
            mma_bf16(acc[mi][ni], af[mi], L[0], L[1]);
          }
        #pragma unroll
        for (int mi = 0; mi < 4; mi++){
          int r = warp_m*64 + mi*16 + a_row_in;
          ldsm4(af[mi], &Alo[r*AP + k16*16 + a_colb]);
        }
        #pragma unroll
        for (int mi = 0; mi < 4; mi++)
          #pragma unroll
          for (int ni = 0; ni < 4; ni++){
            const uint32_t* h = &bh[ni>>1][(ni&1)*2];
            mma_bf16(acc[mi][ni], af[mi], h[0], h[1]);
          }
      }
    }
  }

  #pragma unroll
  for (int mi = 0; mi < 4; mi++){
    int lv0 = warp_m*64 + mi*16 + (lane >> 2);
    #pragma unroll
    for (int ni = 0; ni < 4; ni++){
      int col = warp_n*32 + ni*8 + (lane & 3)*2;
      float2 bb = *(const float2*)&bias[col];
      #pragma unroll
      for (int h = 0; h < 2; h++){
        int rv = vbase + lv0 + h*8;
        int vw = rv & 7; int t = rv >> 3; int vh = t & 7; int vd = t >> 3;
        int od = 2*vd + pd, oh = 2*vh + ph, ow = 2*vw + pw;
        size_t oo = (size_t)((od*16 + oh)*16 + ow) * 128 + col;
        float2 r;
        r.x = acc[mi][ni][2*h+0] + bb.x;
        r.y = acc[mi][ni][2*h+1] + bb.y;
        *(float2*)&out[oo] = r;
      }
    }
  }
}

// ---------------------------------------------------------------------------
// Fused L5+L6 path tables (R6-proven).
// ---------------------------------------------------------------------------
__device__ __constant__ int c_np[2][3]   = {{2,2,0},{1,3,1}};
__device__ __constant__ int c_k1[2][3][3] = {{{1,0,0},{2,1,0},{0,0,0}},
                                             {{0,0,0},{2,1,0},{2,0,0}}};
__device__ __constant__ int c_k2[2][3][3] = {{{0,1,0},{1,2,0},{0,0,0}},
                                             {{0,0,0},{0,1,2},{2,0,0}}};

// P1 (R10-proven, verbatim): Wp + WpT
__global__ __launch_bounds__(256) void p1_wp(
    const float* __restrict__ w2, const float* __restrict__ w20)
{
  int t = blockIdx.x * 256 + threadIdx.x;
  if (t >= 27*27*128) return;
  int ci = t & 127;
  int k2l = (t >> 7) % 27;
  int k1l = t / (27*128);
  const float* a = w2 + ((size_t)k1l*128 + ci) * 64;
  const float* b = w20 + (size_t)k2l * 64 * 3;
  float s0 = 0.f, s1 = 0.f, s2 = 0.f;
  #pragma unroll 4
  for (int cm = 0; cm < 64; cm++){
    float av = a[cm];
    s0 = fmaf(av, b[cm*3+0], s0);
    s1 = fmaf(av, b[cm*3+1], s1);
    s2 = fmaf(av, b[cm*3+2], s2);
  }
  float* o = g_Wp + (size_t)t * 3;
  o[0] = s0; o[1] = s1; o[2] = s2;
  size_t kk = (size_t)k1l*27 + k2l;
  g_WpT[kk*384 + 0*128 + ci] = s0;
  g_WpT[kk*384 + 1*128 + ci] = s1;
  g_WpT[kk*384 + 2*128 + ci] = s2;
}

// P2 (R7-proven, verbatim): Weff[pz][dxl][co][ci]
__global__ __launch_bounds__(256) void p2_weff()
{
  int t = blockIdx.x * 256 + threadIdx.x;
  if (t >= 8*27*128) return;
  int ci = t & 127;
  int dxl = (t >> 7) % 27;
  int pz = t / (27*128);
  int jd = dxl / 9, jh = (dxl / 3) % 3, jw = dxl % 3;
  int pd = (pz >> 2) & 1, ph = (pz >> 1) & 1, pw = pz & 1;
  int nd = c_np[pd][jd], nh = c_np[ph][jh], nw = c_np[pw][jw];
  float s0 = 0.f, s1 = 0.f, s2 = 0.f;
  for (int a = 0; a < nd; a++)
  for (int b = 0; b < nh; b++)
  for (int c = 0; c < nw; c++){
    int k1l = (c_k1[pd][jd][a]*3 + c_k1[ph][jh][b])*3 + c_k1[pw][jw][c];
    int k2l = (c_k2[pd][jd][a]*3 + c_k2[ph][jh][b])*3 + c_k2[pw][jw][c];
    const float* wp = g_Wp + ((size_t)(k1l*27 + k2l)*128 + ci)*3;
    s0 += wp[0]; s1 += wp[1]; s2 += wp[2];
  }
  float* o = g_Weff + (size_t)(pz*27 + dxl) * 3 * 128;
  o[0*128 + ci] = s0;
  o[1*128 + ci] = s1;
  o[2*128 + ci] = s2;
}

// P3 (R6-proven, verbatim)
__global__ void p3_bias(const float* __restrict__ w20,
                        const float* __restrict__ b2,
                        const float* __restrict__ b20)
{
  int tid = threadIdx.x;
  if (tid < 81){
    int k2 = tid / 3, co = tid % 3;
    float s = 0.f;
    for (int cm = 0; cm < 64; cm++)
      s = fmaf(w20[(k2*64+cm)*3+co], b2[cm], s);
    g_bconv[tid] = s;
  }
  __syncthreads();
  if (tid < 3){
    float s = b20[tid];
    for (int k2 = 0; k2 < 27; k2++) s += g_bconv[k2*3+tid];
    g_btot[tid] = s;
  }
}

// ---------------------------------------------------------------------------
// Fused L5+L6 consumer (R7 math; round-14 x-hoisting across jw — loads
// reordered only, accumulation order per acc[r] unchanged => bitwise same).
// ---------------------------------------------------------------------------
__global__ __launch_bounds__(256) void fused56b(
    const float* __restrict__ x, float* __restrict__ out)
{
  const int wid  = threadIdx.x >> 5;
  const int lane = threadIdx.x & 31;
  const int pz = blockIdx.z;
  const int pd = (pz >> 2) & 1, ph = (pz >> 1) & 1, pw = pz & 1;
  const int wg  = blockIdx.x * 8 + wid;
  const int seg = wg & 3;
  const int row = wg >> 2;
  const int rd = row >> 5, rh = row & 31;
  const int rw0 = seg * 8;
  const int l2 = 2 * lane;
  const int nw = 2 + pw;

  ull acc[8][3];
  #pragma unroll
  for (int r = 0; r < 8; r++)
    #pragma unroll
    for (int c = 0; c < 3; c++) acc[r][c] = 0ull;

  for (int jd = 0; jd <= 1 + pd; jd++){
    int id = rd + jd - 1;
    if ((unsigned)id >= 32u) continue;
    for (int jh = 0; jh <= 1 + ph; jh++){
      int ih = rh + jh - 1;
      if ((unsigned)ih >= 32u) continue;
      const float* xrow = x + (size_t)((id*32 + ih)*32) * 128;

      // hoist weights for the (up to 3) jw taps of this row
      ull W[3][6];
      #pragma unroll
      for (int jw = 0; jw < 3; jw++){
        if (jw < nw){
          const float* Wt = g_Weff + (size_t)(pz*27 + jd*9 + jh*3 + jw) * 384;
          W[jw][0] = *(const ull*)(Wt +   0 + l2);
          W[jw][1] = *(const ull*)(Wt +  64 + l2);
          W[jw][2] = *(const ull*)(Wt + 128 + l2);
          W[jw][3] = *(const ull*)(Wt + 192 + l2);
          W[jw][4] = *(const ull*)(Wt + 256 + l2);
          W[jw][5] = *(const ull*)(Wt + 320 + l2);
        }
      }

      // each distinct iw loaded ONCE; fan into acc[r], r = t - jw
      #pragma unroll
      for (int t = 0; t < 10; t++){
        int iw = rw0 - 1 + t;
        if ((unsigned)iw >= 32u) continue;
        const float* xp = xrow + iw * 128;
        ull x0 = *(const ull*)(xp + l2);
        ull x1 = *(const ull*)(xp + 64 + l2);
        #pragma unroll
        for (int jw = 0; jw < 3; jw++){
          int r = t - jw;
          if (jw < nw && (unsigned)r < 8u){
            ffma2(acc[r][0], x0, W[jw][0]); ffma2(acc[r][0], x1, W[jw][1]);
            ffma2(acc[r][1], x0, W[jw][2]); ffma2(acc[r][1], x1, W[jw][3]);
            ffma2(acc[r][2], x0, W[jw][4]); ffma2(acc[r][2], x1, W[jw][5]);
          }
        }
      }
    }
  }

  const float bt0 = g_btot[0], bt1 = g_btot[1], bt2 = g_btot[2];
  const int od = 2*rd + pd, oh = 2*rh + ph;

  #pragma unroll
  for (int r = 0; r < 8; r++){
    float s0, s1, s2;
    {
      float a, b;
      unpack2(acc[r][0], a, b); s0 = a + b;
      unpack2(acc[r][1], a, b); s1 = a + b;
      unpack2(acc[r][2], a, b); s2 = a + b;
    }
    #pragma unroll
    for (int sh = 16; sh > 0; sh >>= 1){
      s0 += __shfl_xor_sync(0xffffffffu, s0, sh);
      s1 += __shfl_xor_sync(0xffffffffu, s1, sh);
      s2 += __shfl_xor_sync(0xffffffffu, s2, sh);
    }
    if (lane == 0){
      int ow = 2*(rw0 + r) + pw;
      float* op = out + (size_t)((od*64 + oh)*64 + ow) * 3;
      op[0] = s0 + bt0;
      op[1] = s1 + bt1;
      op[2] = s2 + bt2;
    }
  }
}

// ---------------------------------------------------------------------------
// fix56w (R8-proven, verbatim): warp-per-voxel exact boundary fix.
// ---------------------------------------------------------------------------
__global__ __launch_bounds__(256) void fix56w(
    const float* __restrict__ x, const float* __restrict__ b20,
    float* __restrict__ out)
{
  const int gw = blockIdx.x * 8 + (threadIdx.x >> 5);
  const int lane = threadIdx.x & 31;
  const int l2 = 2 * lane;

  int plane = gw / 4096, r = gw % 4096;
  int a = r / 64, b = r % 64;
  int od, oh, ow;
  if      (plane == 0){ od = 0;  oh = a; ow = b; }
  else if (plane == 1){ od = 63; oh = a; ow = b; }
  else if (plane == 2){ oh = 0;  od = a; ow = b; if (od==0||od==63) return; }
  else if (plane == 3){ oh = 63; od = a; ow = b; if (od==0||od==63) return; }
  else if (plane == 4){ ow = 0;  od = a; oh = b; if (od==0||od==63||oh==0||oh==63) return; }
  else               { ow = 63; od = a; oh = b; if (od==0||od==63||oh==0||oh==63) return; }

  ull a0 = 0ull, a1 = 0ull, a2 = 0ull;
  float bias0 = __ldg(&b20[0]), bias1 = __ldg(&b20[1]), bias2 = __ldg(&b20[2]);

  for (int k2d = 0; k2d < 3; k2d++){
    int md = od + k2d - 1; if ((unsigned)md >= 64u) continue;
    int pmd = md & 1, rd = (md - pmd) >> 1;
    int n_d = pmd ? 1 : 2;
    int k1d[2], ixd[2];
    if (pmd){ k1d[0] = 1; ixd[0] = rd; }
    else    { k1d[0] = 0; ixd[0] = rd - 1; k1d[1] = 2; ixd[1] = rd; }
    for (int k2h = 0; k2h < 3; k2h++){
      int mh = oh + k2h - 1; if ((unsigned)mh >= 64u) continue;
      int pmh = mh & 1, rh = (mh - pmh) >> 1;
      int n_h = pmh ? 1 : 2;
      int k1h[2], ixh[2];
      if (pmh){ k1h[0] = 1; ixh[0] = rh; }
      else    { k1h[0] = 0; ixh[0] = rh - 1; k1h[1] = 2; ixh[1] = rh; }
      for (int k2w = 0; k2w < 3; k2w++){
        int mw = ow + k2w - 1; if ((unsigned)mw >= 64u) continue;
        int pmw = mw & 1, rw = (mw - pmw) >> 1;
        int n_w = pmw ? 1 : 2;
        int k1w[2], ixw[2];
        if (pmw){ k1w[0] = 1; ixw[0] = rw; }
        else    { k1w[0] = 0; ixw[0] = rw - 1; k1w[1] = 2; ixw[1] = rw; }

        int k2l = (k2d*3 + k2h)*3 + k2w;
        bias0 += g_bconv[k2l*3+0];
        bias1 += g_bconv[k2l*3+1];
        bias2 += g_bconv[k2l*3+2];

        for (int ia = 0; ia < n_d; ia++){
          if ((unsigned)ixd[ia] >= 32u) continue;
          for (int ib = 0; ib < n_h; ib++){
            if ((unsigned)ixh[ib] >= 32u) continue;
            for (int ic = 0; ic < n_w; ic++){
              if ((unsigned)ixw[ic] >= 32u) continue;
              int k1l = (k1d[ia]*3 + k1h[ib])*3 + k1w[ic];
              const float* wt = g_WpT + (size_t)(k1l*27 + k2l)*384;
              const float* xp = x + (size_t)((ixd[ia]*32 + ixh[ib])*32 + ixw[ic])*128;
              ull x0 = *(const ull*)(xp + l2);
              ull x1 = *(const ull*)(xp + 64 + l2);
              ffma2(a0, x0, *(const ull*)(wt +   0 + l2));
              ffma2(a0, x1, *(const ull*)(wt +  64 + l2));
              ffma2(a1, x0, *(const ull*)(wt + 128 + l2));
              ffma2(a1, x1, *(const ull*)(wt + 192 + l2));
              ffma2(a2, x0, *(const ull*)(wt + 256 + l2));
              ffma2(a2, x1, *(const ull*)(wt + 320 + l2));
            }
          }
        }
      }
    }
  }

  float s0, s1, s2;
  {
    float u, v;
    unpack2(a0, u, v); s0 = u + v;
    unpack2(a1, u, v); s1 = u + v;
    unpack2(a2, u, v); s2 = u + v;
  }
  #pragma unroll
  for (int sh = 16; sh > 0; sh >>= 1){
    s0 += __shfl_xor_sync(0xffffffffu, s0, sh);
    s1 += __shfl_xor_sync(0xffffffffu, s1, sh);
    s2 += __shfl_xor_sync(0xffffffffu, s2, sh);
  }
  if (lane == 0){
    float* op = out + (size_t)((od*64 + oh)*64 + ow) * 3;
    op[0] = s0 + bias0;
    op[1] = s1 + bias1;
    op[2] = s2 + bias2;
  }
}

// ---------------------------------------------------------------------------
// kernel_launch
// ---------------------------------------------------------------------------
extern "C" void kernel_launch(void* const* d_in, const int* in_sizes, int n_in,
                              void* d_out, int out_size)
{
  (void)in_sizes; (void)n_in; (void)out_size;
  const float* x   = (const float*)d_in[0];
  const float* w0  = (const float*)d_in[1];
  const float* b0  = (const float*)d_in[2];
  const float* w00 = (const float*)d_in[3];
  const float* b00 = (const float*)d_in[4];
  const float* w1  = (const float*)d_in[5];
  const float* b1  = (const float*)d_in[6];
  const float* w10 = (const float*)d_in[7];
  const float* b10 = (const float*)d_in[8];
  const float* w2  = (const float*)d_in[9];
  const float* b2  = (const float*)d_in[10];
  const float* w20 = (const float*)d_in[11];
  const float* b20 = (const float*)d_in[12];
  float* out = (float*)d_out;

  float *bufA = nullptr, *bufB = nullptr, *part = nullptr;
  __nv_bfloat16 *xhi, *xlo, *whi, *wlo, *whiB, *wloB, *whiC, *wloC, *whiD, *wloD;
  cudaGetSymbolAddress((void**)&bufA, g_bufA);
  cudaGetSymbolAddress((void**)&bufB, g_bufB);
  cudaGetSymbolAddress((void**)&part, g_part);
  cudaGetSymbolAddress((void**)&xhi, g_xhi);
  cudaGetSymbolAddress((void**)&xlo, g_xlo);
  cudaGetSymbolAddress((void**)&whi, g_whi);
  cudaGetSymbolAddress((void**)&wlo, g_wlo);
  cudaGetSymbolAddress((void**)&whiB, g_whiB);
  cudaGetSymbolAddress((void**)&wloB, g_wloB);
  cudaGetSymbolAddress((void**)&whiC, g_whiC);
  cudaGetSymbolAddress((void**)&wloC, g_wloC);
  cudaGetSymbolAddress((void**)&whiD, g_whiD);
  cudaGetSymbolAddress((void**)&wloD, g_wloD);

  static bool attr_set = false;
  const int PIPE_SMEM = 2*37888 + 27*128*4;   // 89600 B
  if (!attr_set){
    cudaFuncSetAttribute(mma_s1r_pipe,
                         cudaFuncAttributeMaxDynamicSharedMemorySize, PIPE_SMEM);
    attr_set = true;
  }

  // (1) Wp + WpT precompute
  p1_wp<<<(27*27*128 + 255)/256, 256>>>(w2, w20);
  // (2-4) split weights for L1 + L2 + L3 HMMA
  split_w_kernel<<<1728, 256>>>(w0, whiD, wloD);
  split_w_kernel<<<1728, 256>>>(w00, whiC, wloC);
  split_w_kernel<<<1728, 256>>>(w1, whiB, wloB);
  // (5) split network input x for L1 HMMA
  split_x_kernel<<<64, 256>>>(x, xhi, xlo, 65536/4);
  // (6) L1 on HMMA: x-split -> bufA(16^3,128)   [NEW mma_s2_d8]
  {
    dim3 g(4, 1, 8);
    mma_s2_d8<<<g, 256>>>(xhi, xlo, whiD, wloD, b0, bufA);
  }
  // (7) split L1 output for L2 HMMA
  split_x_kernel<<<512, 256>>>(bufA, xhi, xlo, 524288/4);
  // (8) L2 on HMMA with 4-way tap split -> partials   [R13 proven]
  {
    dim3 g(32, 4, 1);
    mma_s1_part<<<g, 256>>>(xhi, xlo, whiC, wloC, part);
  }
  // (9) L2 finish
  l2_finish<<<512, 256>>>(part, b00, bufB);
  // (10) split L2 output for L3 HMMA
  split_x_kernel<<<512, 256>>>(bufB, xhi, xlo, 524288/4);
  // (11) L3 on HMMA   [R10 proven]
  {
    dim3 g(32, 1, 8);
    mma_s2<<<g, 256>>>(xhi, xlo, whiB, wloB, b1, bufA);
  }
  // (12) split w10 for L4 HMMA
  split_w_kernel<<<1728, 256>>>(w10, whi, wlo);
  // (13) split L3 output for L4 HMMA
  split_x_kernel<<<4096, 256>>>(bufA, xhi, xlo, 4194304/4);
  // (14) L4 on pipelined HMMA   [R11 proven]
  mma_s1r_pipe<<<256, 256, PIPE_SMEM>>>(xhi, xlo, whi, wlo, b10, bufB);
  // (15-16) fused-weight precompute for L5+L6
  p2_weff<<<(8*27*128 + 255)/256, 256>>>();
  p3_bias<<<1, 128>>>(w20, b2, b20);
  // (17) Fused L5+L6 with x-hoisted loads   [UPDATED]
  {
    dim3 g(512, 1, 8);
    fused56b<<<g, 256>>>(bufB, out);
  }
  // (18) Exact boundary fix   [R8 proven]
  fix56w<<<3072, 256>>>(bufB, b20, out);
}

// round 15
// speedup vs baseline: 1.4180x; 1.0193x over previous
#include <cuda_runtime.h>
#include <cuda_bf16.h>
#include <cstdint>

// ---------------------------------------------------------------------------
// Static scratch (no allocation allowed)
// ---------------------------------------------------------------------------
__device__ float g_bufB[4194304];
__device__ float g_part[3670016];   // 7 x (4096 x 128) L2 partials
__device__ float g_Wp[279936];
__device__ float g_WpT[279936];
__device__ float g_Weff[110592];
__device__ float g_bconv[81];
__device__ float g_btot[3];
__device__ __nv_bfloat16 g_xhiA[4194304];   // pair A
__device__ __nv_bfloat16 g_xloA[4194304];
__device__ __nv_bfloat16 g_xhiB[4194304];   // pair B
__device__ __nv_bfloat16 g_xloB[4194304];
__device__ __nv_bfloat16 g_whi[442368];    // L4 weights (w10)
__device__ __nv_bfloat16 g_wlo[442368];
__device__ __nv_bfloat16 g_whiB[442368];   // L3 weights (w1)
__device__ __nv_bfloat16 g_wloB[442368];
__device__ __nv_bfloat16 g_whiC[442368];   // L2 weights (w00)
__device__ __nv_bfloat16 g_wloC[442368];
__device__ __nv_bfloat16 g_whiD[442368];   // L1 weights (w0)
__device__ __nv_bfloat16 g_wloD[442368];

typedef unsigned long long ull;

// ---------------------------------------------------------------------------
// f32x2 packed helpers
// ---------------------------------------------------------------------------
__device__ __forceinline__ ull pack2(float x, float y){
  ull r; asm("mov.b64 %0, {%1, %2};" : "=l"(r) : "f"(x), "f"(y)); return r;
}
__device__ __forceinline__ void unpack2(ull v, float& x, float& y){
  asm("mov.b64 {%0, %1}, %2;" : "=f"(x), "=f"(y) : "l"(v));
}
__device__ __forceinline__ void ffma2(ull& acc, ull a, ull b){
  asm("fma.rn.f32x2 %0, %1, %2, %0;" : "+l"(acc) : "l"(a), "l"(b));
}

// pack two floats into hi/lo bf16-pair words (matches split_x arithmetic)
__device__ __forceinline__ void split2(float vx, float vy,
                                       unsigned& hw, unsigned& lw){
  __nv_bfloat16 h0 = __float2bfloat16_rn(vx);
  __nv_bfloat16 h1 = __float2bfloat16_rn(vy);
  __nv_bfloat16 l0 = __float2bfloat16_rn(vx - __bfloat162float(h0));
  __nv_bfloat16 l1 = __float2bfloat16_rn(vy - __bfloat162float(h1));
  hw = (unsigned)*(unsigned short*)&h0 | ((unsigned)*(unsigned short*)&h1 << 16);
  lw = (unsigned)*(unsigned short*)&l0 | ((unsigned)*(unsigned short*)&l1 << 16);
}

// ---------------------------------------------------------------------------
// mma.sync / ldmatrix / cp.async helpers (baseline PTX, legal on sm_103)
// ---------------------------------------------------------------------------
__device__ __forceinline__ void ldsm4(uint32_t* r, const void* p){
  uint32_t a = (uint32_t)__cvta_generic_to_shared(p);
  asm volatile("ldmatrix.sync.aligned.m8n8.x4.shared.b16 {%0,%1,%2,%3}, [%4];"
    : "=r"(r[0]), "=r"(r[1]), "=r"(r[2]), "=r"(r[3]) : "r"(a));
}
__device__ __forceinline__ void ldsm4t(uint32_t* r, const void* p){
  uint32_t a = (uint32_t)__cvta_generic_to_shared(p);
  asm volatile("ldmatrix.sync.aligned.m8n8.x4.trans.shared.b16 {%0,%1,%2,%3}, [%4];"
    : "=r"(r[0]), "=r"(r[1]), "=r"(r[2]), "=r"(r[3]) : "r"(a));
}
__device__ __forceinline__ void mma_bf16(float* c, const uint32_t* a,
                                         uint32_t b0, uint32_t b1){
  asm volatile("mma.sync.aligned.m16n8k16.row.col.f32.bf16.bf16.f32 "
    "{%0,%1,%2,%3}, {%4,%5,%6,%7}, {%8,%9}, {%0,%1,%2,%3};"
    : "+f"(c[0]), "+f"(c[1]), "+f"(c[2]), "+f"(c[3])
    : "r"(a[0]), "r"(a[1]), "r"(a[2]), "r"(a[3]), "r"(b0), "r"(b1));
}
__device__ __forceinline__ void cpasync16(void* dst, const void* src, bool pred){
  uint32_t d = (uint32_t)__cvta_generic_to_shared(dst);
  int sz = pred ? 16 : 0;
  asm volatile("cp.async.cg.shared.global [%0], [%1], 16, %2;"
               :: "r"(d), "l"(src), "r"(sz));
}
#define CP_COMMIT() asm volatile("cp.async.commit_group;")
#define CP_WAIT1()  asm volatile("cp.async.wait_group 1;")
#define CP_WAIT0()  asm volatile("cp.async.wait_group 0;")

// ---------------------------------------------------------------------------
// bf16 hi/lo split pre-passes (R9-proven, verbatim) — used for x and weights
// ---------------------------------------------------------------------------
__global__ __launch_bounds__(256) void split_x_kernel(
    const float* __restrict__ x, __nv_bfloat16* __restrict__ hi,
    __nv_bfloat16* __restrict__ lo, int n4)
{
  int i = blockIdx.x * 256 + threadIdx.x;
  if (i >= n4) return;
  float4 v = ((const float4*)x)[i];
  __nv_bfloat16 h0 = __float2bfloat16_rn(v.x);
  __nv_bfloat16 h1 = __float2bfloat16_rn(v.y);
  __nv_bfloat16 h2 = __float2bfloat16_rn(v.z);
  __nv_bfloat16 h3 = __float2bfloat16_rn(v.w);
  __nv_bfloat16 l0 = __float2bfloat16_rn(v.x - __bfloat162float(h0));
  __nv_bfloat16 l1 = __float2bfloat16_rn(v.y - __bfloat162float(h1));
  __nv_bfloat16 l2 = __float2bfloat16_rn(v.z - __bfloat162float(h2));
  __nv_bfloat16 l3 = __float2bfloat16_rn(v.w - __bfloat162float(h3));
  ushort4 hv = make_ushort4(*(unsigned short*)&h0, *(unsigned short*)&h1,
                            *(unsigned short*)&h2, *(unsigned short*)&h3);
  ushort4 lv = make_ushort4(*(unsigned short*)&l0, *(unsigned short*)&l1,
                            *(unsigned short*)&l2, *(unsigned short*)&l3);
  ((ushort4*)hi)[i] = hv;
  ((ushort4*)lo)[i] = lv;
}

__global__ __launch_bounds__(256) void split_w_kernel(
    const float* __restrict__ w, __nv_bfloat16* __restrict__ hi,
    __nv_bfloat16* __restrict__ lo)
{
  int i = blockIdx.x * 256 + threadIdx.x;
  if (i >= 27*128*128) return;
  float v = w[i];
  __nv_bfloat16 h = __float2bfloat16_rn(v);
  hi[i] = h;
  lo[i] = __float2bfloat16_rn(v - __bfloat162float(h));
}

// ---------------------------------------------------------------------------
// R13-PROVEN core: L2 on HMMA with tap-split partials (now 7 groups of <=4).
// ---------------------------------------------------------------------------
__global__ __launch_bounds__(256, 2) void mma_s1_part(
    const __nv_bfloat16* __restrict__ xhi, const __nv_bfloat16* __restrict__ xlo,
    const __nv_bfloat16* __restrict__ whi, const __nv_bfloat16* __restrict__ wlo,
    float* __restrict__ part)
{
  constexpr int BM = 128, BK = 32;
  constexpr int AP = 40;
  constexpr int BP = 136;

  __shared__ __align__(16) unsigned short Ahi[BM*AP];
  __shared__ __align__(16) unsigned short Alo[BM*AP];
  __shared__ __align__(16) unsigned short Bhi[BK*BP];
  __shared__ __align__(16) unsigned short Blo[BK*BP];
  __shared__ int offs[BM];

  const int tid  = threadIdx.x;
  const int lane = tid & 31;
  const int wid  = tid >> 5;
  const int warp_m = wid >> 2;
  const int warp_n = wid & 3;
  const int vbase = blockIdx.x * BM;
  const int tap0 = blockIdx.y * 4;
  const int tap1 = min(27, tap0 + 4);
  float* outp = part + (size_t)blockIdx.y * 524288;

  int md, mh, mw;
  { int rv = vbase + (tid & 127);
    mw = rv & 15; int t = rv >> 4; mh = t & 15; md = t >> 4; }

  const int a_row_in = lane & 15;
  const int a_colb   = (lane >> 4) << 3;
  const int b_krow   = lane & 15;
  const int b_coln   = (lane >> 4) << 3;

  float acc[4][4][4];
  #pragma unroll
  for (int mi = 0; mi < 4; mi++)
    #pragma unroll
    for (int ni = 0; ni < 4; ni++)
      #pragma unroll
      for (int q = 0; q < 4; q++) acc[mi][ni][q] = 0.f;

  for (int tap = tap0; tap < tap1; tap++){
    const int kw = tap % 3, kh = (tap / 3) % 3, kd = tap / 9;
    __syncthreads();
    if (tid < BM){
      int id = md + kd - 1, ih = mh + kh - 1, iw = mw + kw - 1;
      bool v = (unsigned)id < 16u && (unsigned)ih < 16u && (unsigned)iw < 16u;
      offs[tid] = v ? ((id*16 + ih)*16 + iw) * 128 : -1;
    }

    for (int c0 = 0; c0 < 128; c0 += BK){
      __syncthreads();
      #pragma unroll
      for (int rep = 0; rep < 2; rep++){
        int idx = rep * 256 + tid;
        int row = idx >> 2, cg = idx & 3;
        int o = offs[row];
        uint4 h = make_uint4(0,0,0,0), l = make_uint4(0,0,0,0);
        if (o >= 0){
          h = *(const uint4*)(xhi + o + c0 + cg*8);
          l = *(const uint4*)(xlo + o + c0 + cg*8);
        }
        *(uint4*)&Ahi[row*AP + cg*8] = h;
        *(uint4*)&Alo[row*AP + cg*8] = l;
      }
      #pragma unroll
      for (int rep = 0; rep < 2; rep++){
        int idx = rep * 256 + tid;
        int kr = idx >> 4, cg = idx & 15;
        int src = tap*16384 + (c0 + kr)*128 + cg*8;
        *(uint4*)&Bhi[kr*BP + cg*8] = *(const uint4*)(whi + src);
        *(uint4*)&Blo[kr*BP + cg*8] = *(const uint4*)(wlo + src);
      }
      __syncthreads();

      #pragma unroll
      for (int k16 = 0; k16 < 2; k16++){
        uint32_t af[4][4], bh[2][4], bl[2][4];
        #pragma unroll
        for (int mi = 0; mi < 4; mi++){
          int r = warp_m*64 + mi*16 + a_row_in;
          ldsm4(af[mi], &Ahi[r*AP + k16*16 + a_colb]);
        }
        #pragma unroll
        for (int nj = 0; nj < 2; nj++){
          int kr = k16*16 + b_krow;
          int nc = warp_n*32 + nj*16 + b_coln;
          ldsm4t(bh[nj], &Bhi[kr*BP + nc]);
          ldsm4t(bl[nj], &Blo[kr*BP + nc]);
        }
        #pragma unroll
        for (int mi = 0; mi < 4; mi++)
          #pragma unroll
          for (int ni = 0; ni < 4; ni++){
            const uint32_t* h = &bh[ni>>1][(ni&1)*2];
            const uint32_t* L = &bl[ni>>1][(ni&1)*2];
            mma_bf16(acc[mi][ni], af[mi], h[0], h[1]);
            mma_bf16(acc[mi][ni], af[mi], L[0], L[1]);
          }
        #pragma unroll
        for (int mi = 0; mi < 4; mi++){
          int r = warp_m*64 + mi*16 + a_row_in;
          ldsm4(af[mi], &Alo[r*AP + k16*16 + a_colb]);
        }
        #pragma unroll
        for (int mi = 0; mi < 4; mi++)
          #pragma unroll
          for (int ni = 0; ni < 4; ni++){
            const uint32_t* h = &bh[ni>>1][(ni&1)*2];
            mma_bf16(acc[mi][ni], af[mi], h[0], h[1]);
          }
      }
    }
  }

  #pragma unroll
  for (int mi = 0; mi < 4; mi++){
    int v0 = vbase + warp_m*64 + mi*16 + (lane >> 2);
    #pragma unroll
    for (int ni = 0; ni < 4; ni++){
      int col = warp_n*32 + ni*8 + (lane & 3)*2;
      *(float2*)&outp[(size_t)v0*128 + col] =
          make_float2(acc[mi][ni][0], acc[mi][ni][1]);
      *(float2*)&outp[(size_t)(v0+8)*128 + col] =
          make_float2(acc[mi][ni][2], acc[mi][ni][3]);
    }
  }
}

// L2 finish: sum 7 partials + bias + relu, write bf16 hi/lo splits directly.
__global__ __launch_bounds__(256) void l2_finish(
    const float* __restrict__ part, const float* __restrict__ bias,
    __nv_bfloat16* __restrict__ xhi, __nv_bfloat16* __restrict__ xlo)
{
  int i = blockIdx.x * 256 + threadIdx.x;
  if (i >= 131072) return;
  float4 s = ((const float4*)part)[i];
  #pragma unroll
  for (int g = 1; g < 7; g++){
    float4 p = ((const float4*)(part + (size_t)g*524288))[i];
    s.x += p.x; s.y += p.y; s.z += p.z; s.w += p.w;
  }
  int col = (i * 4) & 127;
  float4 b = *(const float4*)&bias[col];
  float4 r;
  r.x = fmaxf(s.x + b.x, 0.f);
  r.y = fmaxf(s.y + b.y, 0.f);
  r.z = fmaxf(s.z + b.z, 0.f);
  r.w = fmaxf(s.w + b.w, 0.f);
  unsigned h0, l0, h1, l1;
  split2(r.x, r.y, h0, l0);
  split2(r.z, r.w, h1, l1);
  ((uint2*)xhi)[i] = make_uint2(h0, h1);
  ((uint2*)xlo)[i] = make_uint2(l0, l1);
}

// ---------------------------------------------------------------------------
// R11-PROVEN (verbatim): L4 on HMMA with cp.async 2-stage pipeline.
// ---------------------------------------------------------------------------
__global__ __launch_bounds__(256, 2) void mma_s1r_pipe(
    const __nv_bfloat16* __restrict__ xhi, const __nv_bfloat16* __restrict__ xlo,
    const __nv_bfloat16* __restrict__ whi, const __nv_bfloat16* __restrict__ wlo,
    const float* __restrict__ bias, float* __restrict__ out)
{
  constexpr int AP = 40, BP = 136;
  constexpr int ASZ = 128*AP;
  constexpr int BSZ = 32*BP;
  constexpr int STG = 2*ASZ + 2*BSZ;
  constexpr int NIT = 27*4;

  extern __shared__ __align__(16) unsigned short dsm[];
  int* offsAll = (int*)(dsm + 2*STG);

  const int tid  = threadIdx.x;
  const int lane = tid & 31;
  const int wid  = tid >> 5;
  const int warp_m = wid >> 2;
  const int warp_n = wid & 3;
  const int vbase = blockIdx.x * 128;

  for (int s = tid; s < 27*128; s += 256){
    int tap = s >> 7, row = s & 127;
    int kw = tap % 3, kh = (tap/3)%3, kd = tap/9;
    int rv = vbase + row;
    int mw = rv & 31, mh = (rv>>5)&31, md = rv>>10;
    int id = md + kd - 1, ih = mh + kh - 1, iw = mw + kw - 1;
    bool v = (unsigned)id < 32u && (unsigned)ih < 32u && (unsigned)iw < 32u;
    offsAll[s] = v ? ((id*32 + ih)*32 + iw) * 128 : -1;
  }
  __syncthreads();

  const int a_row_in = lane & 15;
  const int a_colb   = (lane >> 4) << 3;
  const int b_krow   = lane & 15;
  const int b_coln   = (lane >> 4) << 3;

  float acc[4][4][4];
  #pragma unroll
  for (int mi = 0; mi < 4; mi++)
    #pragma unroll
    for (int ni = 0; ni < 4; ni++)
      #pragma unroll
      for (int q = 0; q < 4; q++) acc[mi][ni][q] = 0.f;

  auto fill = [&](int st, int it){
    int tap = it >> 2, c0 = (it & 3) * 32;
    unsigned short* Ah = dsm + st*STG;
    unsigned short* Al = Ah + ASZ;
    unsigned short* Bh = Ah + 2*ASZ;
    unsigned short* Bl = Bh + BSZ;
    #pragma unroll
    for (int rep = 0; rep < 2; rep++){
      int idx = rep*256 + tid;
      int row = idx >> 2, cg = idx & 3;
      int o = offsAll[tap*128 + row];
      bool p = o >= 0;
      int ob = (p ? o : 0) + c0 + cg*8;
      cpasync16(&Ah[row*AP + cg*8], xhi + ob, p);
      cpasync16(&Al[row*AP + cg*8], xlo + ob, p);
    }
    #pragma unroll
    for (int rep = 0; rep < 2; rep++){
      int idx = rep*256 + tid;
      int kr = idx >> 4, cg = idx & 15;
      int src = tap*16384 + (c0 + kr)*128 + cg*8;
      cpasync16(&Bh[kr*BP + cg*8], whi + src, true);
      cpasync16(&Bl[kr*BP + cg*8], wlo + src, true);
    }
  };

  fill(0, 0);
  CP_COMMIT();

  for (int it = 0; it < NIT; ++it){
    const int b = it & 1;
    if (it + 1 < NIT){
      fill(b ^ 1, it + 1);
      CP_COMMIT();
      CP_WAIT1();
    } else {
      CP_WAIT0();
    }
    __syncthreads();

    const unsigned short* Ah = dsm + b*STG;
    const unsigned short* Al = Ah + ASZ;
    const unsigned short* Bh = Ah + 2*ASZ;
    const unsigned short* Bl = Bh + BSZ;

    #pragma unroll
    for (int k16 = 0; k16 < 2; k16++){
      uint32_t af[4][4], bh[2][4], bl[2][4];
      #pragma unroll
      for (int mi = 0; mi < 4; mi++){
        int r = warp_m*64 + mi*16 + a_row_in;
        ldsm4(af[mi], &Ah[r*AP + k16*16 + a_colb]);
      }
      #pragma unroll
      for (int nj = 0; nj < 2; nj++){
        int kr = k16*16 + b_krow;
        int nc = warp_n*32 + nj*16 + b_coln;
        ldsm4t(bh[nj], &Bh[kr*BP + nc]);
        ldsm4t(bl[nj], &Bl[kr*BP + nc]);
      }
      #pragma unroll
      for (int mi = 0; mi < 4; mi++)
        #pragma unroll
        for (int ni = 0; ni < 4; ni++){
          const uint32_t* h = &bh[ni>>1][(ni&1)*2];
          const uint32_t* L = &bl[ni>>1][(ni&1)*2];
          mma_bf16(acc[mi][ni], af[mi], h[0], h[1]);
          mma_bf16(acc[mi][ni], af[mi], L[0], L[1]);
        }
      #pragma unroll
      for (int mi = 0; mi < 4; mi++){
        int r = warp_m*64 + mi*16 + a_row_in;
        ldsm4(af[mi], &Al[r*AP + k16*16 + a_colb]);
      }
      #pragma unroll
      for (int mi = 0; mi < 4; mi++)
        #pragma unroll
        for (int ni = 0; ni < 4; ni++){
          const uint32_t* h = &bh[ni>>1][(ni&1)*2];
          mma_bf16(acc[mi][ni], af[mi], h[0], h[1]);
        }
    }
    __syncthreads();
  }

  #pragma unroll
  for (int mi = 0; mi < 4; mi++){
    int v0 = vbase + warp_m*64 + mi*16 + (lane >> 2);
    #pragma unroll
    for (int ni = 0; ni < 4; ni++){
      int col = warp_n*32 + ni*8 + (lane & 3)*2;
      float2 bb = *(const float2*)&bias[col];
      float2 r0, r1;
      r0.x = fmaxf(acc[mi][ni][0] + bb.x, 0.f);
      r0.y = fmaxf(acc[mi][ni][1] + bb.y, 0.f);
      r1.x = fmaxf(acc[mi][ni][2] + bb.x, 0.f);
      r1.y = fmaxf(acc[mi][ni][3] + bb.y, 0.f);
      *(float2*)&out[(size_t)v0*128 + col]     = r0;
      *(float2*)&out[(size_t)(v0+8)*128 + col] = r1;
    }
  }
}

// ---------------------------------------------------------------------------
// R10-PROVEN core: L3 on HMMA, stride-2, DIM=16 -> out 32.
// Round-15 change: epilogue emits bf16 hi/lo splits (for L4) instead of fp32.
// ---------------------------------------------------------------------------
__global__ __launch_bounds__(256, 2) void mma_s2(
    const __nv_bfloat16* __restrict__ xhi, const __nv_bfloat16* __restrict__ xlo,
    const __nv_bfloat16* __restrict__ whi, const __nv_bfloat16* __restrict__ wlo,
    const float* __restrict__ bias,
    __nv_bfloat16* __restrict__ ohi, __nv_bfloat16* __restrict__ olo)
{
  constexpr int BM = 128, BK = 32;
  constexpr int AP = 40;
  constexpr int BP = 136;

  __shared__ __align__(16) unsigned short Ahi[BM*AP];
  __shared__ __align__(16) unsigned short Alo[BM*AP];
  __shared__ __align__(16) unsigned short Bhi[BK*BP];
  __shared__ __align__(16) unsigned short Blo[BK*BP];
  __shared__ int offs[BM];

  const int tid  = threadIdx.x;
  const int lane = tid & 31;
  const int wid  = tid >> 5;
  const int warp_m = wid >> 2;
  const int warp_n = wid & 3;
  const int vbase = blockIdx.x * BM;
  const int pz = blockIdx.z;
  const int pd = (pz >> 2) & 1, ph = (pz >> 1) & 1, pw = pz & 1;

  int md, mh, mw;
  { int rv = vbase + (tid & 127);
    mw = rv & 15; int t = rv >> 4; mh = t & 15; md = t >> 4; }

  int nkd, kdL[2], ddL[2];
  int nkh, khL[2], dhL[2];
  int nkw, kwL[2], dwL[2];
  auto mk2 = [&](int p, int& n, int* kL, int* dL){
    if (p == 0){ n = 2; kL[0]=0; kL[1]=2; dL[0]=-1; dL[1]=0; }
    else       { n = 1; kL[0]=1; dL[0]=0; }
  };
  mk2(pd, nkd, kdL, ddL);
  mk2(ph, nkh, khL, dhL);
  mk2(pw, nkw, kwL, dwL);

  const int a_row_in = lane & 15;
  const int a_colb   = (lane >> 4) << 3;
  const int b_krow   = lane & 15;
  const int b_coln   = (lane >> 4) << 3;

  float acc[4][4][4];
  #pragma unroll
  for (int mi = 0; mi < 4; mi++)
    #pragma unroll
    for (int ni = 0; ni < 4; ni++)
      #pragma unroll
      for (int q = 0; q < 4; q++) acc[mi][ni][q] = 0.f;

  for (int ia = 0; ia < nkd; ia++)
  for (int ib = 0; ib < nkh; ib++)
  for (int ic = 0; ic < nkw; ic++){
    const int tap = (kdL[ia]*3 + khL[ib])*3 + kwL[ic];
    __syncthreads();
    if (tid < BM){
      int id = md + ddL[ia], ih = mh + dhL[ib], iw = mw + dwL[ic];
      bool v = (unsigned)id < 16u && (unsigned)ih < 16u && (unsigned)iw < 16u;
      offs[tid] = v ? ((id*16 + ih)*16 + iw) * 128 : -1;
    }

    for (int c0 = 0; c0 < 128; c0 += BK){
      __syncthreads();
      #pragma unroll
      for (int rep = 0; rep < 2; rep++){
        int idx = rep * 256 + tid;
        int row = idx >> 2, cg = idx & 3;
        int o = offs[row];
        uint4 h = make_uint4(0,0,0,0), l = make_uint4(0,0,0,0);
        if (o >= 0){
          h = *(const uint4*)(xhi + o + c0 + cg*8);
          l = *(const uint4*)(xlo + o + c0 + cg*8);
        }
        *(uint4*)&Ahi[row*AP + cg*8] = h;
        *(uint4*)&Alo[row*AP + cg*8] = l;
      }
      #pragma unroll
      for (int rep = 0; rep < 2; rep++){
        int idx = rep * 256 + tid;
        int kr = idx >> 4, cg = idx & 15;
        int src = tap*16384 + (c0 + kr)*128 + cg*8;
        *(uint4*)&Bhi[kr*BP + cg*8] = *(const uint4*)(whi + src);
        *(uint4*)&Blo[kr*BP + cg*8] = *(const uint4*)(wlo + src);
      }
      __syncthreads();

      #pragma unroll
      for (int k16 = 0; k16 < 2; k16++){
        uint32_t af[4][4], bh[2][4], bl[2][4];
        #pragma unroll
        for (int mi = 0; mi < 4; mi++){
          int r = warp_m*64 + mi*16 + a_row_in;
          ldsm4(af[mi], &Ahi[r*AP + k16*16 + a_colb]);
        }
        #pragma unroll
        for (int nj = 0; nj < 2; nj++){
          int kr = k16*16 + b_krow;
          int nc = warp_n*32 + nj*16 + b_coln;
          ldsm4t(bh[nj], &Bhi[kr*BP + nc]);
          ldsm4t(bl[nj], &Blo[kr*BP + nc]);
        }
        #pragma unroll
        for (int mi = 0; mi < 4; mi++)
          #pragma unroll
          for (int ni = 0; ni < 4; ni++){
            const uint32_t* h = &bh[ni>>1][(ni&1)*2];
            const uint32_t* L = &bl[ni>>1][(ni&1)*2];
            mma_bf16(acc[mi][ni], af[mi], h[0], h[1]);
            mma_bf16(acc[mi][ni], af[mi], L[0], L[1]);
          }
        #pragma unroll
        for (int mi = 0; mi < 4; mi++){
          int r = warp_m*64 + mi*16 + a_row_in;
          ldsm4(af[mi], &Alo[r*AP + k16*16 + a_colb]);
        }
        #pragma unroll
        for (int mi = 0; mi < 4; mi++)
          #pragma unroll
          for (int ni = 0; ni < 4; ni++){
            const uint32_t* h = &bh[ni>>1][(ni&1)*2];
            mma_bf16(acc[mi][ni], af[mi], h[0], h[1]);
          }
      }
    }
  }

  #pragma unroll
  for (int mi = 0; mi < 4; mi++){
    int lv0 = warp_m*64 + mi*16 + (lane >> 2);
    #pragma unroll
    for (int ni = 0; ni < 4; ni++){
      int col = warp_n*32 + ni*8 + (lane & 3)*2;
      float2 bb = *(const float2*)&bias[col];
      #pragma unroll
      for (int h = 0; h < 2; h++){
        int rv = vbase + lv0 + h*8;
        int vw = rv & 15; int t = rv >> 4; int vh = t & 15; int vd = t >> 4;
        int od = 2*vd + pd, oh = 2*vh + ph, ow = 2*vw + pw;
        size_t oo = (size_t)((od*32 + oh)*32 + ow) * 128 + col;
        unsigned hw, lw;
        split2(acc[mi][ni][2*h+0] + bb.x, acc[mi][ni][2*h+1] + bb.y, hw, lw);
        *(unsigned*)&ohi[oo] = hw;
        *(unsigned*)&olo[oo] = lw;
      }
    }
  }
}

// ---------------------------------------------------------------------------
// R14-PROVEN core: L1 on HMMA (DIM=8). Round-15: epilogue emits hi/lo splits.
// ---------------------------------------------------------------------------
__global__ __launch_bounds__(256, 2) void mma_s2_d8(
    const __nv_bfloat16* __restrict__ xhi, const __nv_bfloat16* __restrict__ xlo,
    const __nv_bfloat16* __restrict__ whi, const __nv_bfloat16* __restrict__ wlo,
    const float* __restrict__ bias,
    __nv_bfloat16* __restrict__ ohi, __nv_bfloat16* __restrict__ olo)
{
  constexpr int BM = 128, BK = 32;
  constexpr int AP = 40;
  constexpr int BP = 136;

  __shared__ __align__(16) unsigned short Ahi[BM*AP];
  __shared__ __align__(16) unsigned short Alo[BM*AP];
  __shared__ __align__(16) unsigned short Bhi[BK*BP];
  __shared__ __align__(16) unsigned short Blo[BK*BP];
  __shared__ int offs[BM];

  const int tid  = threadIdx.x;
  const int lane = tid & 31;
  const int wid  = tid >> 5;
  const int warp_m = wid >> 2;
  const int warp_n = wid & 3;
  const int vbase = blockIdx.x * BM;
  const int pz = blockIdx.z;
  const int pd = (pz >> 2) & 1, ph = (pz >> 1) & 1, pw = pz & 1;

  int md, mh, mw;
  { int rv = vbase + (tid & 127);
    mw = rv & 7; int t = rv >> 3; mh = t & 7; md = t >> 3; }

  int nkd, kdL[2], ddL[2];
  int nkh, khL[2], dhL[2];
  int nkw, kwL[2], dwL[2];
  auto mk2 = [&](int p, int& n, int* kL, int* dL){
    if (p == 0){ n = 2; kL[0]=0; kL[1]=2; dL[0]=-1; dL[1]=0; }
    else       { n = 1; kL[0]=1; dL[0]=0; }
  };
  mk2(pd, nkd, kdL, ddL);
  mk2(ph, nkh, khL, dhL);
  mk2(pw, nkw, kwL, dwL);

  const int a_row_in = lane & 15;
  const int a_colb   = (lane >> 4) << 3;
  const int b_krow   = lane & 15;
  const int b_coln   = (lane >> 4) << 3;

  float acc[4][4][4];
  #pragma unroll
  for (int mi = 0; mi < 4; mi++)
    #pragma unroll
    for (int ni = 0; ni < 4; ni++)
      #pragma unroll
      for (int q = 0; q < 4; q++) acc[mi][ni][q] = 0.f;

  for (int ia = 0; ia < nkd; ia++)
  for (int ib = 0; ib < nkh; ib++)
  for (int ic = 0; ic < nkw; ic++){
    const int tap = (kdL[ia]*3 + khL[ib])*3 + kwL[ic];
    __syncthreads();
    if (tid < BM){
      int id = md + ddL[ia], ih = mh + dhL[ib], iw = mw + dwL[ic];
      bool v = (unsigned)id < 8u && (unsigned)ih < 8u && (unsigned)iw < 8u;
      offs[tid] = v ? ((id*8 + ih)*8 + iw) * 128 : -1;
    }

    for (int c0 = 0; c0 < 128; c0 += BK){
      __syncthreads();
      #pragma unroll
      for (int rep = 0; rep < 2; rep++){
        int idx = rep * 256 + tid;
        int row = idx >> 2, cg = idx & 3;
        int o = offs[row];
        uint4 h = make_uint4(0,0,0,0), l = make_uint4(0,0,0,0);
        if (o >= 0){
          h = *(const uint4*)(xhi + o + c0 + cg*8);
          l = *(const uint4*)(xlo + o + c0 + cg*8);
        }
        *(uint4*)&Ahi[row*AP + cg*8] = h;
        *(uint4*)&Alo[row*AP + cg*8] = l;
      }
      #pragma unroll
      for (int rep = 0; rep < 2; rep++){
        int idx = rep * 256 + tid;
        int kr = idx >> 4, cg = idx & 15;
        int src = tap*16384 + (c0 + kr)*128 + cg*8;
        *(uint4*)&Bhi[kr*BP + cg*8] = *(const uint4*)(whi + src);
        *(uint4*)&Blo[kr*BP + cg*8] = *(const uint4*)(wlo + src);
      }
      __syncthreads();

      #pragma unroll
      for (int k16 = 0; k16 < 2; k16++){
        uint32_t af[4][4], bh[2][4], bl[2][4];
        #pragma unroll
        for (int mi = 0; mi < 4; mi++){
          int r = warp_m*64 + mi*16 + a_row_in;
          ldsm4(af[mi], &Ahi[r*AP + k16*16 + a_colb]);
        }
        #pragma unroll
        for (int nj = 0; nj < 2; nj++){
          int kr = k16*16 + b_krow;
          int nc = warp_n*32 + nj*16 + b_coln;
          ldsm4t(bh[nj], &Bhi[kr*BP + nc]);
          ldsm4t(bl[nj], &Blo[kr*BP + nc]);
        }
        #pragma unroll
        for (int mi = 0; mi < 4; mi++)
          #pragma unroll
          for (int ni = 0; ni < 4; ni++){
            const uint32_t* h = &bh[ni>>1][(ni&1)*2];
            const uint32_t* L = &bl[ni>>1][(ni&1)*2];
            mma_bf16(acc[mi][ni], af[mi], h[0], h[1]);
            mma_bf16(acc[mi][ni], af[mi], L[0], L[1]);
          }
        #pragma unroll
        for (int mi = 0; mi < 4; mi++){
          int r = warp_m*64 + mi*16 + a_row_in;
          ldsm4(af[mi], &Alo[r*AP + k16*16 + a_colb]);
        }
        #pragma unroll
        for (int mi = 0; mi < 4; mi++)
          #pragma unroll
          for (int ni = 0; ni < 4; ni++){
            const uint32_t* h = &bh[ni>>1][(ni&1)*2];
            mma_bf16(acc[mi][ni], af[mi], h[0], h[1]);
          }
      }
    }
  }

  #pragma unroll
  for (int mi = 0; mi < 4; mi++){
    int lv0 = warp_m*64 + mi*16 + (lane >> 2);
    #pragma unroll
    for (int ni = 0; ni < 4; ni++){
      int col = warp_n*32 + ni*8 + (lane & 3)*2;
      float2 bb = *(const float2*)&bias[col];
      #pragma unroll
      for (int h = 0; h < 2; h++){
        int rv = vbase + lv0 + h*8;
        int vw = rv & 7; int t = rv >> 3; int vh = t & 7; int vd = t >> 3;
        int od = 2*vd + pd, oh = 2*vh + ph, ow = 2*vw + pw;
        size_t oo = (size_t)((od*16 + oh)*16 + ow) * 128 + col;
        unsigned hw, lw;
        split2(acc[mi][ni][2*h+0] + bb.x, acc[mi][ni][2*h+1] + bb.y, hw, lw);
        *(unsigned*)&ohi[oo] = hw;
        *(unsigned*)&olo[oo] = lw;
      }
    }
  }
}

// ---------------------------------------------------------------------------
// Fused L5+L6 path tables (R6-proven).
// ---------------------------------------------------------------------------
__device__ __constant__ int c_np[2][3]   = {{2,2,0},{1,3,1}};
__device__ __constant__ int c_k1[2][3][3] = {{{1,0,0},{2,1,0},{0,0,0}},
                                             {{0,0,0},{2,1,0},{2,0,0}}};
__device__ __constant__ int c_k2[2][3][3] = {{{0,1,0},{1,2,0},{0,0,0}},
                                             {{0,0,0},{0,1,2},{2,0,0}}};

// P1 (R10-proven, verbatim): Wp + WpT
__global__ __launch_bounds__(256) void p1_wp(
    const float* __restrict__ w2, const float* __restrict__ w20)
{
  int t = blockIdx.x * 256 + threadIdx.x;
  if (t >= 27*27*128) return;
  int ci = t & 127;
  int k2l = (t >> 7) % 27;
  int k1l = t / (27*128);
  const float* a = w2 + ((size_t)k1l*128 + ci) * 64;
  const float* b = w20 + (size_t)k2l * 64 * 3;
  float s0 = 0.f, s1 = 0.f, s2 = 0.f;
  #pragma unroll 4
  for (int cm = 0; cm < 64; cm++){
    float av = a[cm];
    s0 = fmaf(av, b[cm*3+0], s0);
    s1 = fmaf(av, b[cm*3+1], s1);
    s2 = fmaf(av, b[cm*3+2], s2);
  }
  float* o = g_Wp + (size_t)t * 3;
  o[0] = s0; o[1] = s1; o[2] = s2;
  size_t kk = (size_t)k1l*27 + k2l;
  g_WpT[kk*384 + 0*128 + ci] = s0;
  g_WpT[kk*384 + 1*128 + ci] = s1;
  g_WpT[kk*384 + 2*128 + ci] = s2;
}

// P2 (R7-proven, verbatim): Weff[pz][dxl][co][ci]
__global__ __launch_bounds__(256) void p2_weff()
{
  int t = blockIdx.x * 256 + threadIdx.x;
  if (t >= 8*27*128) return;
  int ci = t & 127;
  int dxl = (t >> 7) % 27;
  int pz = t / (27*128);
  int jd = dxl / 9, jh = (dxl / 3) % 3, jw = dxl % 3;
  int pd = (pz >> 2) & 1, ph = (pz >> 1) & 1, pw = pz & 1;
  int nd = c_np[pd][jd], nh = c_np[ph][jh], nw = c_np[pw][jw];
  float s0 = 0.f, s1 = 0.f, s2 = 0.f;
  for (int a = 0; a < nd; a++)
  for (int b = 0; b < nh; b++)
  for (int c = 0; c < nw; c++){
    int k1l = (c_k1[pd][jd][a]*3 + c_k1[ph][jh][b])*3 + c_k1[pw][jw][c];
    int k2l = (c_k2[pd][jd][a]*3 + c_k2[ph][jh][b])*3 + c_k2[pw][jw][c];
    const float* wp = g_Wp + ((size_t)(k1l*27 + k2l)*128 + ci)*3;
    s0 += wp[0]; s1 += wp[1]; s2 += wp[2];
  }
  float* o = g_Weff + (size_t)(pz*27 + dxl) * 3 * 128;
  o[0*128 + ci] = s0;
  o[1*128 + ci] = s1;
  o[2*128 + ci] = s2;
}

// P3 (R6-proven, verbatim)
__global__ void p3_bias(const float* __restrict__ w20,
                        const float* __restrict__ b2,
                        const float* __restrict__ b20)
{
  int tid = threadIdx.x;
  if (tid < 81){
    int k2 = tid / 3, co = tid % 3;
    float s = 0.f;
    for (int cm = 0; cm < 64; cm++)
      s = fmaf(w20[(k2*64+cm)*3+co], b2[cm], s);
    g_bconv[tid] = s;
  }
  __syncthreads();
  if (tid < 3){
    float s = b20[tid];
    for (int k2 = 0; k2 < 27; k2++) s += g_bconv[k2*3+tid];
    g_btot[tid] = s;
  }
}

// ---------------------------------------------------------------------------
// Fused L5+L6 consumer (R14-proven, verbatim).
// ---------------------------------------------------------------------------
__global__ __launch_bounds__(256) void fused56b(
    const float* __restrict__ x, float* __restrict__ out)
{
  const int wid  = threadIdx.x >> 5;
  const int lane = threadIdx.x & 31;
  const int pz = blockIdx.z;
  const int pd = (pz >> 2) & 1, ph = (pz >> 1) & 1, pw = pz & 1;
  const int wg  = blockIdx.x * 8 + wid;
  const int seg = wg & 3;
  const int row = wg >> 2;
  const int rd = row >> 5, rh = row & 31;
  const int rw0 = seg * 8;
  const int l2 = 2 * lane;
  const int nw = 2 + pw;

  ull acc[8][3];
  #pragma unroll
  for (int r = 0; r < 8; r++)
    #pragma unroll
    for (int c = 0; c < 3; c++) acc[r][c] = 0ull;

  for (int jd = 0; jd <= 1 + pd; jd++){
    int id = rd + jd - 1;
    if ((unsigned)id >= 32u) continue;
    for (int jh = 0; jh <= 1 + ph; jh++){
      int ih = rh + jh - 1;
      if ((unsigned)ih >= 32u) continue;
      const float* xrow = x + (size_t)((id*32 + ih)*32) * 128;

      ull W[3][6];
      #pragma unroll
      for (int jw = 0; jw < 3; jw++){
        if (jw < nw){
          const float* Wt = g_Weff + (size_t)(pz*27 + jd*9 + jh*3 + jw) * 384;
          W[jw][0] = *(const ull*)(Wt +   0 + l2);
          W[jw][1] = *(const ull*)(Wt +  64 + l2);
          W[jw][2] = *(const ull*)(Wt + 128 + l2);
          W[jw][3] = *(const ull*)(Wt + 192 + l2);
          W[jw][4] = *(const ull*)(Wt + 256 + l2);
          W[jw][5] = *(const ull*)(Wt + 320 + l2);
        }
      }

      #pragma unroll
      for (int t = 0; t < 10; t++){
        int iw = rw0 - 1 + t;
        if ((unsigned)iw >= 32u) continue;
        const float* xp = xrow + iw * 128;
        ull x0 = *(const ull*)(xp + l2);
        ull x1 = *(const ull*)(xp + 64 + l2);
        #pragma unroll
        for (int jw = 0; jw < 3; jw++){
          int r = t - jw;
          if (jw < nw && (unsigned)r < 8u){
            ffma2(acc[r][0], x0, W[jw][0]); ffma2(acc[r][0], x1, W[jw][1]);
            ffma2(acc[r][1], x0, W[jw][2]); ffma2(acc[r][1], x1, W[jw][3]);
            ffma2(acc[r][2], x0, W[jw][4]); ffma2(acc[r][2], x1, W[jw][5]);
          }
        }
      }
    }
  }

  const float bt0 = g_btot[0], bt1 = g_btot[1], bt2 = g_btot[2];
  const int od = 2*rd + pd, oh = 2*rh + ph;

  #pragma unroll
  for (int r = 0; r < 8; r++){
    float s0, s1, s2;
    {
      float a, b;
      unpack2(acc[r][0], a, b); s0 = a + b;
      unpack2(acc[r][1], a, b); s1 = a + b;
      unpack2(acc[r][2], a, b); s2 = a + b;
    }
    #pragma unroll
    for (int sh = 16; sh > 0; sh >>= 1){
      s0 += __shfl_xor_sync(0xffffffffu, s0, sh);
      s1 += __shfl_xor_sync(0xffffffffu, s1, sh);
      s2 += __shfl_xor_sync(0xffffffffu, s2, sh);
    }
    if (lane == 0){
      int ow = 2*(rw0 + r) + pw;
      float* op = out + (size_t)((od*64 + oh)*64 + ow) * 3;
      op[0] = s0 + bt0;
      op[1] = s1 + bt1;
      op[2] = s2 + bt2;
    }
  }
}

// ---------------------------------------------------------------------------
// fix56w (R8-proven, verbatim): warp-per-voxel exact boundary fix.
// ---------------------------------------------------------------------------
__global__ __launch_bounds__(256) void fix56w(
    const float* __restrict__ x, const float* __restrict__ b20,
    float* __restrict__ out)
{
  const int gw = blockIdx.x * 8 + (threadIdx.x >> 5);
  const int lane = threadIdx.x & 31;
  const int l2 = 2 * lane;

  int plane = gw / 4096, r = gw % 4096;
  int a = r / 64, b = r % 64;
  int od, oh, ow;
  if      (plane == 0){ od = 0;  oh = a; ow = b; }
  else if (plane == 1){ od = 63; oh = a; ow = b; }
  else if (plane == 2){ oh = 0;  od = a; ow = b; if (od==0||od==63) return; }
  else if (plane == 3){ oh = 63; od = a; ow = b; if (od==0||od==63) return; }
  else if (plane == 4){ ow = 0;  od = a; oh = b; if (od==0||od==63||oh==0||oh==63) return; }
  else               { ow = 63; od = a; oh = b; if (od==0||od==63||oh==0||oh==63) return; }

  ull a0 = 0ull, a1 = 0ull, a2 = 0ull;
  float bias0 = __ldg(&b20[0]), bias1 = __ldg(&b20[1]), bias2 = __ldg(&b20[2]);

  for (int k2d = 0; k2d < 3; k2d++){
    int md = od + k2d - 1; if ((unsigned)md >= 64u) continue;
    int pmd = md & 1, rd = (md - pmd) >> 1;
    int n_d = pmd ? 1 : 2;
    int k1d[2], ixd[2];
    if (pmd){ k1d[0] = 1; ixd[0] = rd; }
    else    { k1d[0] = 0; ixd[0] = rd - 1; k1d[1] = 2; ixd[1] = rd; }
    for (int k2h = 0; k2h < 3; k2h++){
      int mh = oh + k2h - 1; if ((unsigned)mh >= 64u) continue;
      int pmh = mh & 1, rh = (mh - pmh) >> 1;
      int n_h = pmh ? 1 : 2;
      int k1h[2], ixh[2];
      if (pmh){ k1h[0] = 1; ixh[0] = rh; }
      else    { k1h[0] = 0; ixh[0] = rh - 1; k1h[1] = 2; ixh[1] = rh; }
      for (int k2w = 0; k2w < 3; k2w++){
        int mw = ow + k2w - 1; if ((unsigned)mw >= 64u) continue;
        int pmw = mw & 1, rw = (mw - pmw) >> 1;
        int n_w = pmw ? 1 : 2;
        int k1w[2], ixw[2];
        if (pmw){ k1w[0] = 1; ixw[0] = rw; }
        else    { k1w[0] = 0; ixw[0] = rw - 1; k1w[1] = 2; ixw[1] = rw; }

        int k2l = (k2d*3 + k2h)*3 + k2w;
        bias0 += g_bconv[k2l*3+0];
        bias1 += g_bconv[k2l*3+1];
        bias2 += g_bconv[k2l*3+2];

        for (int ia = 0; ia < n_d; ia++){
          if ((unsigned)ixd[ia] >= 32u) continue;
          for (int ib = 0; ib < n_h; ib++){
            if ((unsigned)ixh[ib] >= 32u) continue;
            for (int ic = 0; ic < n_w; ic++){
              if ((unsigned)ixw[ic] >= 32u) continue;
              int k1l = (k1d[ia]*3 + k1h[ib])*3 + k1w[ic];
              const float* wt = g_WpT + (size_t)(k1l*27 + k2l)*384;
              const float* xp = x + (size_t)((ixd[ia]*32 + ixh[ib])*32 + ixw[ic])*128;
              ull x0 = *(const ull*)(xp + l2);
              ull x1 = *(const ull*)(xp + 64 + l2);
              ffma2(a0, x0, *(const ull*)(wt +   0 + l2));
              ffma2(a0, x1, *(const ull*)(wt +  64 + l2));
              ffma2(a1, x0, *(const ull*)(wt + 128 + l2));
              ffma2(a1, x1, *(const ull*)(wt + 192 + l2));
              ffma2(a2, x0, *(const ull*)(wt + 256 + l2));
              ffma2(a2, x1, *(const ull*)(wt + 320 + l2));
            }
          }
        }
      }
    }
  }

  float s0, s1, s2;
  {
    float u, v;
    unpack2(a0, u, v); s0 = u + v;
    unpack2(a1, u, v); s1 = u + v;
    unpack2(a2, u, v); s2 = u + v;
  }
  #pragma unroll
  for (int sh = 16; sh > 0; sh >>= 1){
    s0 += __shfl_xor_sync(0xffffffffu, s0, sh);
    s1 += __shfl_xor_sync(0xffffffffu, s1, sh);
    s2 += __shfl_xor_sync(0xffffffffu, s2, sh);
  }
  if (lane == 0){
    float* op = out + (size_t)((od*64 + oh)*64 + ow) * 3;
    op[0] = s0 + bias0;
    op[1] = s1 + bias1;
    op[2] = s2 + bias2;
  }
}

// ---------------------------------------------------------------------------
// kernel_launch — split-fused pipeline with bf16 pair ping-pong (A/B).
// ---------------------------------------------------------------------------
extern "C" void kernel_launch(void* const* d_in, const int* in_sizes, int n_in,
                              void* d_out, int out_size)
{
  (void)in_sizes; (void)n_in; (void)out_size;
  const float* x   = (const float*)d_in[0];
  const float* w0  = (const float*)d_in[1];
  const float* b0  = (const float*)d_in[2];
  const float* w00 = (const float*)d_in[3];
  const float* b00 = (const float*)d_in[4];
  const float* w1  = (const float*)d_in[5];
  const float* b1  = (const float*)d_in[6];
  const float* w10 = (const float*)d_in[7];
  const float* b10 = (const float*)d_in[8];
  const float* w2  = (const float*)d_in[9];
  const float* b2  = (const float*)d_in[10];
  const float* w20 = (const float*)d_in[11];
  const float* b20 = (const float*)d_in[12];
  float* out = (float*)d_out;

  float *bufB = nullptr, *part = nullptr;
  __nv_bfloat16 *xhA, *xlA, *xhB, *xlB;
  __nv_bfloat16 *whi, *wlo, *whiB, *wloB, *whiC, *wloC, *whiD, *wloD;
  cudaGetSymbolAddress((void**)&bufB, g_bufB);
  cudaGetSymbolAddress((void**)&part, g_part);
  cudaGetSymbolAddress((void**)&xhA, g_xhiA);
  cudaGetSymbolAddress((void**)&xlA, g_xloA);
  cudaGetSymbolAddress((void**)&xhB, g_xhiB);
  cudaGetSymbolAddress((void**)&xlB, g_xloB);
  cudaGetSymbolAddress((void**)&whi, g_whi);
  cudaGetSymbolAddress((void**)&wlo, g_wlo);
  cudaGetSymbolAddress((void**)&whiB, g_whiB);
  cudaGetSymbolAddress((void**)&wloB, g_wloB);
  cudaGetSymbolAddress((void**)&whiC, g_whiC);
  cudaGetSymbolAddress((void**)&wloC, g_wloC);
  cudaGetSymbolAddress((void**)&whiD, g_whiD);
  cudaGetSymbolAddress((void**)&wloD, g_wloD);

  static bool attr_set = false;
  const int PIPE_SMEM = 2*37888 + 27*128*4;   // 89600 B
  if (!attr_set){
    cudaFuncSetAttribute(mma_s1r_pipe,
                         cudaFuncAttributeMaxDynamicSharedMemorySize, PIPE_SMEM);
    attr_set = true;
  }

  // (1) Wp + WpT precompute
  p1_wp<<<(27*27*128 + 255)/256, 256>>>(w2, w20);
  // (2-5) split all conv weights
  split_w_kernel<<<1728, 256>>>(w0, whiD, wloD);
  split_w_kernel<<<1728, 256>>>(w00, whiC, wloC);
  split_w_kernel<<<1728, 256>>>(w1, whiB, wloB);
  split_w_kernel<<<1728, 256>>>(w10, whi, wlo);
  // (6) split network input x -> pair A (65536 elems)
  split_x_kernel<<<64, 256>>>(x, xhA, xlA, 65536/4);
  // (7) L1 on HMMA: reads A, writes splits -> pair B (512K)
  {
    dim3 g(4, 1, 8);
    mma_s2_d8<<<g, 256>>>(xhA, xlA, whiD, wloD, b0, xhB, xlB);
  }
  // (8) L2 on HMMA, 7-way tap split: reads B -> partials
  {
    dim3 g(32, 7, 1);
    mma_s1_part<<<g, 256>>>(xhB, xlB, whiC, wloC, part);
  }
  // (9) L2 finish: sum partials + bias + relu, write splits -> pair A (512K)
  l2_finish<<<512, 256>>>(part, b00, xhA, xlA);
  // (10) L3 on HMMA: reads A, writes splits -> pair B (4M)
  {
    dim3 g(32, 1, 8);
    mma_s2<<<g, 256>>>(xhA, xlA, whiB, wloB, b1, xhB, xlB);
  }
  // (11) L4 on pipelined HMMA: reads B -> bufB (fp32, for fused L5+L6)
  mma_s1r_pipe<<<256, 256, PIPE_SMEM>>>(xhB, xlB, whi, wlo, b10, bufB);
  // (12-13) fused-weight precompute for L5+L6
  p2_weff<<<(8*27*128 + 255)/256, 256>>>();
  p3_bias<<<1, 128>>>(w20, b2, b20);
  // (14) Fused L5+L6
  {
    dim3 g(512, 1, 8);
    fused56b<<<g, 256>>>(bufB, out);
  }
  // (15) Exact boundary fix
  fix56w<<<3072, 256>>>(bufB, b20, out);
}

// round 16
// speedup vs baseline: 1.4373x; 1.0136x over previous
#include <cuda_runtime.h>
#include <cuda_bf16.h>
#include <cstdint>

// ---------------------------------------------------------------------------
// Static scratch (no allocation allowed)
// ---------------------------------------------------------------------------
__device__ float g_bufB[4194304];
__device__ float g_part[3670016];   // L2 partials; later reused for fix56 partials
__device__ float g_Wp[279936];
__device__ float g_WpT[279936];
__device__ float g_Weff[110592];
__device__ float g_bconv[81];
__device__ float g_btot[3];
__device__ __nv_bfloat16 g_xhiA[4194304];   // pair A
__device__ __nv_bfloat16 g_xloA[4194304];
__device__ __nv_bfloat16 g_xhiB[4194304];   // pair B
__device__ __nv_bfloat16 g_xloB[4194304];
__device__ __nv_bfloat16 g_whi[442368];    // L4 weights (w10)
__device__ __nv_bfloat16 g_wlo[442368];
__device__ __nv_bfloat16 g_whiB[442368];   // L3 weights (w1)
__device__ __nv_bfloat16 g_wloB[442368];
__device__ __nv_bfloat16 g_whiC[442368];   // L2 weights (w00)
__device__ __nv_bfloat16 g_wloC[442368];
__device__ __nv_bfloat16 g_whiD[442368];   // L1 weights (w0)
__device__ __nv_bfloat16 g_wloD[442368];

typedef unsigned long long ull;

// ---------------------------------------------------------------------------
// f32x2 packed helpers
// ---------------------------------------------------------------------------
__device__ __forceinline__ ull pack2(float x, float y){
  ull r; asm("mov.b64 %0, {%1, %2};" : "=l"(r) : "f"(x), "f"(y)); return r;
}
__device__ __forceinline__ void unpack2(ull v, float& x, float& y){
  asm("mov.b64 {%0, %1}, %2;" : "=f"(x), "=f"(y) : "l"(v));
}
__device__ __forceinline__ void ffma2(ull& acc, ull a, ull b){
  asm("fma.rn.f32x2 %0, %1, %2, %0;" : "+l"(acc) : "l"(a), "l"(b));
}

// pack two floats into hi/lo bf16-pair words (matches split_x arithmetic)
__device__ __forceinline__ void split2(float vx, float vy,
                                       unsigned& hw, unsigned& lw){
  __nv_bfloat16 h0 = __float2bfloat16_rn(vx);
  __nv_bfloat16 h1 = __float2bfloat16_rn(vy);
  __nv_bfloat16 l0 = __float2bfloat16_rn(vx - __bfloat162float(h0));
  __nv_bfloat16 l1 = __float2bfloat16_rn(vy - __bfloat162float(h1));
  hw = (unsigned)*(unsigned short*)&h0 | ((unsigned)*(unsigned short*)&h1 << 16);
  lw = (unsigned)*(unsigned short*)&l0 | ((unsigned)*(unsigned short*)&l1 << 16);
}

// ---------------------------------------------------------------------------
// mma.sync / ldmatrix / cp.async helpers (baseline PTX, legal on sm_103)
// ---------------------------------------------------------------------------
__device__ __forceinline__ void ldsm4(uint32_t* r, const void* p){
  uint32_t a = (uint32_t)__cvta_generic_to_shared(p);
  asm volatile("ldmatrix.sync.aligned.m8n8.x4.shared.b16 {%0,%1,%2,%3}, [%4];"
    : "=r"(r[0]), "=r"(r[1]), "=r"(r[2]), "=r"(r[3]) : "r"(a));
}
__device__ __forceinline__ void ldsm4t(uint32_t* r, const void* p){
  uint32_t a = (uint32_t)__cvta_generic_to_shared(p);
  asm volatile("ldmatrix.sync.aligned.m8n8.x4.trans.shared.b16 {%0,%1,%2,%3}, [%4];"
    : "=r"(r[0]), "=r"(r[1]), "=r"(r[2]), "=r"(r[3]) : "r"(a));
}
__device__ __forceinline__ void mma_bf16(float* c, const uint32_t* a,
                                         uint32_t b0, uint32_t b1){
  asm volatile("mma.sync.aligned.m16n8k16.row.col.f32.bf16.bf16.f32 "
    "{%0,%1,%2,%3}, {%4,%5,%6,%7}, {%8,%9}, {%0,%1,%2,%3};"
    : "+f"(c[0]), "+f"(c[1]), "+f"(c[2]), "+f"(c[3])
    : "r"(a[0]), "r"(a[1]), "r"(a[2]), "r"(a[3]), "r"(b0), "r"(b1));
}
__device__ __forceinline__ void cpasync16(void* dst, const void* src, bool pred){
  uint32_t d = (uint32_t)__cvta_generic_to_shared(dst);
  int sz = pred ? 16 : 0;
  asm volatile("cp.async.cg.shared.global [%0], [%1], 16, %2;"
               :: "r"(d), "l"(src), "r"(sz));
}
#define CP_COMMIT() asm volatile("cp.async.commit_group;")
#define CP_WAIT1()  asm volatile("cp.async.wait_group 1;")
#define CP_WAIT0()  asm volatile("cp.async.wait_group 0;")

// ---------------------------------------------------------------------------
// bf16 hi/lo split pre-passes
// ---------------------------------------------------------------------------
__global__ __launch_bounds__(256) void split_x_kernel(
    const float* __restrict__ x, __nv_bfloat16* __restrict__ hi,
    __nv_bfloat16* __restrict__ lo, int n4)
{
  int i = blockIdx.x * 256 + threadIdx.x;
  if (i >= n4) return;
  float4 v = ((const float4*)x)[i];
  __nv_bfloat16 h0 = __float2bfloat16_rn(v.x);
  __nv_bfloat16 h1 = __float2bfloat16_rn(v.y);
  __nv_bfloat16 h2 = __float2bfloat16_rn(v.z);
  __nv_bfloat16 h3 = __float2bfloat16_rn(v.w);
  __nv_bfloat16 l0 = __float2bfloat16_rn(v.x - __bfloat162float(h0));
  __nv_bfloat16 l1 = __float2bfloat16_rn(v.y - __bfloat162float(h1));
  __nv_bfloat16 l2 = __float2bfloat16_rn(v.z - __bfloat162float(h2));
  __nv_bfloat16 l3 = __float2bfloat16_rn(v.w - __bfloat162float(h3));
  ushort4 hv = make_ushort4(*(unsigned short*)&h0, *(unsigned short*)&h1,
                            *(unsigned short*)&h2, *(unsigned short*)&h3);
  ushort4 lv = make_ushort4(*(unsigned short*)&l0, *(unsigned short*)&l1,
                            *(unsigned short*)&l2, *(unsigned short*)&l3);
  ((ushort4*)hi)[i] = hv;
  ((ushort4*)lo)[i] = lv;
}

// NEW (round 16): split all 4 weight tensors in one launch (blockIdx.y selects)
__global__ __launch_bounds__(256) void split_w4_kernel(
    const float* __restrict__ wa, const float* __restrict__ wb,
    const float* __restrict__ wc, const float* __restrict__ wd,
    __nv_bfloat16* __restrict__ ha, __nv_bfloat16* __restrict__ la,
    __nv_bfloat16* __restrict__ hb, __nv_bfloat16* __restrict__ lb,
    __nv_bfloat16* __restrict__ hc, __nv_bfloat16* __restrict__ lc,
    __nv_bfloat16* __restrict__ hd, __nv_bfloat16* __restrict__ ld)
{
  int i = blockIdx.x * 256 + threadIdx.x;
  if (i >= 27*128*128) return;
  const float* w; __nv_bfloat16 *hi, *lo;
  switch (blockIdx.y){
    case 0: w = wa; hi = ha; lo = la; break;
    case 1: w = wb; hi = hb; lo = lb; break;
    case 2: w = wc; hi = hc; lo = lc; break;
    default: w = wd; hi = hd; lo = ld; break;
  }
  float v = w[i];
  __nv_bfloat16 h = __float2bfloat16_rn(v);
  hi[i] = h;
  lo[i] = __float2bfloat16_rn(v - __bfloat162float(h));
}

// ---------------------------------------------------------------------------
// R13-PROVEN core: L2 on HMMA with tap-split partials (7 groups of <=4).
// ---------------------------------------------------------------------------
__global__ __launch_bounds__(256, 2) void mma_s1_part(
    const __nv_bfloat16* __restrict__ xhi, const __nv_bfloat16* __restrict__ xlo,
    const __nv_bfloat16* __restrict__ whi, const __nv_bfloat16* __restrict__ wlo,
    float* __restrict__ part)
{
  constexpr int BM = 128, BK = 32;
  constexpr int AP = 40;
  constexpr int BP = 136;

  __shared__ __align__(16) unsigned short Ahi[BM*AP];
  __shared__ __align__(16) unsigned short Alo[BM*AP];
  __shared__ __align__(16) unsigned short Bhi[BK*BP];
  __shared__ __align__(16) unsigned short Blo[BK*BP];
  __shared__ int offs[BM];

  const int tid  = threadIdx.x;
  const int lane = tid & 31;
  const int wid  = tid >> 5;
  const int warp_m = wid >> 2;
  const int warp_n = wid & 3;
  const int vbase = blockIdx.x * BM;
  const int tap0 = blockIdx.y * 4;
  const int tap1 = min(27, tap0 + 4);
  float* outp = part + (size_t)blockIdx.y * 524288;

  int md, mh, mw;
  { int rv = vbase + (tid & 127);
    mw = rv & 15; int t = rv >> 4; mh = t & 15; md = t >> 4; }

  const int a_row_in = lane & 15;
  const int a_colb   = (lane >> 4) << 3;
  const int b_krow   = lane & 15;
  const int b_coln   = (lane >> 4) << 3;

  float acc[4][4][4];
  #pragma unroll
  for (int mi = 0; mi < 4; mi++)
    #pragma unroll
    for (int ni = 0; ni < 4; ni++)
      #pragma unroll
      for (int q = 0; q < 4; q++) acc[mi][ni][q] = 0.f;

  for (int tap = tap0; tap < tap1; tap++){
    const int kw = tap % 3, kh = (tap / 3) % 3, kd = tap / 9;
    __syncthreads();
    if (tid < BM){
      int id = md + kd - 1, ih = mh + kh - 1, iw = mw + kw - 1;
      bool v = (unsigned)id < 16u && (unsigned)ih < 16u && (unsigned)iw < 16u;
      offs[tid] = v ? ((id*16 + ih)*16 + iw) * 128 : -1;
    }

    for (int c0 = 0; c0 < 128; c0 += BK){
      __syncthreads();
      #pragma unroll
      for (int rep = 0; rep < 2; rep++){
        int idx = rep * 256 + tid;
        int row = idx >> 2, cg = idx & 3;
        int o = offs[row];
        uint4 h = make_uint4(0,0,0,0), l = make_uint4(0,0,0,0);
        if (o >= 0){
          h = *(const uint4*)(xhi + o + c0 + cg*8);
          l = *(const uint4*)(xlo + o + c0 + cg*8);
        }
        *(uint4*)&Ahi[row*AP + cg*8] = h;
        *(uint4*)&Alo[row*AP + cg*8] = l;
      }
      #pragma unroll
      for (int rep = 0; rep < 2; rep++){
        int idx = rep * 256 + tid;
        int kr = idx >> 4, cg = idx & 15;
        int src = tap*16384 + (c0 + kr)*128 + cg*8;
        *(uint4*)&Bhi[kr*BP + cg*8] = *(const uint4*)(whi + src);
        *(uint4*)&Blo[kr*BP + cg*8] = *(const uint4*)(wlo + src);
      }
      __syncthreads();

      #pragma unroll
      for (int k16 = 0; k16 < 2; k16++){
        uint32_t af[4][4], bh[2][4], bl[2][4];
        #pragma unroll
        for (int mi = 0; mi < 4; mi++){
          int r = warp_m*64 + mi*16 + a_row_in;
          ldsm4(af[mi], &Ahi[r*AP + k16*16 + a_colb]);
        }
        #pragma unroll
        for (int nj = 0; nj < 2; nj++){
          int kr = k16*16 + b_krow;
          int nc = warp_n*32 + nj*16 + b_coln;
          ldsm4t(bh[nj], &Bhi[kr*BP + nc]);
          ldsm4t(bl[nj], &Blo[kr*BP + nc]);
        }
        #pragma unroll
        for (int mi = 0; mi < 4; mi++)
          #pragma unroll
          for (int ni = 0; ni < 4; ni++){
            const uint32_t* h = &bh[ni>>1][(ni&1)*2];
            const uint32_t* L = &bl[ni>>1][(ni&1)*2];
            mma_bf16(acc[mi][ni], af[mi], h[0], h[1]);
            mma_bf16(acc[mi][ni], af[mi], L[0], L[1]);
          }
        #pragma unroll
        for (int mi = 0; mi < 4; mi++){
          int r = warp_m*64 + mi*16 + a_row_in;
          ldsm4(af[mi], &Alo[r*AP + k16*16 + a_colb]);
        }
        #pragma unroll
        for (int mi = 0; mi < 4; mi++)
          #pragma unroll
          for (int ni = 0; ni < 4; ni++){
            const uint32_t* h = &bh[ni>>1][(ni&1)*2];
            mma_bf16(acc[mi][ni], af[mi], h[0], h[1]);
          }
      }
    }
  }

  #pragma unroll
  for (int mi = 0; mi < 4; mi++){
    int v0 = vbase + warp_m*64 + mi*16 + (lane >> 2);
    #pragma unroll
    for (int ni = 0; ni < 4; ni++){
      int col = warp_n*32 + ni*8 + (lane & 3)*2;
      *(float2*)&outp[(size_t)v0*128 + col] =
          make_float2(acc[mi][ni][0], acc[mi][ni][1]);
      *(float2*)&outp[(size_t)(v0+8)*128 + col] =
          make_float2(acc[mi][ni][2], acc[mi][ni][3]);
    }
  }
}

// L2 finish (R15-proven, verbatim)
__global__ __launch_bounds__(256) void l2_finish(
    const float* __restrict__ part, const float* __restrict__ bias,
    __nv_bfloat16* __restrict__ xhi, __nv_bfloat16* __restrict__ xlo)
{
  int i = blockIdx.x * 256 + threadIdx.x;
  if (i >= 131072) return;
  float4 s = ((const float4*)part)[i];
  #pragma unroll
  for (int g = 1; g < 7; g++){
    float4 p = ((const float4*)(part + (size_t)g*524288))[i];
    s.x += p.x; s.y += p.y; s.z += p.z; s.w += p.w;
  }
  int col = (i * 4) & 127;
  float4 b = *(const float4*)&bias[col];
  float4 r;
  r.x = fmaxf(s.x + b.x, 0.f);
  r.y = fmaxf(s.y + b.y, 0.f);
  r.z = fmaxf(s.z + b.z, 0.f);
  r.w = fmaxf(s.w + b.w, 0.f);
  unsigned h0, l0, h1, l1;
  split2(r.x, r.y, h0, l0);
  split2(r.z, r.w, h1, l1);
  ((uint2*)xhi)[i] = make_uint2(h0, h1);
  ((uint2*)xlo)[i] = make_uint2(l0, l1);
}

// ---------------------------------------------------------------------------
// R11-PROVEN (verbatim): L4 on HMMA with cp.async 2-stage pipeline.
// ---------------------------------------------------------------------------
__global__ __launch_bounds__(256, 2) void mma_s1r_pipe(
    const __nv_bfloat16* __restrict__ xhi, const __nv_bfloat16* __restrict__ xlo,
    const __nv_bfloat16* __restrict__ whi, const __nv_bfloat16* __restrict__ wlo,
    const float* __restrict__ bias, float* __restrict__ out)
{
  constexpr int AP = 40, BP = 136;
  constexpr int ASZ = 128*AP;
  constexpr int BSZ = 32*BP;
  constexpr int STG = 2*ASZ + 2*BSZ;
  constexpr int NIT = 27*4;

  extern __shared__ __align__(16) unsigned short dsm[];
  int* offsAll = (int*)(dsm + 2*STG);

  const int tid  = threadIdx.x;
  const int lane = tid & 31;
  const int wid  = tid >> 5;
  const int warp_m = wid >> 2;
  const int warp_n = wid & 3;
  const int vbase = blockIdx.x * 128;

  for (int s = tid; s < 27*128; s += 256){
    int tap = s >> 7, row = s & 127;
    int kw = tap % 3, kh = (tap/3)%3, kd = tap/9;
    int rv = vbase + row;
    int mw = rv & 31, mh = (rv>>5)&31, md = rv>>10;
    int id = md + kd - 1, ih = mh + kh - 1, iw = mw + kw - 1;
    bool v = (unsigned)id < 32u && (unsigned)ih < 32u && (unsigned)iw < 32u;
    offsAll[s] = v ? ((id*32 + ih)*32 + iw) * 128 : -1;
  }
  __syncthreads();

  const int a_row_in = lane & 15;
  const int a_colb   = (lane >> 4) << 3;
  const int b_krow   = lane & 15;
  const int b_coln   = (lane >> 4) << 3;

  float acc[4][4][4];
  #pragma unroll
  for (int mi = 0; mi < 4; mi++)
    #pragma unroll
    for (int ni = 0; ni < 4; ni++)
      #pragma unroll
      for (int q = 0; q < 4; q++) acc[mi][ni][q] = 0.f;

  auto fill = [&](int st, int it){
    int tap = it >> 2, c0 = (it & 3) * 32;
    unsigned short* Ah = dsm + st*STG;
    unsigned short* Al = Ah + ASZ;
    unsigned short* Bh = Ah + 2*ASZ;
    unsigned short* Bl = Bh + BSZ;
    #pragma unroll
    for (int rep = 0; rep < 2; rep++){
      int idx = rep*256 + tid;
      int row = idx >> 2, cg = idx & 3;
      int o = offsAll[tap*128 + row];
      bool p = o >= 0;
      int ob = (p ? o : 0) + c0 + cg*8;
      cpasync16(&Ah[row*AP + cg*8], xhi + ob, p);
      cpasync16(&Al[row*AP + cg*8], xlo + ob, p);
    }
    #pragma unroll
    for (int rep = 0; rep < 2; rep++){
      int idx = rep*256 + tid;
      int kr = idx >> 4, cg = idx & 15;
      int src = tap*16384 + (c0 + kr)*128 + cg*8;
      cpasync16(&Bh[kr*BP + cg*8], whi + src, true);
      cpasync16(&Bl[kr*BP + cg*8], wlo + src, true);
    }
  };

  fill(0, 0);
  CP_COMMIT();

  for (int it = 0; it < NIT; ++it){
    const int b = it & 1;
    if (it + 1 < NIT){
      fill(b ^ 1, it + 1);
      CP_COMMIT();
      CP_WAIT1();
    } else {
      CP_WAIT0();
    }
    __syncthreads();

    const unsigned short* Ah = dsm + b*STG;
    const unsigned short* Al = Ah + ASZ;
    const unsigned short* Bh = Ah + 2*ASZ;
    const unsigned short* Bl = Bh + BSZ;

    #pragma unroll
    for (int k16 = 0; k16 < 2; k16++){
      uint32_t af[4][4], bh[2][4], bl[2][4];
      #pragma unroll
      for (int mi = 0; mi < 4; mi++){
        int r = warp_m*64 + mi*16 + a_row_in;
        ldsm4(af[mi], &Ah[r*AP + k16*16 + a_colb]);
      }
      #pragma unroll
      for (int nj = 0; nj < 2; nj++){
        int kr = k16*16 + b_krow;
        int nc = warp_n*32 + nj*16 + b_coln;
        ldsm4t(bh[nj], &Bh[kr*BP + nc]);
        ldsm4t(bl[nj], &Bl[kr*BP + nc]);
      }
      #pragma unroll
      for (int mi = 0; mi < 4; mi++)
        #pragma unroll
        for (int ni = 0; ni < 4; ni++){
          const uint32_t* h = &bh[ni>>1][(ni&1)*2];
          const uint32_t* L = &bl[ni>>1][(ni&1)*2];
          mma_bf16(acc[mi][ni], af[mi], h[0], h[1]);
          mma_bf16(acc[mi][ni], af[mi], L[0], L[1]);
        }
      #pragma unroll
      for (int mi = 0; mi < 4; mi++){
        int r = warp_m*64 + mi*16 + a_row_in;
        ldsm4(af[mi], &Al[r*AP + k16*16 + a_colb]);
      }
      #pragma unroll
      for (int mi = 0; mi < 4; mi++)
        #pragma unroll
        for (int ni = 0; ni < 4; ni++){
          const uint32_t* h = &bh[ni>>1][(ni&1)*2];
          mma_bf16(acc[mi][ni], af[mi], h[0], h[1]);
        }
    }
    __syncthreads();
  }

  #pragma unroll
  for (int mi = 0; mi < 4; mi++){
    int v0 = vbase + warp_m*64 + mi*16 + (lane >> 2);
    #pragma unroll
    for (int ni = 0; ni < 4; ni++){
      int col = warp_n*32 + ni*8 + (lane & 3)*2;
      float2 bb = *(const float2*)&bias[col];
      float2 r0, r1;
      r0.x = fmaxf(acc[mi][ni][0] + bb.x, 0.f);
      r0.y = fmaxf(acc[mi][ni][1] + bb.y, 0.f);
      r1.x = fmaxf(acc[mi][ni][2] + bb.x, 0.f);
      r1.y = fmaxf(acc[mi][ni][3] + bb.y, 0.f);
      *(float2*)&out[(size_t)v0*128 + col]     = r0;
      *(float2*)&out[(size_t)(v0+8)*128 + col] = r1;
    }
  }
}

// ---------------------------------------------------------------------------
// R15-PROVEN (verbatim): L3 on HMMA, stride-2, DIM=16 -> 32; emits hi/lo.
// ---------------------------------------------------------------------------
__global__ __launch_bounds__(256, 2) void mma_s2(
    const __nv_bfloat16* __restrict__ xhi, const __nv_bfloat16* __restrict__ xlo,
    const __nv_bfloat16* __restrict__ whi, const __nv_bfloat16* __restrict__ wlo,
    const float* __restrict__ bias,
    __nv_bfloat16* __restrict__ ohi, __nv_bfloat16* __restrict__ olo)
{
  constexpr int BM = 128, BK = 32;
  constexpr int AP = 40;
  constexpr int BP = 136;

  __shared__ __align__(16) unsigned short Ahi[BM*AP];
  __shared__ __align__(16) unsigned short Alo[BM*AP];
  __shared__ __align__(16) unsigned short Bhi[BK*BP];
  __shared__ __align__(16) unsigned short Blo[BK*BP];
  __shared__ int offs[BM];

  const int tid  = threadIdx.x;
  const int lane = tid & 31;
  const int wid  = tid >> 5;
  const int warp_m = wid >> 2;
  const int warp_n = wid & 3;
  const int vbase = blockIdx.x * BM;
  const int pz = blockIdx.z;
  const int pd = (pz >> 2) & 1, ph = (pz >> 1) & 1, pw = pz & 1;

  int md, mh, mw;
  { int rv = vbase + (tid & 127);
    mw = rv & 15; int t = rv >> 4; mh = t & 15; md = t >> 4; }

  int nkd, kdL[2], ddL[2];
  int nkh, khL[2], dhL[2];
  int nkw, kwL[2], dwL[2];
  auto mk2 = [&](int p, int& n, int* kL, int* dL){
    if (p == 0){ n = 2; kL[0]=0; kL[1]=2; dL[0]=-1; dL[1]=0; }
    else       { n = 1; kL[0]=1; dL[0]=0; }
  };
  mk2(pd, nkd, kdL, ddL);
  mk2(ph, nkh, khL, dhL);
  mk2(pw, nkw, kwL, dwL);

  const int a_row_in = lane & 15;
  const int a_colb   = (lane >> 4) << 3;
  const int b_krow   = lane & 15;
  const int b_coln   = (lane >> 4) << 3;

  float acc[4][4][4];
  #pragma unroll
  for (int mi = 0; mi < 4; mi++)
    #pragma unroll
    for (int ni = 0; ni < 4; ni++)
      #pragma unroll
      for (int q = 0; q < 4; q++) acc[mi][ni][q] = 0.f;

  for (int ia = 0; ia < nkd; ia++)
  for (int ib = 0; ib < nkh; ib++)
  for (int ic = 0; ic < nkw; ic++){
    const int tap = (kdL[ia]*3 + khL[ib])*3 + kwL[ic];
    __syncthreads();
    if (tid < BM){
      int id = md + ddL[ia], ih = mh + dhL[ib], iw = mw + dwL[ic];
      bool v = (unsigned)id < 16u && (unsigned)ih < 16u && (unsigned)iw < 16u;
      offs[tid] = v ? ((id*16 + ih)*16 + iw) * 128 : -1;
    }

    for (int c0 = 0; c0 < 128; c0 += BK){
      __syncthreads();
      #pragma unroll
      for (int rep = 0; rep < 2; rep++){
        int idx = rep * 256 + tid;
        int row = idx >> 2, cg = idx & 3;
        int o = offs[row];
        uint4 h = make_uint4(0,0,0,0), l = make_uint4(0,0,0,0);
        if (o >= 0){
          h = *(const uint4*)(xhi + o + c0 + cg*8);
          l = *(const uint4*)(xlo + o + c0 + cg*8);
        }
        *(uint4*)&Ahi[row*AP + cg*8] = h;
        *(uint4*)&Alo[row*AP + cg*8] = l;
      }
      #pragma unroll
      for (int rep = 0; rep < 2; rep++){
        int idx = rep * 256 + tid;
        int kr = idx >> 4, cg = idx & 15;
        int src = tap*16384 + (c0 + kr)*128 + cg*8;
        *(uint4*)&Bhi[kr*BP + cg*8] = *(const uint4*)(whi + src);
        *(uint4*)&Blo[kr*BP + cg*8] = *(const uint4*)(wlo + src);
      }
      __syncthreads();

      #pragma unroll
      for (int k16 = 0; k16 < 2; k16++){
        uint32_t af[4][4], bh[2][4], bl[2][4];
        #pragma unroll
        for (int mi = 0; mi < 4; mi++){
          int r = warp_m*64 + mi*16 + a_row_in;
          ldsm4(af[mi], &Ahi[r*AP + k16*16 + a_colb]);
        }
        #pragma unroll
        for (int nj = 0; nj < 2; nj++){
          int kr = k16*16 + b_krow;
          int nc = warp_n*32 + nj*16 + b_coln;
          ldsm4t(bh[nj], &Bhi[kr*BP + nc]);
          ldsm4t(bl[nj], &Blo[kr*BP + nc]);
        }
        #pragma unroll
        for (int mi = 0; mi < 4; mi++)
          #pragma unroll
          for (int ni = 0; ni < 4; ni++){
            const uint32_t* h = &bh[ni>>1][(ni&1)*2];
            const uint32_t* L = &bl[ni>>1][(ni&1)*2];
            mma_bf16(acc[mi][ni], af[mi], h[0], h[1]);
            mma_bf16(acc[mi][ni], af[mi], L[0], L[1]);
          }
        #pragma unroll
        for (int mi = 0; mi < 4; mi++){
          int r = warp_m*64 + mi*16 + a_row_in;
          ldsm4(af[mi], &Alo[r*AP + k16*16 + a_colb]);
        }
        #pragma unroll
        for (int mi = 0; mi < 4; mi++)
          #pragma unroll
          for (int ni = 0; ni < 4; ni++){
            const uint32_t* h = &bh[ni>>1][(ni&1)*2];
            mma_bf16(acc[mi][ni], af[mi], h[0], h[1]);
          }
      }
    }
  }

  #pragma unroll
  for (int mi = 0; mi < 4; mi++){
    int lv0 = warp_m*64 + mi*16 + (lane >> 2);
    #pragma unroll
    for (int ni = 0; ni < 4; ni++){
      int col = warp_n*32 + ni*8 + (lane & 3)*2;
      float2 bb = *(const float2*)&bias[col];
      #pragma unroll
      for (int h = 0; h < 2; h++){
        int rv = vbase + lv0 + h*8;
        int vw = rv & 15; int t = rv >> 4; int vh = t & 15; int vd = t >> 4;
        int od = 2*vd + pd, oh = 2*vh + ph, ow = 2*vw + pw;
        size_t oo = (size_t)((od*32 + oh)*32 + ow) * 128 + col;
        unsigned hw, lw;
        split2(acc[mi][ni][2*h+0] + bb.x, acc[mi][ni][2*h+1] + bb.y, hw, lw);
        *(unsigned*)&ohi[oo] = hw;
        *(unsigned*)&olo[oo] = lw;
      }
    }
  }
}

// ---------------------------------------------------------------------------
// R15-PROVEN (verbatim): L1 on HMMA (DIM=8); emits hi/lo splits.
// ---------------------------------------------------------------------------
__global__ __launch_bounds__(256, 2) void mma_s2_d8(
    const __nv_bfloat16* __restrict__ xhi, const __nv_bfloat16* __restrict__ xlo,
    const __nv_bfloat16* __restrict__ whi, const __nv_bfloat16* __restrict__ wlo,
    const float* __restrict__ bias,
    __nv_bfloat16* __restrict__ ohi, __nv_bfloat16* __restrict__ olo)
{
  constexpr int BM = 128, BK = 32;
  constexpr int AP = 40;
  constexpr int BP = 136;

  __shared__ __align__(16) unsigned short Ahi[BM*AP];
  __shared__ __align__(16) unsigned short Alo[BM*AP];
  __shared__ __align__(16) unsigned short Bhi[BK*BP];
  __shared__ __align__(16) unsigned short Blo[BK*BP];
  __shared__ int offs[BM];

  const int tid  = threadIdx.x;
  const int lane = tid & 31;
  const int wid  = tid >> 5;
  const int warp_m = wid >> 2;
  const int warp_n = wid & 3;
  const int vbase = blockIdx.x * BM;
  const int pz = blockIdx.z;
  const int pd = (pz >> 2) & 1, ph = (pz >> 1) & 1, pw = pz & 1;

  int md, mh, mw;
  { int rv = vbase + (tid & 127);
    mw = rv & 7; int t = rv >> 3; mh = t & 7; md = t >> 3; }

  int nkd, kdL[2], ddL[2];
  int nkh, khL[2], dhL[2];
  int nkw, kwL[2], dwL[2];
  auto mk2 = [&](int p, int& n, int* kL, int* dL){
    if (p == 0){ n = 2; kL[0]=0; kL[1]=2; dL[0]=-1; dL[1]=0; }
    else       { n = 1; kL[0]=1; dL[0]=0; }
  };
  mk2(pd, nkd, kdL, ddL);
  mk2(ph, nkh, khL, dhL);
  mk2(pw, nkw, kwL, dwL);

  const int a_row_in = lane & 15;
  const int a_colb   = (lane >> 4) << 3;
  const int b_krow   = lane & 15;
  const int b_coln   = (lane >> 4) << 3;

  float acc[4][4][4];
  #pragma unroll
  for (int mi = 0; mi < 4; mi++)
    #pragma unroll
    for (int ni = 0; ni < 4; ni++)
      #pragma unroll
      for (int q = 0; q < 4; q++) acc[mi][ni][q] = 0.f;

  for (int ia = 0; ia < nkd; ia++)
  for (int ib = 0; ib < nkh; ib++)
  for (int ic = 0; ic < nkw; ic++){
    const int tap = (kdL[ia]*3 + khL[ib])*3 + kwL[ic];
    __syncthreads();
    if (tid < BM){
      int id = md + ddL[ia], ih = mh + dhL[ib], iw = mw + dwL[ic];
      bool v = (unsigned)id < 8u && (unsigned)ih < 8u && (unsigned)iw < 8u;
      offs[tid] = v ? ((id*8 + ih)*8 + iw) * 128 : -1;
    }

    for (int c0 = 0; c0 < 128; c0 += BK){
      __syncthreads();
      #pragma unroll
      for (int rep = 0; rep < 2; rep++){
        int idx = rep * 256 + tid;
        int row = idx >> 2, cg = idx & 3;
        int o = offs[row];
        uint4 h = make_uint4(0,0,0,0), l = make_uint4(0,0,0,0);
        if (o >= 0){
          h = *(const uint4*)(xhi + o + c0 + cg*8);
          l = *(const uint4*)(xlo + o + c0 + cg*8);
        }
        *(uint4*)&Ahi[row*AP + cg*8] = h;
        *(uint4*)&Alo[row*AP + cg*8] = l;
      }
      #pragma unroll
      for (int rep = 0; rep < 2; rep++){
        int idx = rep * 256 + tid;
        int kr = idx >> 4, cg = idx & 15;
        int src = tap*16384 + (c0 + kr)*128 + cg*8;
        *(uint4*)&Bhi[kr*BP + cg*8] = *(const uint4*)(whi + src);
        *(uint4*)&Blo[kr*BP + cg*8] = *(const uint4*)(wlo + src);
      }
      __syncthreads();

      #pragma unroll
      for (int k16 = 0; k16 < 2; k16++){
        uint32_t af[4][4], bh[2][4], bl[2][4];
        #pragma unroll
        for (int mi = 0; mi < 4; mi++){
          int r = warp_m*64 + mi*16 + a_row_in;
          ldsm4(af[mi], &Ahi[r*AP + k16*16 + a_colb]);
        }
        #pragma unroll
        for (int nj = 0; nj < 2; nj++){
          int kr = k16*16 + b_krow;
          int nc = warp_n*32 + nj*16 + b_coln;
          ldsm4t(bh[nj], &Bhi[kr*BP + nc]);
          ldsm4t(bl[nj], &Blo[kr*BP + nc]);
        }
        #pragma unroll
        for (int mi = 0; mi < 4; mi++)
          #pragma unroll
          for (int ni = 0; ni < 4; ni++){
            const uint32_t* h = &bh[ni>>1][(ni&1)*2];
            const uint32_t* L = &bl[ni>>1][(ni&1)*2];
            mma_bf16(acc[mi][ni], af[mi], h[0], h[1]);
            mma_bf16(acc[mi][ni], af[mi], L[0], L[1]);
          }
        #pragma unroll
        for (int mi = 0; mi < 4; mi++){
          int r = warp_m*64 + mi*16 + a_row_in;
          ldsm4(af[mi], &Alo[r*AP + k16*16 + a_colb]);
        }
        #pragma unroll
        for (int mi = 0; mi < 4; mi++)
          #pragma unroll
          for (int ni = 0; ni < 4; ni++){
            const uint32_t* h = &bh[ni>>1][(ni&1)*2];
            mma_bf16(acc[mi][ni], af[mi], h[0], h[1]);
          }
      }
    }
  }

  #pragma unroll
  for (int mi = 0; mi < 4; mi++){
    int lv0 = warp_m*64 + mi*16 + (lane >> 2);
    #pragma unroll
    for (int ni = 0; ni < 4; ni++){
      int col = warp_n*32 + ni*8 + (lane & 3)*2;
      float2 bb = *(const float2*)&bias[col];
      #pragma unroll
      for (int h = 0; h < 2; h++){
        int rv = vbase + lv0 + h*8;
        int vw = rv & 7; int t = rv >> 3; int vh = t & 7; int vd = t >> 3;
        int od = 2*vd + pd, oh = 2*vh + ph, ow = 2*vw + pw;
        size_t oo = (size_t)((od*16 + oh)*16 + ow) * 128 + col;
        unsigned hw, lw;
        split2(acc[mi][ni][2*h+0] + bb.x, acc[mi][ni][2*h+1] + bb.y, hw, lw);
        *(unsigned*)&ohi[oo] = hw;
        *(unsigned*)&olo[oo] = lw;
      }
    }
  }
}

// ---------------------------------------------------------------------------
// Fused L5+L6 path tables (R6-proven).
// ---------------------------------------------------------------------------
__device__ __constant__ int c_np[2][3]   = {{2,2,0},{1,3,1}};
__device__ __constant__ int c_k1[2][3][3] = {{{1,0,0},{2,1,0},{0,0,0}},
                                             {{0,0,0},{2,1,0},{2,0,0}}};
__device__ __constant__ int c_k2[2][3][3] = {{{0,1,0},{1,2,0},{0,0,0}},
                                             {{0,0,0},{0,1,2},{2,0,0}}};

// P1 (R10-proven, verbatim): Wp + WpT
__global__ __launch_bounds__(256) void p1_wp(
    const float* __restrict__ w2, const float* __restrict__ w20)
{
  int t = blockIdx.x * 256 + threadIdx.x;
  if (t >= 27*27*128) return;
  int ci = t & 127;
  int k2l = (t >> 7) % 27;
  int k1l = t / (27*128);
  const float* a = w2 + ((size_t)k1l*128 + ci) * 64;
  const float* b = w20 + (size_t)k2l * 64 * 3;
  float s0 = 0.f, s1 = 0.f, s2 = 0.f;
  #pragma unroll 4
  for (int cm = 0; cm < 64; cm++){
    float av = a[cm];
    s0 = fmaf(av, b[cm*3+0], s0);
    s1 = fmaf(av, b[cm*3+1], s1);
    s2 = fmaf(av, b[cm*3+2], s2);
  }
  float* o = g_Wp + (size_t)t * 3;
  o[0] = s0; o[1] = s1; o[2] = s2;
  size_t kk = (size_t)k1l*27 + k2l;
  g_WpT[kk*384 + 0*128 + ci] = s0;
  g_WpT[kk*384 + 1*128 + ci] = s1;
  g_WpT[kk*384 + 2*128 + ci] = s2;
}

// P2 (R7-proven, verbatim): Weff[pz][dxl][co][ci]
__global__ __launch_bounds__(256) void p2_weff()
{
  int t = blockIdx.x * 256 + threadIdx.x;
  if (t >= 8*27*128) return;
  int ci = t & 127;
  int dxl = (t >> 7) % 27;
  int pz = t / (27*128);
  int jd = dxl / 9, jh = (dxl / 3) % 3, jw = dxl % 3;
  int pd = (pz >> 2) & 1, ph = (pz >> 1) & 1, pw = pz & 1;
  int nd = c_np[pd][jd], nh = c_np[ph][jh], nw = c_np[pw][jw];
  float s0 = 0.f, s1 = 0.f, s2 = 0.f;
  for (int a = 0; a < nd; a++)
  for (int b = 0; b < nh; b++)
  for (int c = 0; c < nw; c++){
    int k1l = (c_k1[pd][jd][a]*3 + c_k1[ph][jh][b])*3 + c_k1[pw][jw][c];
    int k2l = (c_k2[pd][jd][a]*3 + c_k2[ph][jh][b])*3 + c_k2[pw][jw][c];
    const float* wp = g_Wp + ((size_t)(k1l*27 + k2l)*128 + ci)*3;
    s0 += wp[0]; s1 += wp[1]; s2 += wp[2];
  }
  float* o = g_Weff + (size_t)(pz*27 + dxl) * 3 * 128;
  o[0*128 + ci] = s0;
  o[1*128 + ci] = s1;
  o[2*128 + ci] = s2;
}

// P3 (R6-proven, verbatim)
__global__ void p3_bias(const float* __restrict__ w20,
                        const float* __restrict__ b2,
                        const float* __restrict__ b20)
{
  int tid = threadIdx.x;
  if (tid < 81){
    int k2 = tid / 3, co = tid % 3;
    float s = 0.f;
    for (int cm = 0; cm < 64; cm++)
      s = fmaf(w20[(k2*64+cm)*3+co], b2[cm], s);
    g_bconv[tid] = s;
  }
  __syncthreads();
  if (tid < 3){
    float s = b20[tid];
    for (int k2 = 0; k2 < 27; k2++) s += g_bconv[k2*3+tid];
    g_btot[tid] = s;
  }
}

// ---------------------------------------------------------------------------
// Fused L5+L6 consumer (R14-proven, verbatim).
// ---------------------------------------------------------------------------
__global__ __launch_bounds__(256) void fused56b(
    const float* __restrict__ x, float* __restrict__ out)
{
  const int wid  = threadIdx.x >> 5;
  const int lane = threadIdx.x & 31;
  const int pz = blockIdx.z;
  const int pd = (pz >> 2) & 1, ph = (pz >> 1) & 1, pw = pz & 1;
  const int wg  = blockIdx.x * 8 + wid;
  const int seg = wg & 3;
  const int row = wg >> 2;
  const int rd = row >> 5, rh = row & 31;
  const int rw0 = seg * 8;
  const int l2 = 2 * lane;
  const int nw = 2 + pw;

  ull acc[8][3];
  #pragma unroll
  for (int r = 0; r < 8; r++)
    #pragma unroll
    for (int c = 0; c < 3; c++) acc[r][c] = 0ull;

  for (int jd = 0; jd <= 1 + pd; jd++){
    int id = rd + jd - 1;
    if ((unsigned)id >= 32u) continue;
    for (int jh = 0; jh <= 1 + ph; jh++){
      int ih = rh + jh - 1;
      if ((unsigned)ih >= 32u) continue;
      const float* xrow = x + (size_t)((id*32 + ih)*32) * 128;

      ull W[3][6];
      #pragma unroll
      for (int jw = 0; jw < 3; jw++){
        if (jw < nw){
          const float* Wt = g_Weff + (size_t)(pz*27 + jd*9 + jh*3 + jw) * 384;
          W[jw][0] = *(const ull*)(Wt +   0 + l2);
          W[jw][1] = *(const ull*)(Wt +  64 + l2);
          W[jw][2] = *(const ull*)(Wt + 128 + l2);
          W[jw][3] = *(const ull*)(Wt + 192 + l2);
          W[jw][4] = *(const ull*)(Wt + 256 + l2);
          W[jw][5] = *(const ull*)(Wt + 320 + l2);
        }
      }

      #pragma unroll
      for (int t = 0; t < 10; t++){
        int iw = rw0 - 1 + t;
        if ((unsigned)iw >= 32u) continue;
        const float* xp = xrow + iw * 128;
        ull x0 = *(const ull*)(xp + l2);
        ull x1 = *(const ull*)(xp + 64 + l2);
        #pragma unroll
        for (int jw = 0; jw < 3; jw++){
          int r = t - jw;
          if (jw < nw && (unsigned)r < 8u){
            ffma2(acc[r][0], x0, W[jw][0]); ffma2(acc[r][0], x1, W[jw][1]);
            ffma2(acc[r][1], x0, W[jw][2]); ffma2(acc[r][1], x1, W[jw][3]);
            ffma2(acc[r][2], x0, W[jw][4]); ffma2(acc[r][2], x1, W[jw][5]);
          }
        }
      }
    }
  }

  const float bt0 = g_btot[0], bt1 = g_btot[1], bt2 = g_btot[2];
  const int od = 2*rd + pd, oh = 2*rh + ph;

  #pragma unroll
  for (int r = 0; r < 8; r++){
    float s0, s1, s2;
    {
      float a, b;
      unpack2(acc[r][0], a, b); s0 = a + b;
      unpack2(acc[r][1], a, b); s1 = a + b;
      unpack2(acc[r][2], a, b); s2 = a + b;
    }
    #pragma unroll
    for (int sh = 16; sh > 0; sh >>= 1){
      s0 += __shfl_xor_sync(0xffffffffu, s0, sh);
      s1 += __shfl_xor_sync(0xffffffffu, s1, sh);
      s2 += __shfl_xor_sync(0xffffffffu, s2, sh);
    }
    if (lane == 0){
      int ow = 2*(rw0 + r) + pw;
      float* op = out + (size_t)((od*64 + oh)*64 + ow) * 3;
      op[0] = s0 + bt0;
      op[1] = s1 + bt1;
      op[2] = s2 + bt2;
    }
  }
}

// ---------------------------------------------------------------------------
// NEW (round 16): fix56p — R8-proven fix56w math with the k2d loop parallelized
// over blockIdx.y (3 partials per voxel; bias partial EXCLUDES b20).
// Partials land in g_part (dead after l2_finish). fix_combine sums them.
// ---------------------------------------------------------------------------
__global__ __launch_bounds__(256) void fix56p(
    const float* __restrict__ x, float* __restrict__ fixP)
{
  const int gw = blockIdx.x * 8 + (threadIdx.x >> 5);
  const int lane = threadIdx.x & 31;
  const int l2 = 2 * lane;
  const int k2d = blockIdx.y;

  int plane = gw / 4096, r = gw % 4096;
  int a = r / 64, b = r % 64;
  int od, oh, ow;
  if      (plane == 0){ od = 0;  oh = a; ow = b; }
  else if (plane == 1){ od = 63; oh = a; ow = b; }
  else if (plane == 2){ oh = 0;  od = a; ow = b; if (od==0||od==63) return; }
  else if (plane == 3){ oh = 63; od = a; ow = b; if (od==0||od==63) return; }
  else if (plane == 4){ ow = 0;  od = a; oh = b; if (od==0||od==63||oh==0||oh==63) return; }
  else               { ow = 63; od = a; oh = b; if (od==0||od==63||oh==0||oh==63) return; }

  ull a0 = 0ull, a1 = 0ull, a2 = 0ull;
  float bias0 = 0.f, bias1 = 0.f, bias2 = 0.f;

  int md = od + k2d - 1;
  if ((unsigned)md < 64u){
    int pmd = md & 1, rd = (md - pmd) >> 1;
    int n_d = pmd ? 1 : 2;
    int k1d[2], ixd[2];
    if (pmd){ k1d[0] = 1; ixd[0] = rd; }
    else    { k1d[0] = 0; ixd[0] = rd - 1; k1d[1] = 2; ixd[1] = rd; }
    for (int k2h = 0; k2h < 3; k2h++){
      int mh = oh + k2h - 1; if ((unsigned)mh >= 64u) continue;
      int pmh = mh & 1, rh = (mh - pmh) >> 1;
      int n_h = pmh ? 1 : 2;
      int k1h[2], ixh[2];
      if (pmh){ k1h[0] = 1; ixh[0] = rh; }
      else    { k1h[0] = 0; ixh[0] = rh - 1; k1h[1] = 2; ixh[1] = rh; }
      for (int k2w = 0; k2w < 3; k2w++){
        int mw = ow + k2w - 1; if ((unsigned)mw >= 64u) continue;
        int pmw = mw & 1, rw = (mw - pmw) >> 1;
        int n_w = pmw ? 1 : 2;
        int k1w[2], ixw[2];
        if (pmw){ k1w[0] = 1; ixw[0] = rw; }
        else    { k1w[0] = 0; ixw[0] = rw - 1; k1w[1] = 2; ixw[1] = rw; }

        int k2l = (k2d*3 + k2h)*3 + k2w;
        bias0 += g_bconv[k2l*3+0];
        bias1 += g_bconv[k2l*3+1];
        bias2 += g_bconv[k2l*3+2];

        for (int ia = 0; ia < n_d; ia++){
          if ((unsigned)ixd[ia] >= 32u) continue;
          for (int ib = 0; ib < n_h; ib++){
            if ((unsigned)ixh[ib] >= 32u) continue;
            for (int ic = 0; ic < n_w; ic++){
              if ((unsigned)ixw[ic] >= 32u) continue;
              int k1l = (k1d[ia]*3 + k1h[ib])*3 + k1w[ic];
              const float* wt = g_WpT + (size_t)(k1l*27 + k2l)*384;
              const float* xp = x + (size_t)((ixd[ia]*32 + ixh[ib])*32 + ixw[ic])*128;
              ull x0 = *(const ull*)(xp + l2);
              ull x1 = *(const ull*)(xp + 64 + l2);
              ffma2(a0, x0, *(const ull*)(wt +   0 + l2));
              ffma2(a0, x1, *(const ull*)(wt +  64 + l2));
              ffma2(a1, x0, *(const ull*)(wt + 128 + l2));
              ffma2(a1, x1, *(const ull*)(wt + 192 + l2));
              ffma2(a2, x0, *(const ull*)(wt + 256 + l2));
              ffma2(a2, x1, *(const ull*)(wt + 320 + l2));
            }
          }
        }
      }
    }
  }

  float s0, s1, s2;
  {
    float u, v;
    unpack2(a0, u, v); s0 = u + v;
    unpack2(a1, u, v); s1 = u + v;
    unpack2(a2, u, v); s2 = u + v;
  }
  #pragma unroll
  for (int sh = 16; sh > 0; sh >>= 1){
    s0 += __shfl_xor_sync(0xffffffffu, s0, sh);
    s1 += __shfl_xor_sync(0xffffffffu, s1, sh);
    s2 += __shfl_xor_sync(0xffffffffu, s2, sh);
  }
  if (lane == 0){
    float4* p = (float4*)fixP + (size_t)k2d * 24576 + gw;
    *p = make_float4(s0 + bias0, s1 + bias1, s2 + bias2, 0.f);
  }
}

// Combine: out = b20 + sum over 3 k2d partials, same voxel/dedup mapping.
__global__ __launch_bounds__(256) void fix_combine(
    const float* __restrict__ fixP, const float* __restrict__ b20,
    float* __restrict__ out)
{
  int gw = blockIdx.x * 256 + threadIdx.x;
  if (gw >= 24576) return;
  int plane = gw / 4096, r = gw % 4096;
  int a = r / 64, b = r % 64;
  int od, oh, ow;
  if      (plane == 0){ od = 0;  oh = a; ow = b; }
  else if (plane == 1){ od = 63; oh = a; ow = b; }
  else if (plane == 2){ oh = 0;  od = a; ow = b; if (od==0||od==63) return; }
  else if (plane == 3){ oh = 63; od = a; ow = b; if (od==0||od==63) return; }
  else if (plane == 4){ ow = 0;  od = a; oh = b; if (od==0||od==63||oh==0||oh==63) return; }
  else               { ow = 63; od = a; oh = b; if (od==0||od==63||oh==0||oh==63) return; }

  const float4* P = (const float4*)fixP;
  float4 p0 = P[0*24576 + gw];
  float4 p1 = P[1*24576 + gw];
  float4 p2 = P[2*24576 + gw];
  float* op = out + (size_t)((od*64 + oh)*64 + ow) * 3;
  op[0] = __ldg(&b20[0]) + p0.x + p1.x + p2.x;
  op[1] = __ldg(&b20[1]) + p0.y + p1.y + p2.y;
  op[2] = __ldg(&b20[2]) + p0.z + p1.z + p2.z;
}

// ---------------------------------------------------------------------------
// kernel_launch
// ---------------------------------------------------------------------------
extern "C" void kernel_launch(void* const* d_in, const int* in_sizes, int n_in,
                              void* d_out, int out_size)
{
  (void)in_sizes; (void)n_in; (void)out_size;
  const float* x   = (const float*)d_in[0];
  const float* w0  = (const float*)d_in[1];
  const float* b0  = (const float*)d_in[2];
  const float* w00 = (const float*)d_in[3];
  const float* b00 = (const float*)d_in[4];
  const float* w1  = (const float*)d_in[5];
  const float* b1  = (const float*)d_in[6];
  const float* w10 = (const float*)d_in[7];
  const float* b10 = (const float*)d_in[8];
  const float* w2  = (const float*)d_in[9];
  const float* b2  = (const float*)d_in[10];
  const float* w20 = (const float*)d_in[11];
  const float* b20 = (const float*)d_in[12];
  float* out = (float*)d_out;

  float *bufB = nullptr, *part = nullptr;
  __nv_bfloat16 *xhA, *xlA, *xhB, *xlB;
  __nv_bfloat16 *whi, *wlo, *whiB, *wloB, *whiC, *wloC, *whiD, *wloD;
  cudaGetSymbolAddress((void**)&bufB, g_bufB);
  cudaGetSymbolAddress((void**)&part, g_part);
  cudaGetSymbolAddress((void**)&xhA, g_xhiA);
  cudaGetSymbolAddress((void**)&xlA, g_xloA);
  cudaGetSymbolAddress((void**)&xhB, g_xhiB);
  cudaGetSymbolAddress((void**)&xlB, g_xloB);
  cudaGetSymbolAddress((void**)&whi, g_whi);
  cudaGetSymbolAddress((void**)&wlo, g_wlo);
  cudaGetSymbolAddress((void**)&whiB, g_whiB);
  cudaGetSymbolAddress((void**)&wloB, g_wloB);
  cudaGetSymbolAddress((void**)&whiC, g_whiC);
  cudaGetSymbolAddress((void**)&wloC, g_wloC);
  cudaGetSymbolAddress((void**)&whiD, g_whiD);
  cudaGetSymbolAddress((void**)&wloD, g_wloD);

  static bool attr_set = false;
  const int PIPE_SMEM = 2*37888 + 27*128*4;   // 89600 B
  if (!attr_set){
    cudaFuncSetAttribute(mma_s1r_pipe,
                         cudaFuncAttributeMaxDynamicSharedMemorySize, PIPE_SMEM);
    attr_set = true;
  }

  // (1) Wp + WpT precompute
  p1_wp<<<(27*27*128 + 255)/256, 256>>>(w2, w20);
  // (2) split all 4 conv weights in one launch
  {
    dim3 g(1728, 4, 1);
    split_w4_kernel<<<g, 256>>>(w0, w00, w1, w10,
                                whiD, wloD, whiC, wloC,
                                whiB, wloB, whi, wlo);
  }
  // (3) split network input x -> pair A
  split_x_kernel<<<64, 256>>>(x, xhA, xlA, 65536/4);
  // (4) L1 on HMMA: A -> pair B
  {
    dim3 g(4, 1, 8);
    mma_s2_d8<<<g, 256>>>(xhA, xlA, whiD, wloD, b0, xhB, xlB);
  }
  // (5) L2 on HMMA, 7-way tap split: B -> partials
  {
    dim3 g(32, 7, 1);
    mma_s1_part<<<g, 256>>>(xhB, xlB, whiC, wloC, part);
  }
  // (6) L2 finish -> pair A
  l2_finish<<<512, 256>>>(part, b00, xhA, xlA);
  // (7) L3 on HMMA: A -> pair B
  {
    dim3 g(32, 1, 8);
    mma_s2<<<g, 256>>>(xhA, xlA, whiB, wloB, b1, xhB, xlB);
  }
  // (8) L4 on pipelined HMMA: B -> bufB (fp32)
  mma_s1r_pipe<<<256, 256, PIPE_SMEM>>>(xhB, xlB, whi, wlo, b10, bufB);
  // (9-10) fused-weight precompute for L5+L6
  p2_weff<<<(8*27*128 + 255)/256, 256>>>();
  p3_bias<<<1, 128>>>(w20, b2, b20);
  // (11) Fused L5+L6 (interior)
  {
    dim3 g(512, 1, 8);
    fused56b<<<g, 256>>>(bufB, out);
  }
  // (12) Boundary fix partials, k2d-parallel  [NEW]
  {
    dim3 g(3072, 3, 1);
    fix56p<<<g, 256>>>(bufB, part);
  }
  // (13) Combine boundary partials  [NEW]
  fix_combine<<<96, 256>>>(part, b20, out);
}

// round 17
// speedup vs baseline: 1.5174x; 1.0557x over previous
#include <cuda_runtime.h>
#include <cuda_bf16.h>
#include <cstdint>

// ---------------------------------------------------------------------------
// Static scratch (no allocation allowed)
// ---------------------------------------------------------------------------
__device__ float g_bufB[4194304];
__device__ float g_part[4194304];   // L1 partials (8x512K) / L2 partials (7x512K) / fix partials
__device__ float g_Wp[279936];
__device__ float g_WpT[279936];
__device__ float g_Weff[110592];
__device__ float g_bconv[81];
__device__ float g_btot[3];
__device__ __nv_bfloat16 g_xhiA[4194304];   // pair A
__device__ __nv_bfloat16 g_xloA[4194304];
__device__ __nv_bfloat16 g_xhiB[4194304];   // pair B
__device__ __nv_bfloat16 g_xloB[4194304];
__device__ __nv_bfloat16 g_whi[442368];    // L4 weights (w10)
__device__ __nv_bfloat16 g_wlo[442368];
__device__ __nv_bfloat16 g_whiB[442368];   // L3 weights (w1)
__device__ __nv_bfloat16 g_wloB[442368];
__device__ __nv_bfloat16 g_whiC[442368];   // L2 weights (w00)
__device__ __nv_bfloat16 g_wloC[442368];
__device__ __nv_bfloat16 g_whiD[442368];   // L1 weights (w0)
__device__ __nv_bfloat16 g_wloD[442368];

typedef unsigned long long ull;

// ---------------------------------------------------------------------------
// f32x2 packed helpers
// ---------------------------------------------------------------------------
__device__ __forceinline__ ull pack2(float x, float y){
  ull r; asm("mov.b64 %0, {%1, %2};" : "=l"(r) : "f"(x), "f"(y)); return r;
}
__device__ __forceinline__ void unpack2(ull v, float& x, float& y){
  asm("mov.b64 {%0, %1}, %2;" : "=f"(x), "=f"(y) : "l"(v));
}
__device__ __forceinline__ void ffma2(ull& acc, ull a, ull b){
  asm("fma.rn.f32x2 %0, %1, %2, %0;" : "+l"(acc) : "l"(a), "l"(b));
}

// pack two floats into hi/lo bf16-pair words (matches split_x arithmetic)
__device__ __forceinline__ void split2(float vx, float vy,
                                       unsigned& hw, unsigned& lw){
  __nv_bfloat16 h0 = __float2bfloat16_rn(vx);
  __nv_bfloat16 h1 = __float2bfloat16_rn(vy);
  __nv_bfloat16 l0 = __float2bfloat16_rn(vx - __bfloat162float(h0));
  __nv_bfloat16 l1 = __float2bfloat16_rn(vy - __bfloat162float(h1));
  hw = (unsigned)*(unsigned short*)&h0 | ((unsigned)*(unsigned short*)&h1 << 16);
  lw = (unsigned)*(unsigned short*)&l0 | ((unsigned)*(unsigned short*)&l1 << 16);
}

// ---------------------------------------------------------------------------
// mma.sync / ldmatrix / cp.async helpers (baseline PTX, legal on sm_103)
// ---------------------------------------------------------------------------
__device__ __forceinline__ void ldsm4(uint32_t* r, const void* p){
  uint32_t a = (uint32_t)__cvta_generic_to_shared(p);
  asm volatile("ldmatrix.sync.aligned.m8n8.x4.shared.b16 {%0,%1,%2,%3}, [%4];"
    : "=r"(r[0]), "=r"(r[1]), "=r"(r[2]), "=r"(r[3]) : "r"(a));
}
__device__ __forceinline__ void ldsm4t(uint32_t* r, const void* p){
  uint32_t a = (uint32_t)__cvta_generic_to_shared(p);
  asm volatile("ldmatrix.sync.aligned.m8n8.x4.trans.shared.b16 {%0,%1,%2,%3}, [%4];"
    : "=r"(r[0]), "=r"(r[1]), "=r"(r[2]), "=r"(r[3]) : "r"(a));
}
__device__ __forceinline__ void mma_bf16(float* c, const uint32_t* a,
                                         uint32_t b0, uint32_t b1){
  asm volatile("mma.sync.aligned.m16n8k16.row.col.f32.bf16.bf16.f32 "
    "{%0,%1,%2,%3}, {%4,%5,%6,%7}, {%8,%9}, {%0,%1,%2,%3};"
    : "+f"(c[0]), "+f"(c[1]), "+f"(c[2]), "+f"(c[3])
    : "r"(a[0]), "r"(a[1]), "r"(a[2]), "r"(a[3]), "r"(b0), "r"(b1));
}
__device__ __forceinline__ void cpasync16(void* dst, const void* src, bool pred){
  uint32_t d = (uint32_t)__cvta_generic_to_shared(dst);
  int sz = pred ? 16 : 0;
  asm volatile("cp.async.cg.shared.global [%0], [%1], 16, %2;"
               :: "r"(d), "l"(src), "r"(sz));
}
#define CP_COMMIT() asm volatile("cp.async.commit_group;")
#define CP_WAIT1()  asm volatile("cp.async.wait_group 1;")
#define CP_WAIT0()  asm volatile("cp.async.wait_group 0;")

// ---------------------------------------------------------------------------
// bf16 hi/lo split pre-passes
// ---------------------------------------------------------------------------
__global__ __launch_bounds__(256) void split_x_kernel(
    const float* __restrict__ x, __nv_bfloat16* __restrict__ hi,
    __nv_bfloat16* __restrict__ lo, int n4)
{
  int i = blockIdx.x * 256 + threadIdx.x;
  if (i >= n4) return;
  float4 v = ((const float4*)x)[i];
  __nv_bfloat16 h0 = __float2bfloat16_rn(v.x);
  __nv_bfloat16 h1 = __float2bfloat16_rn(v.y);
  __nv_bfloat16 h2 = __float2bfloat16_rn(v.z);
  __nv_bfloat16 h3 = __float2bfloat16_rn(v.w);
  __nv_bfloat16 l0 = __float2bfloat16_rn(v.x - __bfloat162float(h0));
  __nv_bfloat16 l1 = __float2bfloat16_rn(v.y - __bfloat162float(h1));
  __nv_bfloat16 l2 = __float2bfloat16_rn(v.z - __bfloat162float(h2));
  __nv_bfloat16 l3 = __float2bfloat16_rn(v.w - __bfloat162float(h3));
  ushort4 hv = make_ushort4(*(unsigned short*)&h0, *(unsigned short*)&h1,
                            *(unsigned short*)&h2, *(unsigned short*)&h3);
  ushort4 lv = make_ushort4(*(unsigned short*)&l0, *(unsigned short*)&l1,
                            *(unsigned short*)&l2, *(unsigned short*)&l3);
  ((ushort4*)hi)[i] = hv;
  ((ushort4*)lo)[i] = lv;
}

// R16-proven: split all 4 weight tensors in one launch (blockIdx.y selects)
__global__ __launch_bounds__(256) void split_w4_kernel(
    const float* __restrict__ wa, const float* __restrict__ wb,
    const float* __restrict__ wc, const float* __restrict__ wd,
    __nv_bfloat16* __restrict__ ha, __nv_bfloat16* __restrict__ la,
    __nv_bfloat16* __restrict__ hb, __nv_bfloat16* __restrict__ lb,
    __nv_bfloat16* __restrict__ hc, __nv_bfloat16* __restrict__ lc,
    __nv_bfloat16* __restrict__ hd, __nv_bfloat16* __restrict__ ld)
{
  int i = blockIdx.x * 256 + threadIdx.x;
  if (i >= 27*128*128) return;
  const float* w; __nv_bfloat16 *hi, *lo;
  switch (blockIdx.y){
    case 0: w = wa; hi = ha; lo = la; break;
    case 1: w = wb; hi = hb; lo = lb; break;
    case 2: w = wc; hi = hc; lo = lc; break;
    default: w = wd; hi = hd; lo = ld; break;
  }
  float v = w[i];
  __nv_bfloat16 h = __float2bfloat16_rn(v);
  hi[i] = h;
  lo[i] = __float2bfloat16_rn(v - __bfloat162float(h));
}

// ---------------------------------------------------------------------------
// NEW (round 17): L1 on HMMA with 8-way (k-chunk x tap-half) sharding.
// mma core identical to R15-proven mma_s2_d8; raw fp32 partials (no bias)
// stored at scattered output offsets into part slice blockIdx.y.
// ---------------------------------------------------------------------------
__global__ __launch_bounds__(256, 2) void mma_s2d8_part(
    const __nv_bfloat16* __restrict__ xhi, const __nv_bfloat16* __restrict__ xlo,
    const __nv_bfloat16* __restrict__ whi, const __nv_bfloat16* __restrict__ wlo,
    float* __restrict__ part)
{
  constexpr int BM = 128;
  constexpr int AP = 40;
  constexpr int BP = 136;

  __shared__ __align__(16) unsigned short Ahi[BM*AP];
  __shared__ __align__(16) unsigned short Alo[BM*AP];
  __shared__ __align__(16) unsigned short Bhi[32*BP];
  __shared__ __align__(16) unsigned short Blo[32*BP];
  __shared__ int offs[BM];

  const int tid  = threadIdx.x;
  const int lane = tid & 31;
  const int wid  = tid >> 5;
  const int warp_m = wid >> 2;
  const int warp_n = wid & 3;
  const int vbase = blockIdx.x * BM;
  const int pz = blockIdx.z;
  const int pd = (pz >> 2) & 1, ph = (pz >> 1) & 1, pw = pz & 1;
  const int chunk = blockIdx.y >> 1;
  const int half  = blockIdx.y & 1;
  const int c0 = chunk * 32;
  float* outp = part + (size_t)blockIdx.y * 524288;

  int md, mh, mw;
  { int rv = vbase + (tid & 127);
    mw = rv & 7; int t = rv >> 3; mh = t & 7; md = t >> 3; }

  // stride-2 tap lists (R1-proven mk2 mapping; delta != k-1, so both carried)
  int nkd, kdL[2], ddL[2];
  int nkh, khL[2], dhL[2];
  int nkw, kwL[2], dwL[2];
  auto mk2 = [&](int p, int& n, int* kL, int* dL){
    if (p == 0){ n = 2; kL[0]=0; kL[1]=2; dL[0]=-1; dL[1]=0; }
    else       { n = 1; kL[0]=1; dL[0]=0; }
  };
  mk2(pd, nkd, kdL, ddL);
  mk2(ph, nkh, khL, dhL);
  mk2(pw, nkw, kwL, dwL);

  // enumerate this parity's taps with encoded (tap, dd,dh,dw)
  int enc[8]; int nt = 0;
  for (int ia = 0; ia < nkd; ia++)
  for (int ib = 0; ib < nkh; ib++)
  for (int ic = 0; ic < nkw; ic++){
    int tap = (kdL[ia]*3 + khL[ib])*3 + kwL[ic];
    enc[nt++] = (tap << 6) | ((ddL[ia]+1) << 4) | ((dhL[ib]+1) << 2) | (dwL[ic]+1);
  }
  const int hlen = (nt + 1) >> 1;
  const int tbeg = half * hlen;
  const int tend = min(nt, tbeg + hlen);

  const int a_row_in = lane & 15;
  const int a_colb   = (lane >> 4) << 3;
  const int b_krow   = lane & 15;
  const int b_coln   = (lane >> 4) << 3;

  float acc[4][4][4];
  #pragma unroll
  for (int mi = 0; mi < 4; mi++)
    #pragma unroll
    for (int ni = 0; ni < 4; ni++)
      #pragma unroll
      for (int q = 0; q < 4; q++) acc[mi][ni][q] = 0.f;

  for (int ti = tbeg; ti < tend; ti++){
    const int e = enc[ti];
    const int tap = e >> 6;
    const int dd = ((e >> 4) & 3) - 1;
    const int dh = ((e >> 2) & 3) - 1;
    const int dw = (e & 3) - 1;

    __syncthreads();
    if (tid < BM){
      int id = md + dd, ih = mh + dh, iw = mw + dw;
      bool v = (unsigned)id < 8u && (unsigned)ih < 8u && (unsigned)iw < 8u;
      offs[tid] = v ? ((id*8 + ih)*8 + iw) * 128 : -1;
    }
    __syncthreads();

    // A fill (gather, hi+lo) for this single k-chunk
    #pragma unroll
    for (int rep = 0; rep < 2; rep++){
      int idx = rep * 256 + tid;
      int row = idx >> 2, cg = idx & 3;
      int o = offs[row];
      uint4 h = make_uint4(0,0,0,0), l = make_uint4(0,0,0,0);
      if (o >= 0){
        h = *(const uint4*)(xhi + o + c0 + cg*8);
        l = *(const uint4*)(xlo + o + c0 + cg*8);
      }
      *(uint4*)&Ahi[row*AP + cg*8] = h;
      *(uint4*)&Alo[row*AP + cg*8] = l;
    }
    // B fill
    #pragma unroll
    for (int rep = 0; rep < 2; rep++){
      int idx = rep * 256 + tid;
      int kr = idx >> 4, cg = idx & 15;
      int src = tap*16384 + (c0 + kr)*128 + cg*8;
      *(uint4*)&Bhi[kr*BP + cg*8] = *(const uint4*)(whi + src);
      *(uint4*)&Blo[kr*BP + cg*8] = *(const uint4*)(wlo + src);
    }
    __syncthreads();

    #pragma unroll
    for (int k16 = 0; k16 < 2; k16++){
      uint32_t af[4][4], bh[2][4], bl[2][4];
      #pragma unroll
      for (int mi = 0; mi < 4; mi++){
        int r = warp_m*64 + mi*16 + a_row_in;
        ldsm4(af[mi], &Ahi[r*AP + k16*16 + a_colb]);
      }
      #pragma unroll
      for (int nj = 0; nj < 2; nj++){
        int kr = k16*16 + b_krow;
        int nc = warp_n*32 + nj*16 + b_coln;
        ldsm4t(bh[nj], &Bhi[kr*BP + nc]);
        ldsm4t(bl[nj], &Blo[kr*BP + nc]);
      }
      #pragma unroll
      for (int mi = 0; mi < 4; mi++)
        #pragma unroll
        for (int ni = 0; ni < 4; ni++){
          const uint32_t* h = &bh[ni>>1][(ni&1)*2];
          const uint32_t* L = &bl[ni>>1][(ni&1)*2];
          mma_bf16(acc[mi][ni], af[mi], h[0], h[1]);
          mma_bf16(acc[mi][ni], af[mi], L[0], L[1]);
        }
      #pragma unroll
      for (int mi = 0; mi < 4; mi++){
        int r = warp_m*64 + mi*16 + a_row_in;
        ldsm4(af[mi], &Alo[r*AP + k16*16 + a_colb]);
      }
      #pragma unroll
      for (int mi = 0; mi < 4; mi++)
        #pragma unroll
        for (int ni = 0; ni < 4; ni++){
          const uint32_t* h = &bh[ni>>1][(ni&1)*2];
          mma_bf16(acc[mi][ni], af[mi], h[0], h[1]);
        }
    }
  }

  // raw partial store at scattered output offsets (R15 epilogue mapping, no bias)
  #pragma unroll
  for (int mi = 0; mi < 4; mi++){
    int lv0 = warp_m*64 + mi*16 + (lane >> 2);
    #pragma unroll
    for (int ni = 0; ni < 4; ni++){
      int col = warp_n*32 + ni*8 + (lane & 3)*2;
      #pragma unroll
      for (int h = 0; h < 2; h++){
        int rv = vbase + lv0 + h*8;
        int vw = rv & 7; int t = rv >> 3; int vh = t & 7; int vd = t >> 3;
        int od = 2*vd + pd, oh = 2*vh + ph, ow = 2*vw + pw;
        size_t oo = (size_t)((od*16 + oh)*16 + ow) * 128 + col;
        *(float2*)&outp[oo] = make_float2(acc[mi][ni][2*h+0], acc[mi][ni][2*h+1]);
      }
    }
  }
}

// L1 finish: sum 8 partial slices + bias (NO relu), write hi/lo splits.
__global__ __launch_bounds__(256) void l1_finish(
    const float* __restrict__ part, const float* __restrict__ bias,
    __nv_bfloat16* __restrict__ xhi, __nv_bfloat16* __restrict__ xlo)
{
  int i = blockIdx.x * 256 + threadIdx.x;
  if (i >= 131072) return;
  float4 s = ((const float4*)part)[i];
  #pragma unroll
  for (int g = 1; g < 8; g++){
    float4 p = ((const float4*)(part + (size_t)g*524288))[i];
    s.x += p.x; s.y += p.y; s.z += p.z; s.w += p.w;
  }
  int col = (i * 4) & 127;
  float4 b = *(const float4*)&bias[col];
  float4 r;
  r.x = s.x + b.x;
  r.y = s.y + b.y;
  r.z = s.z + b.z;
  r.w = s.w + b.w;
  unsigned h0, l0, h1, l1;
  split2(r.x, r.y, h0, l0);
  split2(r.z, r.w, h1, l1);
  ((uint2*)xhi)[i] = make_uint2(h0, h1);
  ((uint2*)xlo)[i] = make_uint2(l0, l1);
}

// ---------------------------------------------------------------------------
// R13-PROVEN core: L2 on HMMA with tap-split partials (7 groups of <=4).
// ---------------------------------------------------------------------------
__global__ __launch_bounds__(256, 2) void mma_s1_part(
    const __nv_bfloat16* __restrict__ xhi, const __nv_bfloat16* __restrict__ xlo,
    const __nv_bfloat16* __restrict__ whi, const __nv_bfloat16* __restrict__ wlo,
    float* __restrict__ part)
{
  constexpr int BM = 128, BK = 32;
  constexpr int AP = 40;
  constexpr int BP = 136;

  __shared__ __align__(16) unsigned short Ahi[BM*AP];
  __shared__ __align__(16) unsigned short Alo[BM*AP];
  __shared__ __align__(16) unsigned short Bhi[BK*BP];
  __shared__ __align__(16) unsigned short Blo[BK*BP];
  __shared__ int offs[BM];

  const int tid  = threadIdx.x;
  const int lane = tid & 31;
  const int wid  = tid >> 5;
  const int warp_m = wid >> 2;
  const int warp_n = wid & 3;
  const int vbase = blockIdx.x * BM;
  const int tap0 = blockIdx.y * 4;
  const int tap1 = min(27, tap0 + 4);
  float* outp = part + (size_t)blockIdx.y * 524288;

  int md, mh, mw;
  { int rv = vbase + (tid & 127);
    mw = rv & 15; int t = rv >> 4; mh = t & 15; md = t >> 4; }

  const int a_row_in = lane & 15;
  const int a_colb   = (lane >> 4) << 3;
  const int b_krow   = lane & 15;
  const int b_coln   = (lane >> 4) << 3;

  float acc[4][4][4];
  #pragma unroll
  for (int mi = 0; mi < 4; mi++)
    #pragma unroll
    for (int ni = 0; ni < 4; ni++)
      #pragma unroll
      for (int q = 0; q < 4; q++) acc[mi][ni][q] = 0.f;

  for (int tap = tap0; tap < tap1; tap++){
    const int kw = tap % 3, kh = (tap / 3) % 3, kd = tap / 9;
    __syncthreads();
    if (tid < BM){
      int id = md + kd - 1, ih = mh + kh - 1, iw = mw + kw - 1;
      bool v = (unsigned)id < 16u && (unsigned)ih < 16u && (unsigned)iw < 16u;
      offs[tid] = v ? ((id*16 + ih)*16 + iw) * 128 : -1;
    }

    for (int c0 = 0; c0 < 128; c0 += BK){
      __syncthreads();
      #pragma unroll
      for (int rep = 0; rep < 2; rep++){
        int idx = rep * 256 + tid;
        int row = idx >> 2, cg = idx & 3;
        int o = offs[row];
        uint4 h = make_uint4(0,0,0,0), l = make_uint4(0,0,0,0);
        if (o >= 0){
          h = *(const uint4*)(xhi + o + c0 + cg*8);
          l = *(const uint4*)(xlo + o + c0 + cg*8);
        }
        *(uint4*)&Ahi[row*AP + cg*8] = h;
        *(uint4*)&Alo[row*AP + cg*8] = l;
      }
      #pragma unroll
      for (int rep = 0; rep < 2; rep++){
        int idx = rep * 256 + tid;
        int kr = idx >> 4, cg = idx & 15;
        int src = tap*16384 + (c0 + kr)*128 + cg*8;
        *(uint4*)&Bhi[kr*BP + cg*8] = *(const uint4*)(whi + src);
        *(uint4*)&Blo[kr*BP + cg*8] = *(const uint4*)(wlo + src);
      }
      __syncthreads();

      #pragma unroll
      for (int k16 = 0; k16 < 2; k16++){
        uint32_t af[4][4], bh[2][4], bl[2][4];
        #pragma unroll
        for (int mi = 0; mi < 4; mi++){
          int r = warp_m*64 + mi*16 + a_row_in;
          ldsm4(af[mi], &Ahi[r*AP + k16*16 + a_colb]);
        }
        #pragma unroll
        for (int nj = 0; nj < 2; nj++){
          int kr = k16*16 + b_krow;
          int nc = warp_n*32 + nj*16 + b_coln;
          ldsm4t(bh[nj], &Bhi[kr*BP + nc]);
          ldsm4t(bl[nj], &Blo[kr*BP + nc]);
        }
        #pragma unroll
        for (int mi = 0; mi < 4; mi++)
          #pragma unroll
          for (int ni = 0; ni < 4; ni++){
            const uint32_t* h = &bh[ni>>1][(ni&1)*2];
            const uint32_t* L = &bl[ni>>1][(ni&1)*2];
            mma_bf16(acc[mi][ni], af[mi], h[0], h[1]);
            mma_bf16(acc[mi][ni], af[mi], L[0], L[1]);
          }
        #pragma unroll
        for (int mi = 0; mi < 4; mi++){
          int r = warp_m*64 + mi*16 + a_row_in;
          ldsm4(af[mi], &Alo[r*AP + k16*16 + a_colb]);
        }
        #pragma unroll
        for (int mi = 0; mi < 4; mi++)
          #pragma unroll
          for (int ni = 0; ni < 4; ni++){
            const uint32_t* h = &bh[ni>>1][(ni&1)*2];
            mma_bf16(acc[mi][ni], af[mi], h[0], h[1]);
          }
      }
    }
  }

  #pragma unroll
  for (int mi = 0; mi < 4; mi++){
    int v0 = vbase + warp_m*64 + mi*16 + (lane >> 2);
    #pragma unroll
    for (int ni = 0; ni < 4; ni++){
      int col = warp_n*32 + ni*8 + (lane & 3)*2;
      *(float2*)&outp[(size_t)v0*128 + col] =
          make_float2(acc[mi][ni][0], acc[mi][ni][1]);
      *(float2*)&outp[(size_t)(v0+8)*128 + col] =
          make_float2(acc[mi][ni][2], acc[mi][ni][3]);
    }
  }
}

// L2 finish (R15-proven, verbatim)
__global__ __launch_bounds__(256) void l2_finish(
    const float* __restrict__ part, const float* __restrict__ bias,
    __nv_bfloat16* __restrict__ xhi, __nv_bfloat16* __restrict__ xlo)
{
  int i = blockIdx.x * 256 + threadIdx.x;
  if (i >= 131072) return;
  float4 s = ((const float4*)part)[i];
  #pragma unroll
  for (int g = 1; g < 7; g++){
    float4 p = ((const float4*)(part + (size_t)g*524288))[i];
    s.x += p.x; s.y += p.y; s.z += p.z; s.w += p.w;
  }
  int col = (i * 4) & 127;
  float4 b = *(const float4*)&bias[col];
  float4 r;
  r.x = fmaxf(s.x + b.x, 0.f);
  r.y = fmaxf(s.y + b.y, 0.f);
  r.z = fmaxf(s.z + b.z, 0.f);
  r.w = fmaxf(s.w + b.w, 0.f);
  unsigned h0, l0, h1, l1;
  split2(r.x, r.y, h0, l0);
  split2(r.z, r.w, h1, l1);
  ((uint2*)xhi)[i] = make_uint2(h0, h1);
  ((uint2*)xlo)[i] = make_uint2(l0, l1);
}

// ---------------------------------------------------------------------------
// R11-PROVEN (verbatim): L4 on HMMA with cp.async 2-stage pipeline.
// ---------------------------------------------------------------------------
__global__ __launch_bounds__(256, 2) void mma_s1r_pipe(
    const __nv_bfloat16* __restrict__ xhi, const __nv_bfloat16* __restrict__ xlo,
    const __nv_bfloat16* __restrict__ whi, const __nv_bfloat16* __restrict__ wlo,
    const float* __restrict__ bias, float* __restrict__ out)
{
  constexpr int AP = 40, BP = 136;
  constexpr int ASZ = 128*AP;
  constexpr int BSZ = 32*BP;
  constexpr int STG = 2*ASZ + 2*BSZ;
  constexpr int NIT = 27*4;

  extern __shared__ __align__(16) unsigned short dsm[];
  int* offsAll = (int*)(dsm + 2*STG);

  const int tid  = threadIdx.x;
  const int lane = tid & 31;
  const int wid  = tid >> 5;
  const int warp_m = wid >> 2;
  const int warp_n = wid & 3;
  const int vbase = blockIdx.x * 128;

  for (int s = tid; s < 27*128; s += 256){
    int tap = s >> 7, row = s & 127;
    int kw = tap % 3, kh = (tap/3)%3, kd = tap/9;
    int rv = vbase + row;
    int mw = rv & 31, mh = (rv>>5)&31, md = rv>>10;
    int id = md + kd - 1, ih = mh + kh - 1, iw = mw + kw - 1;
    bool v = (unsigned)id < 32u && (unsigned)ih < 32u && (unsigned)iw < 32u;
    offsAll[s] = v ? ((id*32 + ih)*32 + iw) * 128 : -1;
  }
  __syncthreads();

  const int a_row_in = lane & 15;
  const int a_colb   = (lane >> 4) << 3;
  const int b_krow   = lane & 15;
  const int b_coln   = (lane >> 4) << 3;

  float acc[4][4][4];
  #pragma unroll
  for (int mi = 0; mi < 4; mi++)
    #pragma unroll
    for (int ni = 0; ni < 4; ni++)
      #pragma unroll
      for (int q = 0; q < 4; q++) acc[mi][ni][q] = 0.f;

  auto fill = [&](int st, int it){
    int tap = it >> 2, c0 = (it & 3) * 32;
    unsigned short* Ah = dsm + st*STG;
    unsigned short* Al = Ah + ASZ;
    unsigned short* Bh = Ah + 2*ASZ;
    unsigned short* Bl = Bh + BSZ;
    #pragma unroll
    for (int rep = 0; rep < 2; rep++){
      int idx = rep*256 + tid;
      int row = idx >> 2, cg = idx & 3;
      int o = offsAll[tap*128 + row];
      bool p = o >= 0;
      int ob = (p ? o : 0) + c0 + cg*8;
      cpasync16(&Ah[row*AP + cg*8], xhi + ob, p);
      cpasync16(&Al[row*AP + cg*8], xlo + ob, p);
    }
    #pragma unroll
    for (int rep = 0; rep < 2; rep++){
      int idx = rep*256 + tid;
      int kr = idx >> 4, cg = idx & 15;
      int src = tap*16384 + (c0 + kr)*128 + cg*8;
      cpasync16(&Bh[kr*BP + cg*8], whi + src, true);
      cpasync16(&Bl[kr*BP + cg*8], wlo + src, true);
    }
  };

  fill(0, 0);
  CP_COMMIT();

  for (int it = 0; it < NIT; ++it){
    const int b = it & 1;
    if (it + 1 < NIT){
      fill(b ^ 1, it + 1);
      CP_COMMIT();
      CP_WAIT1();
    } else {
      CP_WAIT0();
    }
    __syncthreads();

    const unsigned short* Ah = dsm + b*STG;
    const unsigned short* Al = Ah + ASZ;
    const unsigned short* Bh = Ah + 2*ASZ;
    const unsigned short* Bl = Bh + BSZ;

    #pragma unroll
    for (int k16 = 0; k16 < 2; k16++){
      uint32_t af[4][4], bh[2][4], bl[2][4];
      #pragma unroll
      for (int mi = 0; mi < 4; mi++){
        int r = warp_m*64 + mi*16 + a_row_in;
        ldsm4(af[mi], &Ah[r*AP + k16*16 + a_colb]);
      }
      #pragma unroll
      for (int nj = 0; nj < 2; nj++){
        int kr = k16*16 + b_krow;
        int nc = warp_n*32 + nj*16 + b_coln;
        ldsm4t(bh[nj], &Bh[kr*BP + nc]);
        ldsm4t(bl[nj], &Bl[kr*BP + nc]);
      }
      #pragma unroll
      for (int mi = 0; mi < 4; mi++)
        #pragma unroll
        for (int ni = 0; ni < 4; ni++){
          const uint32_t* h = &bh[ni>>1][(ni&1)*2];
          const uint32_t* L = &bl[ni>>1][(ni&1)*2];
          mma_bf16(acc[mi][ni], af[mi], h[0], h[1]);
          mma_bf16(acc[mi][ni], af[mi], L[0], L[1]);
        }
      #pragma unroll
      for (int mi = 0; mi < 4; mi++){
        int r = warp_m*64 + mi*16 + a_row_in;
        ldsm4(af[mi], &Al[r*AP + k16*16 + a_colb]);
      }
      #pragma unroll
      for (int mi = 0; mi < 4; mi++)
        #pragma unroll
        for (int ni = 0; ni < 4; ni++){
          const uint32_t* h = &bh[ni>>1][(ni&1)*2];
          mma_bf16(acc[mi][ni], af[mi], h[0], h[1]);
        }
    }
    __syncthreads();
  }

  #pragma unroll
  for (int mi = 0; mi < 4; mi++){
    int v0 = vbase + warp_m*64 + mi*16 + (lane >> 2);
    #pragma unroll
    for (int ni = 0; ni < 4; ni++){
      int col = warp_n*32 + ni*8 + (lane & 3)*2;
      float2 bb = *(const float2*)&bias[col];
      float2 r0, r1;
      r0.x = fmaxf(acc[mi][ni][0] + bb.x, 0.f);
      r0.y = fmaxf(acc[mi][ni][1] + bb.y, 0.f);
      r1.x = fmaxf(acc[mi][ni][2] + bb.x, 0.f);
      r1.y = fmaxf(acc[mi][ni][3] + bb.y, 0.f);
      *(float2*)&out[(size_t)v0*128 + col]     = r0;
      *(float2*)&out[(size_t)(v0+8)*128 + col] = r1;
    }
  }
}

// ---------------------------------------------------------------------------
// R15-PROVEN (verbatim): L3 on HMMA, stride-2, DIM=16 -> 32; emits hi/lo.
// ---------------------------------------------------------------------------
__global__ __launch_bounds__(256, 2) void mma_s2(
    const __nv_bfloat16* __restrict__ xhi, const __nv_bfloat16* __restrict__ xlo,
    const __nv_bfloat16* __restrict__ whi, const __nv_bfloat16* __restrict__ wlo,
    const float* __restrict__ bias,
    __nv_bfloat16* __restrict__ ohi, __nv_bfloat16* __restrict__ olo)
{
  constexpr int BM = 128, BK = 32;
  constexpr int AP = 40;
  constexpr int BP = 136;

  __shared__ __align__(16) unsigned short Ahi[BM*AP];
  __shared__ __align__(16) unsigned short Alo[BM*AP];
  __shared__ __align__(16) unsigned short Bhi[BK*BP];
  __shared__ __align__(16) unsigned short Blo[BK*BP];
  __shared__ int offs[BM];

  const int tid  = threadIdx.x;
  const int lane = tid & 31;
  const int wid  = tid >> 5;
  const int warp_m = wid >> 2;
  const int warp_n = wid & 3;
  const int vbase = blockIdx.x * BM;
  const int pz = blockIdx.z;
  const int pd = (pz >> 2) & 1, ph = (pz >> 1) & 1, pw = pz & 1;

  int md, mh, mw;
  { int rv = vbase + (tid & 127);
    mw = rv & 15; int t = rv >> 4; mh = t & 15; md = t >> 4; }

  int nkd, kdL[2], ddL[2];
  int nkh, khL[2], dhL[2];
  int nkw, kwL[2], dwL[2];
  auto mk2 = [&](int p, int& n, int* kL, int* dL){
    if (p == 0){ n = 2; kL[0]=0; kL[1]=2; dL[0]=-1; dL[1]=0; }
    else       { n = 1; kL[0]=1; dL[0]=0; }
  };
  mk2(pd, nkd, kdL, ddL);
  mk2(ph, nkh, khL, dhL);
  mk2(pw, nkw, kwL, dwL);

  const int a_row_in = lane & 15;
  const int a_colb   = (lane >> 4) << 3;
  const int b_krow   = lane & 15;
  const int b_coln   = (lane >> 4) << 3;

  float acc[4][4][4];
  #pragma unroll
  for (int mi = 0; mi < 4; mi++)
    #pragma unroll
    for (int ni = 0; ni < 4; ni++)
      #pragma unroll
      for (int q = 0; q < 4; q++) acc[mi][ni][q] = 0.f;

  for (int ia = 0; ia < nkd; ia++)
  for (int ib = 0; ib < nkh; ib++)
  for (int ic = 0; ic < nkw; ic++){
    const int tap = (kdL[ia]*3 + khL[ib])*3 + kwL[ic];
    __syncthreads();
    if (tid < BM){
      int id = md + ddL[ia], ih = mh + dhL[ib], iw = mw + dwL[ic];
      bool v = (unsigned)id < 16u && (unsigned)ih < 16u && (unsigned)iw < 16u;
      offs[tid] = v ? ((id*16 + ih)*16 + iw) * 128 : -1;
    }

    for (int c0 = 0; c0 < 128; c0 += BK){
      __syncthreads();
      #pragma unroll
      for (int rep = 0; rep < 2; rep++){
        int idx = rep * 256 + tid;
        int row = idx >> 2, cg = idx & 3;
        int o = offs[row];
        uint4 h = make_uint4(0,0,0,0), l = make_uint4(0,0,0,0);
        if (o >= 0){
          h = *(const uint4*)(xhi + o + c0 + cg*8);
          l = *(const uint4*)(xlo + o + c0 + cg*8);
        }
        *(uint4*)&Ahi[row*AP + cg*8] = h;
        *(uint4*)&Alo[row*AP + cg*8] = l;
      }
      #pragma unroll
      for (int rep = 0; rep < 2; rep++){
        int idx = rep * 256 + tid;
        int kr = idx >> 4, cg = idx & 15;
        int src = tap*16384 + (c0 + kr)*128 + cg*8;
        *(uint4*)&Bhi[kr*BP + cg*8] = *(const uint4*)(whi + src);
        *(uint4*)&Blo[kr*BP + cg*8] = *(const uint4*)(wlo + src);
      }
      __syncthreads();

      #pragma unroll
      for (int k16 = 0; k16 < 2; k16++){
        uint32_t af[4][4], bh[2][4], bl[2][4];
        #pragma unroll
        for (int mi = 0; mi < 4; mi++){
          int r = warp_m*64 + mi*16 + a_row_in;
          ldsm4(af[mi], &Ahi[r*AP + k16*16 + a_colb]);
        }
        #pragma unroll
        for (int nj = 0; nj < 2; nj++){
          int kr = k16*16 + b_krow;
          int nc = warp_n*32 + nj*16 + b_coln;
          ldsm4t(bh[nj], &Bhi[kr*BP + nc]);
          ldsm4t(bl[nj], &Blo[kr*BP + nc]);
        }
        #pragma unroll
        for (int mi = 0; mi < 4; mi++)
          #pragma unroll
          for (int ni = 0; ni < 4; ni++){
            const uint32_t* h = &bh[ni>>1][(ni&1)*2];
            const uint32_t* L = &bl[ni>>1][(ni&1)*2];
            mma_bf16(acc[mi][ni], af[mi], h[0], h[1]);
            mma_bf16(acc[mi][ni], af[mi], L[0], L[1]);
          }
        #pragma unroll
        for (int mi = 0; mi < 4; mi++){
          int r = warp_m*64 + mi*16 + a_row_in;
          ldsm4(af[mi], &Alo[r*AP + k16*16 + a_colb]);
        }
        #pragma unroll
        for (int mi = 0; mi < 4; mi++)
          #pragma unroll
          for (int ni = 0; ni < 4; ni++){
            const uint32_t* h = &bh[ni>>1][(ni&1)*2];
            mma_bf16(acc[mi][ni], af[mi], h[0], h[1]);
          }
      }
    }
  }

  #pragma unroll
  for (int mi = 0; mi < 4; mi++){
    int lv0 = warp_m*64 + mi*16 + (lane >> 2);
    #pragma unroll
    for (int ni = 0; ni < 4; ni++){
      int col = warp_n*32 + ni*8 + (lane & 3)*2;
      float2 bb = *(const float2*)&bias[col];
      #pragma unroll
      for (int h = 0; h < 2; h++){
        int rv = vbase + lv0 + h*8;
        int vw = rv & 15; int t = rv >> 4; int vh = t & 15; int vd = t >> 4;
        int od = 2*vd + pd, oh = 2*vh + ph, ow = 2*vw + pw;
        size_t oo = (size_t)((od*32 + oh)*32 + ow) * 128 + col;
        unsigned hw, lw;
        split2(acc[mi][ni][2*h+0] + bb.x, acc[mi][ni][2*h+1] + bb.y, hw, lw);
        *(unsigned*)&ohi[oo] = hw;
        *(unsigned*)&olo[oo] = lw;
      }
    }
  }
}

// ---------------------------------------------------------------------------
// Fused L5+L6 path tables (R6-proven).
// ---------------------------------------------------------------------------
__device__ __constant__ int c_np[2][3]   = {{2,2,0},{1,3,1}};
__device__ __constant__ int c_k1[2][3][3] = {{{1,0,0},{2,1,0},{0,0,0}},
                                             {{0,0,0},{2,1,0},{2,0,0}}};
__device__ __constant__ int c_k2[2][3][3] = {{{0,1,0},{1,2,0},{0,0,0}},
                                             {{0,0,0},{0,1,2},{2,0,0}}};

// P1 (R10-proven, verbatim): Wp + WpT
__global__ __launch_bounds__(256) void p1_wp(
    const float* __restrict__ w2, const float* __restrict__ w20)
{
  int t = blockIdx.x * 256 + threadIdx.x;
  if (t >= 27*27*128) return;
  int ci = t & 127;
  int k2l = (t >> 7) % 27;
  int k1l = t / (27*128);
  const float* a = w2 + ((size_t)k1l*128 + ci) * 64;
  const float* b = w20 + (size_t)k2l * 64 * 3;
  float s0 = 0.f, s1 = 0.f, s2 = 0.f;
  #pragma unroll 4
  for (int cm = 0; cm < 64; cm++){
    float av = a[cm];
    s0 = fmaf(av, b[cm*3+0], s0);
    s1 = fmaf(av, b[cm*3+1], s1);
    s2 = fmaf(av, b[cm*3+2], s2);
  }
  float* o = g_Wp + (size_t)t * 3;
  o[0] = s0; o[1] = s1; o[2] = s2;
  size_t kk = (size_t)k1l*27 + k2l;
  g_WpT[kk*384 + 0*128 + ci] = s0;
  g_WpT[kk*384 + 1*128 + ci] = s1;
  g_WpT[kk*384 + 2*128 + ci] = s2;
}

// P2 (R7-proven, verbatim): Weff[pz][dxl][co][ci]
__global__ __launch_bounds__(256) void p2_weff()
{
  int t = blockIdx.x * 256 + threadIdx.x;
  if (t >= 8*27*128) return;
  int ci = t & 127;
  int dxl = (t >> 7) % 27;
  int pz = t / (27*128);
  int jd = dxl / 9, jh = (dxl / 3) % 3, jw = dxl % 3;
  int pd = (pz >> 2) & 1, ph = (pz >> 1) & 1, pw = pz & 1;
  int nd = c_np[pd][jd], nh = c_np[ph][jh], nw = c_np[pw][jw];
  float s0 = 0.f, s1 = 0.f, s2 = 0.f;
  for (int a = 0; a < nd; a++)
  for (int b = 0; b < nh; b++)
  for (int c = 0; c < nw; c++){
    int k1l = (c_k1[pd][jd][a]*3 + c_k1[ph][jh][b])*3 + c_k1[pw][jw][c];
    int k2l = (c_k2[pd][jd][a]*3 + c_k2[ph][jh][b])*3 + c_k2[pw][jw][c];
    const float* wp = g_Wp + ((size_t)(k1l*27 + k2l)*128 + ci)*3;
    s0 += wp[0]; s1 += wp[1]; s2 += wp[2];
  }
  float* o = g_Weff + (size_t)(pz*27 + dxl) * 3 * 128;
  o[0*128 + ci] = s0;
  o[1*128 + ci] = s1;
  o[2*128 + ci] = s2;
}

// P3 (R6-proven, verbatim)
__global__ void p3_bias(const float* __restrict__ w20,
                        const float* __restrict__ b2,
                        const float* __restrict__ b20)
{
  int tid = threadIdx.x;
  if (tid < 81){
    int k2 = tid / 3, co = tid % 3;
    float s = 0.f;
    for (int cm = 0; cm < 64; cm++)
      s = fmaf(w20[(k2*64+cm)*3+co], b2[cm], s);
    g_bconv[tid] = s;
  }
  __syncthreads();
  if (tid < 3){
    float s = b20[tid];
    for (int k2 = 0; k2 < 27; k2++) s += g_bconv[k2*3+tid];
    g_btot[tid] = s;
  }
}

// ---------------------------------------------------------------------------
// Fused L5+L6 consumer (R14-proven, verbatim).
// ---------------------------------------------------------------------------
__global__ __launch_bounds__(256) void fused56b(
    const float* __restrict__ x, float* __restrict__ out)
{
  const int wid  = threadIdx.x >> 5;
  const int lane = threadIdx.x & 31;
  const int pz = blockIdx.z;
  const int pd = (pz >> 2) & 1, ph = (pz >> 1) & 1, pw = pz & 1;
  const int wg  = blockIdx.x * 8 + wid;
  const int seg = wg & 3;
  const int row = wg >> 2;
  const int rd = row >> 5, rh = row & 31;
  const int rw0 = seg * 8;
  const int l2 = 2 * lane;
  const int nw = 2 + pw;

  ull acc[8][3];
  #pragma unroll
  for (int r = 0; r < 8; r++)
    #pragma unroll
    for (int c = 0; c < 3; c++) acc[r][c] = 0ull;

  for (int jd = 0; jd <= 1 + pd; jd++){
    int id = rd + jd - 1;
    if ((unsigned)id >= 32u) continue;
    for (int jh = 0; jh <= 1 + ph; jh++){
      int ih = rh + jh - 1;
      if ((unsigned)ih >= 32u) continue;
      const float* xrow = x + (size_t)((id*32 + ih)*32) * 128;

      ull W[3][6];
      #pragma unroll
      for (int jw = 0; jw < 3; jw++){
        if (jw < nw){
          const float* Wt = g_Weff + (size_t)(pz*27 + jd*9 + jh*3 + jw) * 384;
          W[jw][0] = *(const ull*)(Wt +   0 + l2);
          W[jw][1] = *(const ull*)(Wt +  64 + l2);
          W[jw][2] = *(const ull*)(Wt + 128 + l2);
          W[jw][3] = *(const ull*)(Wt + 192 + l2);
          W[jw][4] = *(const ull*)(Wt + 256 + l2);
          W[jw][5] = *(const ull*)(Wt + 320 + l2);
        }
      }

      #pragma unroll
      for (int t = 0; t < 10; t++){
        int iw = rw0 - 1 + t;
        if ((unsigned)iw >= 32u) continue;
        const float* xp = xrow + iw * 128;
        ull x0 = *(const ull*)(xp + l2);
        ull x1 = *(const ull*)(xp + 64 + l2);
        #pragma unroll
        for (int jw = 0; jw < 3; jw++){
          int r = t - jw;
          if (jw < nw && (unsigned)r < 8u){
            ffma2(acc[r][0], x0, W[jw][0]); ffma2(acc[r][0], x1, W[jw][1]);
            ffma2(acc[r][1], x0, W[jw][2]); ffma2(acc[r][1], x1, W[jw][3]);
            ffma2(acc[r][2], x0, W[jw][4]); ffma2(acc[r][2], x1, W[jw][5]);
          }
        }
      }
    }
  }

  const float bt0 = g_btot[0], bt1 = g_btot[1], bt2 = g_btot[2];
  const int od = 2*rd + pd, oh = 2*rh + ph;

  #pragma unroll
  for (int r = 0; r < 8; r++){
    float s0, s1, s2;
    {
      float a, b;
      unpack2(acc[r][0], a, b); s0 = a + b;
      unpack2(acc[r][1], a, b); s1 = a + b;
      unpack2(acc[r][2], a, b); s2 = a + b;
    }
    #pragma unroll
    for (int sh = 16; sh > 0; sh >>= 1){
      s0 += __shfl_xor_sync(0xffffffffu, s0, sh);
      s1 += __shfl_xor_sync(0xffffffffu, s1, sh);
      s2 += __shfl_xor_sync(0xffffffffu, s2, sh);
    }
    if (lane == 0){
      int ow = 2*(rw0 + r) + pw;
      float* op = out + (size_t)((od*64 + oh)*64 + ow) * 3;
      op[0] = s0 + bt0;
      op[1] = s1 + bt1;
      op[2] = s2 + bt2;
    }
  }
}

// ---------------------------------------------------------------------------
// fix56p (R16-proven, verbatim): boundary partials, k2d-parallel.
// ---------------------------------------------------------------------------
__global__ __launch_bounds__(256) void fix56p(
    const float* __restrict__ x, float* __restrict__ fixP)
{
  const int gw = blockIdx.x * 8 + (threadIdx.x >> 5);
  const int lane = threadIdx.x & 31;
  const int l2 = 2 * lane;
  const int k2d = blockIdx.y;

  int plane = gw / 4096, r = gw % 4096;
  int a = r / 64, b = r % 64;
  int od, oh, ow;
  if      (plane == 0){ od = 0;  oh = a; ow = b; }
  else if (plane == 1){ od = 63; oh = a; ow = b; }
  else if (plane == 2){ oh = 0;  od = a; ow = b; if (od==0||od==63) return; }
  else if (plane == 3){ oh = 63; od = a; ow = b; if (od==0||od==63) return; }
  else if (plane == 4){ ow = 0;  od = a; oh = b; if (od==0||od==63||oh==0||oh==63) return; }
  else               { ow = 63; od = a; oh = b; if (od==0||od==63||oh==0||oh==63) return; }

  ull a0 = 0ull, a1 = 0ull, a2 = 0ull;
  float bias0 = 0.f, bias1 = 0.f, bias2 = 0.f;

  int md = od + k2d - 1;
  if ((unsigned)md < 64u){
    int pmd = md & 1, rd = (md - pmd) >> 1;
    int n_d = pmd ? 1 : 2;
    int k1d[2], ixd[2];
    if (pmd){ k1d[0] = 1; ixd[0] = rd; }
    else    { k1d[0] = 0; ixd[0] = rd - 1; k1d[1] = 2; ixd[1] = rd; }
    for (int k2h = 0; k2h < 3; k2h++){
      int mh = oh + k2h - 1; if ((unsigned)mh >= 64u) continue;
      int pmh = mh & 1, rh = (mh - pmh) >> 1;
      int n_h = pmh ? 1 : 2;
      int k1h[2], ixh[2];
      if (pmh){ k1h[0] = 1; ixh[0] = rh; }
      else    { k1h[0] = 0; ixh[0] = rh - 1; k1h[1] = 2; ixh[1] = rh; }
      for (int k2w = 0; k2w < 3; k2w++){
        int mw = ow + k2w - 1; if ((unsigned)mw >= 64u) continue;
        int pmw = mw & 1, rw = (mw - pmw) >> 1;
        int n_w = pmw ? 1 : 2;
        int k1w[2], ixw[2];
        if (pmw){ k1w[0] = 1; ixw[0] = rw; }
        else    { k1w[0] = 0; ixw[0] = rw - 1; k1w[1] = 2; ixw[1] = rw; }

        int k2l = (k2d*3 + k2h)*3 + k2w;
        bias0 += g_bconv[k2l*3+0];
        bias1 += g_bconv[k2l*3+1];
        bias2 += g_bconv[k2l*3+2];

        for (int ia = 0; ia < n_d; ia++){
          if ((unsigned)ixd[ia] >= 32u) continue;
          for (int ib = 0; ib < n_h; ib++){
            if ((unsigned)ixh[ib] >= 32u) continue;
            for (int ic = 0; ic < n_w; ic++){
              if ((unsigned)ixw[ic] >= 32u) continue;
              int k1l = (k1d[ia]*3 + k1h[ib])*3 + k1w[ic];
              const float* wt = g_WpT + (size_t)(k1l*27 + k2l)*384;
              const float* xp = x + (size_t)((ixd[ia]*32 + ixh[ib])*32 + ixw[ic])*128;
              ull x0 = *(const ull*)(xp + l2);
              ull x1 = *(const ull*)(xp + 64 + l2);
              ffma2(a0, x0, *(const ull*)(wt +   0 + l2));
              ffma2(a0, x1, *(const ull*)(wt +  64 + l2));
              ffma2(a1, x0, *(const ull*)(wt + 128 + l2));
              ffma2(a1, x1, *(const ull*)(wt + 192 + l2));
              ffma2(a2, x0, *(const ull*)(wt + 256 + l2));
              ffma2(a2, x1, *(const ull*)(wt + 320 + l2));
            }
          }
        }
      }
    }
  }

  float s0, s1, s2;
  {
    float u, v;
    unpack2(a0, u, v); s0 = u + v;
    unpack2(a1, u, v); s1 = u + v;
    unpack2(a2, u, v); s2 = u + v;
  }
  #pragma unroll
  for (int sh = 16; sh > 0; sh >>= 1){
    s0 += __shfl_xor_sync(0xffffffffu, s0, sh);
    s1 += __shfl_xor_sync(0xffffffffu, s1, sh);
    s2 += __shfl_xor_sync(0xffffffffu, s2, sh);
  }
  if (lane == 0){
    float4* p = (float4*)fixP + (size_t)k2d * 24576 + gw;
    *p = make_float4(s0 + bias0, s1 + bias1, s2 + bias2, 0.f);
  }
}

// fix_combine (R16-proven, verbatim)
__global__ __launch_bounds__(256) void fix_combine(
    const float* __restrict__ fixP, const float* __restrict__ b20,
    float* __restrict__ out)
{
  int gw = blockIdx.x * 256 + threadIdx.x;
  if (gw >= 24576) return;
  int plane = gw / 4096, r = gw % 4096;
  int a = r / 64, b = r % 64;
  int od, oh, ow;
  if      (plane == 0){ od = 0;  oh = a; ow = b; }
  else if (plane == 1){ od = 63; oh = a; ow = b; }
  else if (plane == 2){ oh = 0;  od = a; ow = b; if (od==0||od==63) return; }
  else if (plane == 3){ oh = 63; od = a; ow = b; if (od==0||od==63) return; }
  else if (plane == 4){ ow = 0;  od = a; oh = b; if (od==0||od==63||oh==0||oh==63) return; }
  else               { ow = 63; od = a; oh = b; if (od==0||od==63||oh==0||oh==63) return; }

  const float4* P = (const float4*)fixP;
  float4 p0 = P[0*24576 + gw];
  float4 p1 = P[1*24576 + gw];
  float4 p2 = P[2*24576 + gw];
  float* op = out + (size_t)((od*64 + oh)*64 + ow) * 3;
  op[0] = __ldg(&b20[0]) + p0.x + p1.x + p2.x;
  op[1] = __ldg(&b20[1]) + p0.y + p1.y + p2.y;
  op[2] = __ldg(&b20[2]) + p0.z + p1.z + p2.z;
}

// ---------------------------------------------------------------------------
// kernel_launch
// ---------------------------------------------------------------------------
extern "C" void kernel_launch(void* const* d_in, const int* in_sizes, int n_in,
                              void* d_out, int out_size)
{
  (void)in_sizes; (void)n_in; (void)out_size;
  const float* x   = (const float*)d_in[0];
  const float* w0  = (const float*)d_in[1];
  const float* b0  = (const float*)d_in[2];
  const float* w00 = (const float*)d_in[3];
  const float* b00 = (const float*)d_in[4];
  const float* w1  = (const float*)d_in[5];
  const float* b1  = (const float*)d_in[6];
  const float* w10 = (const float*)d_in[7];
  const float* b10 = (const float*)d_in[8];
  const float* w2  = (const float*)d_in[9];
  const float* b2  = (const float*)d_in[10];
  const float* w20 = (const float*)d_in[11];
  const float* b20 = (const float*)d_in[12];
  float* out = (float*)d_out;

  float *bufB = nullptr, *part = nullptr;
  __nv_bfloat16 *xhA, *xlA, *xhB, *xlB;
  __nv_bfloat16 *whi, *wlo, *whiB, *wloB, *whiC, *wloC, *whiD, *wloD;
  cudaGetSymbolAddress((void**)&bufB, g_bufB);
  cudaGetSymbolAddress((void**)&part, g_part);
  cudaGetSymbolAddress((void**)&xhA, g_xhiA);
  cudaGetSymbolAddress((void**)&xlA, g_xloA);
  cudaGetSymbolAddress((void**)&xhB, g_xhiB);
  cudaGetSymbolAddress((void**)&xlB, g_xloB);
  cudaGetSymbolAddress((void**)&whi, g_whi);
  cudaGetSymbolAddress((void**)&wlo, g_wlo);
  cudaGetSymbolAddress((void**)&whiB, g_whiB);
  cudaGetSymbolAddress((void**)&wloB, g_wloB);
  cudaGetSymbolAddress((void**)&whiC, g_whiC);
  cudaGetSymbolAddress((void**)&wloC, g_wloC);
  cudaGetSymbolAddress((void**)&whiD, g_whiD);
  cudaGetSymbolAddress((void**)&wloD, g_wloD);

  static bool attr_set = false;
  const int PIPE_SMEM = 2*37888 + 27*128*4;   // 89600 B
  if (!attr_set){
    cudaFuncSetAttribute(mma_s1r_pipe,
                         cudaFuncAttributeMaxDynamicSharedMemorySize, PIPE_SMEM);
    attr_set = true;
  }

  // (1) Wp + WpT precompute
  p1_wp<<<(27*27*128 + 255)/256, 256>>>(w2, w20);
  // (2) split all 4 conv weights in one launch
  {
    dim3 g(1728, 4, 1);
    split_w4_kernel<<<g, 256>>>(w0, w00, w1, w10,
                                whiD, wloD, whiC, wloC,
                                whiB, wloB, whi, wlo);
  }
  // (3) split network input x -> pair A
  split_x_kernel<<<64, 256>>>(x, xhA, xlA, 65536/4);
  // (4) L1 on HMMA, 8-way (chunk x tap-half) shard -> partials   [NEW]
  {
    dim3 g(4, 8, 8);
    mma_s2d8_part<<<g, 256>>>(xhA, xlA, whiD, wloD, part);
  }
  // (5) L1 finish: sum 8 partials + bias -> pair B   [NEW]
  l1_finish<<<512, 256>>>(part, b0, xhB, xlB);
  // (6) L2 on HMMA, 7-way tap split: B -> partials
  {
    dim3 g(32, 7, 1);
    mma_s1_part<<<g, 256>>>(xhB, xlB, whiC, wloC, part);
  }
  // (7) L2 finish -> pair A
  l2_finish<<<512, 256>>>(part, b00, xhA, xlA);
  // (8) L3 on HMMA: A -> pair B
  {
    dim3 g(32, 1, 8);
    mma_s2<<<g, 256>>>(xhA, xlA, whiB, wloB, b1, xhB, xlB);
  }
  // (9) L4 on pipelined HMMA: B -> bufB (fp32)
  mma_s1r_pipe<<<256, 256, PIPE_SMEM>>>(xhB, xlB, whi, wlo, b10, bufB);
  // (10-11) fused-weight precompute for L5+L6
  p2_weff<<<(8*27*128 + 255)/256, 256>>>();
  p3_bias<<<1, 128>>>(w20, b2, b20);
  // (12) Fused L5+L6 (interior)
  {
    dim3 g(512, 1, 8);
    fused56b<<<g, 256>>>(bufB, out);
  }
  // (13) Boundary fix partials, k2d-parallel
  {
    dim3 g(3072, 3, 1);
    fix56p<<<g, 256>>>(bufB, part);
  }
  // (14) Combine boundary partials
  fix_combine<<<96, 256>>>(part, b20, out);
}